// round 10
// baseline (speedup 1.0000x reference)
#include <cuda_runtime.h>
#include <math.h>
#include <stdint.h>

#define T  2048
#define H  2048
#define NH 16
#define HD 128
#define NE 16
#define II 2048
#define I2 4096
#define EPS 1e-6f

#define TBM 128
#define TBN 128
#define TBK 64
#define KBLK_STR 33
#define MBLK_STR 133
#define APH 4256
#define ATILE64 (2 * APH)
#define GSMEM (4 * ATILE64 * 4)  // 136192 bytes

// ---------------- scratch ----------------
__device__ float g_h[(size_t)T * H];
__device__ float g_qkv[(size_t)T * 3 * H];
__device__ float g_S[(size_t)NH * T * T];
__device__ float g_rsum[(size_t)NH * T];
__device__ float g_attn[(size_t)T * H];
__device__ float g_x2[(size_t)T * H];
__device__ float g_h2[(size_t)T * H];
__device__ float g_logits[(size_t)T * NE];
__device__ float g_topw[T];
__device__ int   g_topi[T];
__device__ int   g_counts[NE];
__device__ int   g_rows[(size_t)NE * T];
__device__ float g_gu[(size_t)T * I2];
__device__ float g_moe[(size_t)T * H];
__device__ float g_sgu[(size_t)T * I2];
__device__ float g_cos[(size_t)T * (HD / 2)];
__device__ float g_sin[(size_t)T * (HD / 2)];

// ---------------- helpers ----------------
__device__ __forceinline__ uint32_t f2tf(float x) {
    uint32_t u;
    asm("cvt.rna.tf32.f32 %0, %1;" : "=r"(u) : "f"(x));
    return u;
}

__device__ __forceinline__ void mma_tf32(float c[4], uint4 a, uint2 b) {
    asm volatile("mma.sync.aligned.m16n8k8.row.col.f32.tf32.tf32.f32 "
                 "{%0,%1,%2,%3}, {%4,%5,%6,%7}, {%8,%9}, {%0,%1,%2,%3};"
                 : "+f"(c[0]), "+f"(c[1]), "+f"(c[2]), "+f"(c[3])
                 : "r"(a.x), "r"(a.y), "r"(a.z), "r"(a.w), "r"(b.x), "r"(b.y));
}

__device__ __forceinline__ float blk_sum(float v) {
    __shared__ float sh[33];
    __syncthreads();
    int lane = threadIdx.x & 31, w = threadIdx.x >> 5;
#pragma unroll
    for (int o = 16; o; o >>= 1) v += __shfl_xor_sync(0xffffffffu, v, o);
    if (lane == 0) sh[w] = v;
    __syncthreads();
    if (threadIdx.x < 32) {
        int nw = (blockDim.x + 31) >> 5;
        float r = (threadIdx.x < nw) ? sh[threadIdx.x] : 0.f;
#pragma unroll
        for (int o = 16; o; o >>= 1) r += __shfl_xor_sync(0xffffffffu, r, o);
        if (threadIdx.x == 0) sh[32] = r;
    }
    __syncthreads();
    return sh[32];
}

__device__ __forceinline__ float blk_max(float v) {
    __shared__ float sh[33];
    __syncthreads();
    int lane = threadIdx.x & 31, w = threadIdx.x >> 5;
#pragma unroll
    for (int o = 16; o; o >>= 1) v = fmaxf(v, __shfl_xor_sync(0xffffffffu, v, o));
    if (lane == 0) sh[w] = v;
    __syncthreads();
    if (threadIdx.x < 32) {
        int nw = (blockDim.x + 31) >> 5;
        float r = (threadIdx.x < nw) ? sh[threadIdx.x] : -3.4e38f;
#pragma unroll
        for (int o = 16; o; o >>= 1) r = fmaxf(r, __shfl_xor_sync(0xffffffffu, r, o));
        if (threadIdx.x == 0) sh[32] = r;
    }
    __syncthreads();
    return sh[32];
}

__device__ __forceinline__ int a_perm_base(int r, int k0) {
    int mblk = r >> 4, g = r & 7, half = (r >> 3) & 1;
    int kblk = k0 >> 3, k4 = (k0 >> 2) & 1;
    return (mblk * MBLK_STR + kblk * KBLK_STR + g * 4) * 4 + (half + 2 * k4);
}
__device__ __forceinline__ int b_perm_base(int r, int k0) {
    int nblk = r >> 3, g = r & 7;
    int kblk = k0 >> 3, k4 = (k0 >> 2) & 1;
    return (nblk * MBLK_STR + kblk * KBLK_STR + g * 4) * 2 + k4;
}
__device__ __forceinline__ void a_store4(float* As, int base, float4 v) {
    As[base]      = __uint_as_float(f2tf(v.x));
    As[base + 4]  = __uint_as_float(f2tf(v.y));
    As[base + 8]  = __uint_as_float(f2tf(v.z));
    As[base + 12] = __uint_as_float(f2tf(v.w));
}
__device__ __forceinline__ void b_store4(float* Bs, int base, float4 v) {
    Bs[base]     = __uint_as_float(f2tf(v.x));
    Bs[base + 2] = __uint_as_float(f2tf(v.y));
    Bs[base + 4] = __uint_as_float(f2tf(v.z));
    Bs[base + 6] = __uint_as_float(f2tf(v.w));
}

// fused A load: plain row, or silu(g)*u from a [*, 2*II] gate-up buffer
__device__ __forceinline__ float4 loadA4(const float* Arow, int col, int siluA) {
    if (!siluA) return *(const float4*)(Arow + col);
    float4 g = *(const float4*)(Arow + col);
    float4 u = *(const float4*)(Arow + II + col);
    float4 r;
    r.x = (g.x / (1.f + expf(-g.x))) * u.x;
    r.y = (g.y / (1.f + expf(-g.y))) * u.y;
    r.z = (g.z / (1.f + expf(-g.z))) * u.z;
    r.w = (g.w / (1.f + expf(-g.w))) * u.w;
    return r;
}

__device__ __forceinline__ void load_frags(const float* Ab, const float* Bb, int sub,
                                           int wmblk, int wnblk, int fragoff,
                                           uint4 af[2], uint2 bf[4]) {
    int khalf = sub >> 2, kblk = sub & 3;
    const float* Ah = Ab + khalf * APH;
    const float* Bh = Bb + khalf * APH;
#pragma unroll
    for (int mi = 0; mi < 2; mi++)
        af[mi] = *(const uint4*)(Ah + ((wmblk + mi) * MBLK_STR + kblk * KBLK_STR + fragoff) * 4);
#pragma unroll
    for (int ni = 0; ni < 4; ni++)
        bf[ni] = *(const uint2*)(Bh + ((wnblk + ni) * MBLK_STR + kblk * KBLK_STR + fragoff) * 2);
}

// ---------------- tf32 GEMM NT (512 thr), TBK=64, frag double-buffered ----------------
__global__ void __launch_bounds__(512) mma_nt(
    const float* __restrict__ A, int lda, long long sA,
    const float* __restrict__ B, int ldb, long long sB,
    float* __restrict__ C, int ldc, long long sC,
    int M, int N, int K,
    const int* __restrict__ rowsAll, const int* __restrict__ cntAll,
    int causal, int siluA,
    const float* __restrict__ addA,
    const float* __restrict__ addS, const float* __restrict__ scaleVec)
{
    extern __shared__ float smem[];
    float* As = smem;
    float* Bs = smem + 2 * ATILE64;
    __shared__ int rid[TBM];

    int z = blockIdx.z;
    A += (size_t)z * sA; B += (size_t)z * sB; C += (size_t)z * sC;
    const int* rows = rowsAll ? rowsAll + (size_t)z * M : 0;
    int Mv = cntAll ? cntAll[z] : M;
    int m0 = blockIdx.y * TBM;
    if (m0 >= Mv) return;
    int n0 = blockIdx.x * TBN;
    if (causal && n0 > m0) return;

    int tid = threadIdx.x;
    if (tid < TBM) {
        int gm = m0 + tid;
        rid[tid] = rows ? (gm < Mv ? rows[gm] : -1) : gm;
    }
    __syncthreads();

    int lrow[4], lcol[4], ra[4], abase[4], bbase[4];
#pragma unroll
    for (int i = 0; i < 4; i++) {
        int idx = tid + i * 512;
        lrow[i] = idx >> 4;
        lcol[i] = (idx & 15) * 4;
        ra[i] = rid[lrow[i]];
        int khalf = lcol[i] >> 5, k0 = lcol[i] & 31;
        abase[i] = khalf * APH + a_perm_base(lrow[i], k0);
        bbase[i] = khalf * APH + b_perm_base(lrow[i], k0);
    }

    float4 rA[4], rB[4];
    const float4 z4 = make_float4(0.f, 0.f, 0.f, 0.f);
#pragma unroll
    for (int i = 0; i < 4; i++) {
        rA[i] = (ra[i] >= 0) ? loadA4(A + (size_t)ra[i] * lda, lcol[i], siluA) : z4;
        rB[i] = *(const float4*)(B + (size_t)(n0 + lrow[i]) * ldb + lcol[i]);
    }
#pragma unroll
    for (int i = 0; i < 4; i++) {
        a_store4(As, abase[i], rA[i]);
        b_store4(Bs, bbase[i], rB[i]);
    }
    __syncthreads();

    int lane = tid & 31, wid = tid >> 5;
    int wmblk = (wid & 3) * 2;
    int wnblk = (wid >> 2) * 4;
    int g = lane >> 2, cc = lane & 3;
    int fragoff = g * 4 + cc;

    float acc[2][4][4];
#pragma unroll
    for (int mi = 0; mi < 2; mi++)
#pragma unroll
        for (int ni = 0; ni < 4; ni++)
#pragma unroll
            for (int j = 0; j < 4; j++) acc[mi][ni][j] = 0.f;

    uint4 afb[2][2];
    uint2 bfb[2][4];
    int nt = K >> 6;
    for (int it = 0; it < nt; it++) {
        int buf = it & 1;
        const float* Ab = As + buf * ATILE64;
        const float* Bb = Bs + buf * ATILE64;
        load_frags(Ab, Bb, 0, wmblk, wnblk, fragoff, afb[0], bfb[0]);
        bool has_next = (it + 1) < nt;
        if (has_next) {
            int kt = (it + 1) << 6;
#pragma unroll
            for (int i = 0; i < 4; i++) {
                rA[i] = (ra[i] >= 0) ? loadA4(A + (size_t)ra[i] * lda, kt + lcol[i], siluA) : z4;
                rB[i] = *(const float4*)(B + (size_t)(n0 + lrow[i]) * ldb + kt + lcol[i]);
            }
        }
#pragma unroll
        for (int s = 0; s < 8; s++) {
            int cur = s & 1;
            if (s < 7)
                load_frags(Ab, Bb, s + 1, wmblk, wnblk, fragoff, afb[cur ^ 1], bfb[cur ^ 1]);
#pragma unroll
            for (int mi = 0; mi < 2; mi++)
#pragma unroll
                for (int ni = 0; ni < 4; ni++)
                    mma_tf32(acc[mi][ni], afb[cur][mi], bfb[cur][ni]);
        }
        if (has_next) {
            float* an = As + (buf ^ 1) * ATILE64;
            float* bn = Bs + (buf ^ 1) * ATILE64;
#pragma unroll
            for (int i = 0; i < 4; i++) {
                a_store4(an, abase[i], rA[i]);
                b_store4(bn, bbase[i], rB[i]);
            }
            __syncthreads();
        }
    }

#pragma unroll
    for (int mi = 0; mi < 2; mi++) {
        int r0 = (wid & 3) * 32 + mi * 16 + g;
        int rr[2] = { rid[r0], rid[r0 + 8] };
#pragma unroll
        for (int half = 0; half < 2; half++) {
            int r = rr[half];
            if (r < 0) continue;
#pragma unroll
            for (int ni = 0; ni < 4; ni++) {
                int col = n0 + (wid >> 2) * 32 + ni * 8 + cc * 2;
                float2 v = make_float2(acc[mi][ni][half * 2], acc[mi][ni][half * 2 + 1]);
                if (addA) {
                    float2 a = *(const float2*)(addA + (size_t)r * ldc + col);
                    v.x += a.x; v.y += a.y;
                }
                if (addS) {
                    float w = scaleVec[r];
                    float2 s = *(const float2*)(addS + (size_t)r * ldc + col);
                    v.x += s.x * w; v.y += s.y * w;
                }
                *(float2*)(C + (size_t)r * ldc + col) = v;
            }
        }
    }
}

// ---------------- tf32 GEMM NN (512 thr), TBK=64, row-scaled epilogue ----------------
__global__ void __launch_bounds__(512) mma_nn(
    const float* __restrict__ A, int lda, long long sA,
    const float* __restrict__ B, int ldb, long long sB,
    float* __restrict__ C, int ldc, long long sC,
    int M, int N, int K, int kcap,
    const float* __restrict__ rscaleAll)   // per-z row scale [z][M], optional
{
    extern __shared__ float smem[];
    float* As = smem;
    float* Bs = smem + 2 * ATILE64;

    int z = blockIdx.z;
    A += (size_t)z * sA; B += (size_t)z * sB; C += (size_t)z * sC;
    const float* rscale = rscaleAll ? rscaleAll + (size_t)z * M : 0;
    int m0 = blockIdx.y * 128;
    int n0 = blockIdx.x * 128;
    int Keff = kcap ? min(K, m0 + 128) : K;

    int tid = threadIdx.x;
    int larow[4], lacol[4], abase[4];
    int lbkr[4], lbng[4], bbase[4];
#pragma unroll
    for (int i = 0; i < 4; i++) {
        int idx = tid + i * 512;
        larow[i] = idx >> 4;
        lacol[i] = (idx & 15) * 4;
        int khalfA = lacol[i] >> 5, k0A = lacol[i] & 31;
        abase[i] = khalfA * APH + a_perm_base(larow[i], k0A);
        lbkr[i] = idx >> 5;
        lbng[i] = (idx & 31) * 4;
        int khalfB = lbkr[i] >> 5, kr = lbkr[i] & 31;
        int kblk = kr >> 3, ccB = kr & 3, k4 = (kr >> 2) & 1;
        int nblk = lbng[i] >> 3, g0 = lbng[i] & 7;
        bbase[i] = khalfB * APH + (nblk * MBLK_STR + kblk * KBLK_STR + g0 * 4 + ccB) * 2 + k4;
    }

    float4 rA[4], rB[4];
#pragma unroll
    for (int i = 0; i < 4; i++) {
        rA[i] = *(const float4*)(A + (size_t)(m0 + larow[i]) * lda + lacol[i]);
        rB[i] = *(const float4*)(B + (size_t)lbkr[i] * ldb + n0 + lbng[i]);
    }
#pragma unroll
    for (int i = 0; i < 4; i++) {
        a_store4(As, abase[i], rA[i]);
        Bs[bbase[i]]      = __uint_as_float(f2tf(rB[i].x));
        Bs[bbase[i] + 8]  = __uint_as_float(f2tf(rB[i].y));
        Bs[bbase[i] + 16] = __uint_as_float(f2tf(rB[i].z));
        Bs[bbase[i] + 24] = __uint_as_float(f2tf(rB[i].w));
    }
    __syncthreads();

    int lane = tid & 31, wid = tid >> 5;
    int wmblk = (wid & 3) * 2, wnblk = (wid >> 2) * 4;
    int g = lane >> 2, cc = lane & 3;
    int fragoff = g * 4 + cc;

    float acc[2][4][4];
#pragma unroll
    for (int mi = 0; mi < 2; mi++)
#pragma unroll
        for (int ni = 0; ni < 4; ni++)
#pragma unroll
            for (int j = 0; j < 4; j++) acc[mi][ni][j] = 0.f;

    uint4 afb[2][2];
    uint2 bfb[2][4];
    int nt = Keff >> 6;
    for (int it = 0; it < nt; it++) {
        int buf = it & 1;
        const float* Ab = As + buf * ATILE64;
        const float* Bb = Bs + buf * ATILE64;
        load_frags(Ab, Bb, 0, wmblk, wnblk, fragoff, afb[0], bfb[0]);
        bool has_next = (it + 1) < nt;
        if (has_next) {
            int kt = (it + 1) << 6;
#pragma unroll
            for (int i = 0; i < 4; i++) {
                rA[i] = *(const float4*)(A + (size_t)(m0 + larow[i]) * lda + kt + lacol[i]);
                rB[i] = *(const float4*)(B + (size_t)(kt + lbkr[i]) * ldb + n0 + lbng[i]);
            }
        }
#pragma unroll
        for (int s = 0; s < 8; s++) {
            int cur = s & 1;
            if (s < 7)
                load_frags(Ab, Bb, s + 1, wmblk, wnblk, fragoff, afb[cur ^ 1], bfb[cur ^ 1]);
#pragma unroll
            for (int mi = 0; mi < 2; mi++)
#pragma unroll
                for (int ni = 0; ni < 4; ni++)
                    mma_tf32(acc[mi][ni], afb[cur][mi], bfb[cur][ni]);
        }
        if (has_next) {
            float* an = As + (buf ^ 1) * ATILE64;
            float* bn = Bs + (buf ^ 1) * ATILE64;
#pragma unroll
            for (int i = 0; i < 4; i++) {
                a_store4(an, abase[i], rA[i]);
                bn[bbase[i]]      = __uint_as_float(f2tf(rB[i].x));
                bn[bbase[i] + 8]  = __uint_as_float(f2tf(rB[i].y));
                bn[bbase[i] + 16] = __uint_as_float(f2tf(rB[i].z));
                bn[bbase[i] + 24] = __uint_as_float(f2tf(rB[i].w));
            }
            __syncthreads();
        }
    }

#pragma unroll
    for (int mi = 0; mi < 2; mi++) {
        int r = m0 + (wid & 3) * 32 + mi * 16 + g;
        float s0 = rscale ? rscale[r] : 1.f;
        float s1 = rscale ? rscale[r + 8] : 1.f;
#pragma unroll
        for (int ni = 0; ni < 4; ni++) {
            int col = n0 + (wid >> 2) * 32 + ni * 8 + cc * 2;
            *(float2*)(C + (size_t)r * ldc + col) =
                make_float2(acc[mi][ni][0] * s0, acc[mi][ni][1] * s0);
            *(float2*)(C + (size_t)(r + 8) * ldc + col) =
                make_float2(acc[mi][ni][2] * s1, acc[mi][ni][3] * s1);
        }
    }
}

// ---------------- rope table (double precision) ----------------
__global__ void rope_table(float* __restrict__ ctab, float* __restrict__ stab) {
    int t = blockIdx.x, i = threadIdx.x;
    double invf = pow(10000.0, -2.0 * (double)i / (double)HD);
    double ang = (double)t * invf;
    ctab[t * (HD / 2) + i] = (float)cos(ang);
    stab[t * (HD / 2) + i] = (float)sin(ang);
}

// ---------------- rmsnorm ----------------
__global__ void rmsnorm_kernel(const float* __restrict__ x, const float* __restrict__ w,
                               float* __restrict__ out, int ncols) {
    int row = blockIdx.x;
    const float* xr = x + (size_t)row * ncols;
    float ss = 0.f;
    for (int i = threadIdx.x; i < ncols; i += blockDim.x) {
        float v = xr[i];
        ss += v * v;
    }
    float tot = blk_sum(ss);
    float inv = rsqrtf(tot / (float)ncols + EPS);
    float* orow = out + (size_t)row * ncols;
    for (int i = threadIdx.x; i < ncols; i += blockDim.x)
        orow[i] = xr[i] * inv * w[i];
}

// ---------------- per-head q/k rmsnorm + rope (table lookup) ----------------
__global__ void qk_norm_rope(float* __restrict__ qkv,
                             const float* __restrict__ qw, const float* __restrict__ kw,
                             const float* __restrict__ ctab, const float* __restrict__ stab) {
    int t = blockIdx.x, h = blockIdx.y, which = blockIdx.z;
    float* base = qkv + (size_t)t * (3 * H) + (size_t)which * H + (size_t)h * HD;
    int d = threadIdx.x;
    float v = base[d];
    float tot = blk_sum(v * v);
    float inv = rsqrtf(tot / (float)HD + EPS);
    const float* w = which ? kw : qw;
    float nv = v * inv * w[d];
    __shared__ float buf[HD];
    buf[d] = nv;
    __syncthreads();
    if (d < HD / 2) {
        int i = d;
        float c = ctab[t * (HD / 2) + i];
        float s = stab[t * (HD / 2) + i];
        float t1 = buf[2 * i], t2 = buf[2 * i + 1];
        base[2 * i]     = t1 * c - t2 * s;
        base[2 * i + 1] = t1 * s + t2 * c;
    }
}

// ---------------- causal softmax: writes unnormalized exp + 1/sum per row ------------
__global__ void softmax_causal(float* __restrict__ S, float* __restrict__ rsum) {
    int t = blockIdx.x, h = blockIdx.y;
    float* row = S + ((size_t)h * T + t) * T;
    int n = t + 1;
    int fill_end = min(T, ((t >> 7) + 1) << 7);
    const float scale = 0.08838834764831845f;
    float mx = -3.4e38f;
    for (int j = threadIdx.x; j < n; j += blockDim.x)
        mx = fmaxf(mx, row[j] * scale);
    mx = blk_max(mx);
    float sum = 0.f;
    for (int j = threadIdx.x; j < n; j += blockDim.x) {
        float e = expf(row[j] * scale - mx);
        row[j] = e;
        sum += e;
    }
    sum = blk_sum(sum);
    if (threadIdx.x == 0) rsum[(size_t)h * T + t] = 1.f / sum;
    for (int j = n + (int)threadIdx.x; j < fill_end; j += blockDim.x) row[j] = 0.f;
}

// ---------------- routing ----------------
__global__ void gate_logits(const float* __restrict__ h2, const float* __restrict__ gw,
                            float* __restrict__ logits) {
    int t = blockIdx.x;
    __shared__ float xs[H];
    for (int i = threadIdx.x; i < H; i += blockDim.x) xs[i] = h2[(size_t)t * H + i];
    __syncthreads();
    int warp = threadIdx.x >> 5, lane = threadIdx.x & 31;
    for (int e = warp; e < NE; e += (blockDim.x >> 5)) {
        const float* w = gw + (size_t)e * H;
        float s = 0.f;
        for (int k = lane; k < H; k += 32) s += xs[k] * w[k];
#pragma unroll
        for (int o = 16; o; o >>= 1) s += __shfl_xor_sync(0xffffffffu, s, o);
        if (lane == 0) logits[(size_t)t * NE + e] = s;
    }
}

__global__ void route_topk(const float* __restrict__ logits, float* __restrict__ topw,
                           int* __restrict__ topi) {
    int t = blockIdx.x * blockDim.x + threadIdx.x;
    if (t >= T) return;
    float mx = -3.4e38f;
    int mi = 0;
#pragma unroll
    for (int e = 0; e < NE; e++) {
        float l = logits[(size_t)t * NE + e];
        if (l > mx) { mx = l; mi = e; }
    }
    float s = 0.f;
#pragma unroll
    for (int e = 0; e < NE; e++) s += expf(logits[(size_t)t * NE + e] - mx);
    topw[t] = 1.f / s;
    topi[t] = mi;
}

__global__ void zero_counts(int* c) {
    if (threadIdx.x < NE) c[threadIdx.x] = 0;
}

__global__ void build_route(const int* __restrict__ topi, int* __restrict__ counts,
                            int* __restrict__ rows) {
    int t = blockIdx.x * blockDim.x + threadIdx.x;
    if (t >= T) return;
    int e = topi[t];
    int p = atomicAdd(&counts[e], 1);
    rows[(size_t)e * T + p] = t;
}

// ---------------- host ----------------
#define SYM(p, s) do { void* _v; cudaGetSymbolAddress(&_v, s); p = (decltype(p))_v; } while (0)

extern "C" void kernel_launch(void* const* d_in, const int* in_sizes, int n_in,
                              void* d_out, int out_size) {
    const float* x      = (const float*)d_in[0];
    const float* ln1    = (const float*)d_in[1];
    const float* qkv_w  = (const float*)d_in[2];
    const float* qlnw   = (const float*)d_in[3];
    const float* klnw   = (const float*)d_in[4];
    const float* o_w    = (const float*)d_in[5];
    const float* ln2    = (const float*)d_in[6];
    const float* gate_w = (const float*)d_in[7];
    const float* egu    = (const float*)d_in[8];
    const float* edown  = (const float*)d_in[9];
    const float* sguw   = (const float*)d_in[10];
    const float* sdw    = (const float*)d_in[11];
    float* out = (float*)d_out;

    float *h, *qkv, *S, *rsum, *attn, *x2, *h2, *logits, *topw, *gu, *moe, *sgu, *ctab, *stab;
    int *topi, *counts, *rows;
    SYM(h, g_h); SYM(qkv, g_qkv); SYM(S, g_S); SYM(rsum, g_rsum); SYM(attn, g_attn);
    SYM(x2, g_x2); SYM(h2, g_h2); SYM(logits, g_logits); SYM(topw, g_topw);
    SYM(gu, g_gu); SYM(moe, g_moe); SYM(sgu, g_sgu);
    SYM(topi, g_topi); SYM(counts, g_counts); SYM(rows, g_rows);
    SYM(ctab, g_cos); SYM(stab, g_sin);

    cudaFuncSetAttribute(mma_nt, cudaFuncAttributeMaxDynamicSharedMemorySize, GSMEM);
    cudaFuncSetAttribute(mma_nn, cudaFuncAttributeMaxDynamicSharedMemorySize, GSMEM);

    rope_table<<<T, HD / 2>>>(ctab, stab);
    rmsnorm_kernel<<<T, 256>>>(x, ln1, h, H);
    // qkv = h @ qkv_w^T
    mma_nt<<<dim3(3 * H / TBN, T / TBM, 1), 512, GSMEM>>>(h, H, 0, qkv_w, H, 0, qkv, 3 * H, 0,
                                                          T, 3 * H, H, 0, 0, 0, 0, 0, 0, 0);
    qk_norm_rope<<<dim3(T, NH, 2), HD>>>(qkv, qlnw, klnw, ctab, stab);
    // S = Q K^T (causal block skip)
    mma_nt<<<dim3(T / TBN, T / TBM, NH), 512, GSMEM>>>(qkv, 3 * H, HD, qkv + H, 3 * H, HD,
                                                       S, T, (long long)T * T, T, T, HD,
                                                       0, 0, 1, 0, 0, 0, 0);
    // softmax: unnormalized exp + row 1/sum
    softmax_causal<<<dim3(T, NH), 256>>>(S, rsum);
    // attn = (E V) * (1/sum)  — normalization folded into PV epilogue
    mma_nn<<<dim3(HD / 128, T / 128, NH), 512, GSMEM>>>(S, T, (long long)T * T, qkv + 2 * H, 3 * H, HD,
                                                        attn, H, HD, T, HD, T, 1, rsum);
    // x2 = x + attn @ o_w^T
    mma_nt<<<dim3(H / TBN, T / TBM, 1), 512, GSMEM>>>(attn, H, 0, o_w, H, 0, x2, H, 0,
                                                      T, H, H, 0, 0, 0, 0, x, 0, 0);
    rmsnorm_kernel<<<T, 256>>>(x2, ln2, h2, H);
    gate_logits<<<T, 256>>>(h2, gate_w, logits);
    route_topk<<<(T + 255) / 256, 256>>>(logits, topw, topi);
    zero_counts<<<1, 32>>>(counts);
    build_route<<<(T + 255) / 256, 256>>>(topi, counts, rows);
    // MoE gate-up (gathered)
    mma_nt<<<dim3(I2 / TBN, T / TBM, NE), 512, GSMEM>>>(h2, H, 0, egu, H, (long long)I2 * H,
                                                        gu, I2, 0, T, I2, H, rows, counts, 0, 0, 0, 0, 0);
    // MoE down with fused silu(g)*u A-load (gathered)
    mma_nt<<<dim3(H / TBN, T / TBM, NE), 512, GSMEM>>>(gu, I2, 0, edown, II, (long long)H * II,
                                                       moe, H, 0, T, H, II, rows, counts, 0, 1, 0, 0, 0);
    // shared gate-up
    mma_nt<<<dim3(I2 / TBN, T / TBM, 1), 512, GSMEM>>>(h2, H, 0, sguw, H, 0, sgu, I2, 0,
                                                       T, I2, H, 0, 0, 0, 0, 0, 0, 0);
    // out = x2 + topw*moe + silu(sg)*su @ sdw^T (fused silu + fused final adds)
    mma_nt<<<dim3(H / TBN, T / TBM, 1), 512, GSMEM>>>(sgu, I2, 0, sdw, II, 0, out, H, 0,
                                                      T, H, II, 0, 0, 0, 1, x2, moe, topw);
}

// round 11
// speedup vs baseline: 1.1815x; 1.1815x over previous
#include <cuda_runtime.h>
#include <math.h>
#include <stdint.h>

#define T  2048
#define H  2048
#define NH 16
#define HD 128
#define NE 16
#define II 2048
#define I2 4096
#define EPS 1e-6f

#define TBM 128
#define TBN 128
#define TBK 64
#define KBLK_STR 33
#define MBLK_STR 133
#define APH 4256
#define ATILE64 (2 * APH)
#define GSMEM (4 * ATILE64 * 4)  // 136192 bytes

// ---------------- scratch ----------------
__device__ float g_h[(size_t)T * H];
__device__ float g_qkv[(size_t)T * 3 * H];
__device__ float g_S[(size_t)NH * T * T];
__device__ float g_rsum[(size_t)NH * T];
__device__ float g_attn[(size_t)T * H];
__device__ float g_x2[(size_t)T * H];
__device__ float g_h2[(size_t)T * H];
__device__ float g_logits[(size_t)T * NE];
__device__ float g_topw[T];
__device__ int   g_topi[T];
__device__ int   g_counts[NE];
__device__ int   g_rows[(size_t)NE * T];
__device__ float g_gu[(size_t)T * I2];
__device__ float g_act[(size_t)T * II];
__device__ float g_moe[(size_t)T * H];
__device__ float g_sgu[(size_t)T * I2];
__device__ float g_sact[(size_t)T * II];
__device__ float g_cos[(size_t)T * (HD / 2)];
__device__ float g_sin[(size_t)T * (HD / 2)];

// ---------------- helpers ----------------
__device__ __forceinline__ uint32_t f2tf(float x) {
    uint32_t u;
    asm("cvt.rna.tf32.f32 %0, %1;" : "=r"(u) : "f"(x));
    return u;
}

__device__ __forceinline__ void mma_tf32(float c[4], uint4 a, uint2 b) {
    asm volatile("mma.sync.aligned.m16n8k8.row.col.f32.tf32.tf32.f32 "
                 "{%0,%1,%2,%3}, {%4,%5,%6,%7}, {%8,%9}, {%0,%1,%2,%3};"
                 : "+f"(c[0]), "+f"(c[1]), "+f"(c[2]), "+f"(c[3])
                 : "r"(a.x), "r"(a.y), "r"(a.z), "r"(a.w), "r"(b.x), "r"(b.y));
}

__device__ __forceinline__ float blk_sum(float v) {
    __shared__ float sh[33];
    __syncthreads();
    int lane = threadIdx.x & 31, w = threadIdx.x >> 5;
#pragma unroll
    for (int o = 16; o; o >>= 1) v += __shfl_xor_sync(0xffffffffu, v, o);
    if (lane == 0) sh[w] = v;
    __syncthreads();
    if (threadIdx.x < 32) {
        int nw = (blockDim.x + 31) >> 5;
        float r = (threadIdx.x < nw) ? sh[threadIdx.x] : 0.f;
#pragma unroll
        for (int o = 16; o; o >>= 1) r += __shfl_xor_sync(0xffffffffu, r, o);
        if (threadIdx.x == 0) sh[32] = r;
    }
    __syncthreads();
    return sh[32];
}

__device__ __forceinline__ float blk_max(float v) {
    __shared__ float sh[33];
    __syncthreads();
    int lane = threadIdx.x & 31, w = threadIdx.x >> 5;
#pragma unroll
    for (int o = 16; o; o >>= 1) v = fmaxf(v, __shfl_xor_sync(0xffffffffu, v, o));
    if (lane == 0) sh[w] = v;
    __syncthreads();
    if (threadIdx.x < 32) {
        int nw = (blockDim.x + 31) >> 5;
        float r = (threadIdx.x < nw) ? sh[threadIdx.x] : -3.4e38f;
#pragma unroll
        for (int o = 16; o; o >>= 1) r = fmaxf(r, __shfl_xor_sync(0xffffffffu, r, o));
        if (threadIdx.x == 0) sh[32] = r;
    }
    __syncthreads();
    return sh[32];
}

__device__ __forceinline__ int a_perm_base(int r, int k0) {
    int mblk = r >> 4, g = r & 7, half = (r >> 3) & 1;
    int kblk = k0 >> 3, k4 = (k0 >> 2) & 1;
    return (mblk * MBLK_STR + kblk * KBLK_STR + g * 4) * 4 + (half + 2 * k4);
}
__device__ __forceinline__ int b_perm_base(int r, int k0) {
    int nblk = r >> 3, g = r & 7;
    int kblk = k0 >> 3, k4 = (k0 >> 2) & 1;
    return (nblk * MBLK_STR + kblk * KBLK_STR + g * 4) * 2 + k4;
}
__device__ __forceinline__ void a_store4(float* As, int base, float4 v) {
    As[base]      = __uint_as_float(f2tf(v.x));
    As[base + 4]  = __uint_as_float(f2tf(v.y));
    As[base + 8]  = __uint_as_float(f2tf(v.z));
    As[base + 12] = __uint_as_float(f2tf(v.w));
}
__device__ __forceinline__ void b_store4(float* Bs, int base, float4 v) {
    Bs[base]     = __uint_as_float(f2tf(v.x));
    Bs[base + 2] = __uint_as_float(f2tf(v.y));
    Bs[base + 4] = __uint_as_float(f2tf(v.z));
    Bs[base + 6] = __uint_as_float(f2tf(v.w));
}

__device__ __forceinline__ void load_frags(const float* Ab, const float* Bb, int sub,
                                           int wmblk, int wnblk, int fragoff,
                                           uint4 af[2], uint2 bf[4]) {
    int khalf = sub >> 2, kblk = sub & 3;
    const float* Ah = Ab + khalf * APH;
    const float* Bh = Bb + khalf * APH;
#pragma unroll
    for (int mi = 0; mi < 2; mi++)
        af[mi] = *(const uint4*)(Ah + ((wmblk + mi) * MBLK_STR + kblk * KBLK_STR + fragoff) * 4);
#pragma unroll
    for (int ni = 0; ni < 4; ni++)
        bf[ni] = *(const uint2*)(Bh + ((wnblk + ni) * MBLK_STR + kblk * KBLK_STR + fragoff) * 2);
}

// ---------------- tf32 GEMM NT (512 thr), TBK=64, frag double-buffered (R8-proven) ---
__global__ void __launch_bounds__(512) mma_nt(
    const float* __restrict__ A, int lda, long long sA,
    const float* __restrict__ B, int ldb, long long sB,
    float* __restrict__ C, int ldc, long long sC,
    int M, int N, int K,
    const int* __restrict__ rowsAll, const int* __restrict__ cntAll,
    int causal,
    const float* __restrict__ addA,
    const float* __restrict__ addS, const float* __restrict__ scaleVec)
{
    extern __shared__ float smem[];
    float* As = smem;
    float* Bs = smem + 2 * ATILE64;
    __shared__ int rid[TBM];

    int z = blockIdx.z;
    A += (size_t)z * sA; B += (size_t)z * sB; C += (size_t)z * sC;
    const int* rows = rowsAll ? rowsAll + (size_t)z * M : 0;
    int Mv = cntAll ? cntAll[z] : M;
    int m0 = blockIdx.y * TBM;
    if (m0 >= Mv) return;
    int n0 = blockIdx.x * TBN;
    if (causal && n0 > m0) return;

    int tid = threadIdx.x;
    if (tid < TBM) {
        int gm = m0 + tid;
        rid[tid] = rows ? (gm < Mv ? rows[gm] : -1) : gm;
    }
    __syncthreads();

    int lrow[4], lcol[4], ra[4], abase[4], bbase[4];
#pragma unroll
    for (int i = 0; i < 4; i++) {
        int idx = tid + i * 512;
        lrow[i] = idx >> 4;
        lcol[i] = (idx & 15) * 4;
        ra[i] = rid[lrow[i]];
        int khalf = lcol[i] >> 5, k0 = lcol[i] & 31;
        abase[i] = khalf * APH + a_perm_base(lrow[i], k0);
        bbase[i] = khalf * APH + b_perm_base(lrow[i], k0);
    }

    float4 rA[4], rB[4];
    const float4 z4 = make_float4(0.f, 0.f, 0.f, 0.f);
#pragma unroll
    for (int i = 0; i < 4; i++) {
        rA[i] = (ra[i] >= 0) ? *(const float4*)(A + (size_t)ra[i] * lda + lcol[i]) : z4;
        rB[i] = *(const float4*)(B + (size_t)(n0 + lrow[i]) * ldb + lcol[i]);
    }
#pragma unroll
    for (int i = 0; i < 4; i++) {
        a_store4(As, abase[i], rA[i]);
        b_store4(Bs, bbase[i], rB[i]);
    }
    __syncthreads();

    int lane = tid & 31, wid = tid >> 5;
    int wmblk = (wid & 3) * 2;
    int wnblk = (wid >> 2) * 4;
    int g = lane >> 2, cc = lane & 3;
    int fragoff = g * 4 + cc;

    float acc[2][4][4];
#pragma unroll
    for (int mi = 0; mi < 2; mi++)
#pragma unroll
        for (int ni = 0; ni < 4; ni++)
#pragma unroll
            for (int j = 0; j < 4; j++) acc[mi][ni][j] = 0.f;

    uint4 afb[2][2];
    uint2 bfb[2][4];
    int nt = K >> 6;
    for (int it = 0; it < nt; it++) {
        int buf = it & 1;
        const float* Ab = As + buf * ATILE64;
        const float* Bb = Bs + buf * ATILE64;
        load_frags(Ab, Bb, 0, wmblk, wnblk, fragoff, afb[0], bfb[0]);
        bool has_next = (it + 1) < nt;
        if (has_next) {
            int kt = (it + 1) << 6;
#pragma unroll
            for (int i = 0; i < 4; i++) {
                rA[i] = (ra[i] >= 0) ? *(const float4*)(A + (size_t)ra[i] * lda + kt + lcol[i]) : z4;
                rB[i] = *(const float4*)(B + (size_t)(n0 + lrow[i]) * ldb + kt + lcol[i]);
            }
        }
#pragma unroll
        for (int s = 0; s < 8; s++) {
            int cur = s & 1;
            if (s < 7)
                load_frags(Ab, Bb, s + 1, wmblk, wnblk, fragoff, afb[cur ^ 1], bfb[cur ^ 1]);
#pragma unroll
            for (int mi = 0; mi < 2; mi++)
#pragma unroll
                for (int ni = 0; ni < 4; ni++)
                    mma_tf32(acc[mi][ni], afb[cur][mi], bfb[cur][ni]);
        }
        if (has_next) {
            float* an = As + (buf ^ 1) * ATILE64;
            float* bn = Bs + (buf ^ 1) * ATILE64;
#pragma unroll
            for (int i = 0; i < 4; i++) {
                a_store4(an, abase[i], rA[i]);
                b_store4(bn, bbase[i], rB[i]);
            }
            __syncthreads();
        }
    }

#pragma unroll
    for (int mi = 0; mi < 2; mi++) {
        int r0 = (wid & 3) * 32 + mi * 16 + g;
        int rr[2] = { rid[r0], rid[r0 + 8] };
#pragma unroll
        for (int half = 0; half < 2; half++) {
            int r = rr[half];
            if (r < 0) continue;
#pragma unroll
            for (int ni = 0; ni < 4; ni++) {
                int col = n0 + (wid >> 2) * 32 + ni * 8 + cc * 2;
                float2 v = make_float2(acc[mi][ni][half * 2], acc[mi][ni][half * 2 + 1]);
                if (addA) {
                    float2 a = *(const float2*)(addA + (size_t)r * ldc + col);
                    v.x += a.x; v.y += a.y;
                }
                if (addS) {
                    float w = scaleVec[r];
                    float2 s = *(const float2*)(addS + (size_t)r * ldc + col);
                    v.x += s.x * w; v.y += s.y * w;
                }
                *(float2*)(C + (size_t)r * ldc + col) = v;
            }
        }
    }
}

// ---------------- tf32 GEMM NN (512 thr), TBK=64, row-scaled epilogue ----------------
__global__ void __launch_bounds__(512) mma_nn(
    const float* __restrict__ A, int lda, long long sA,
    const float* __restrict__ B, int ldb, long long sB,
    float* __restrict__ C, int ldc, long long sC,
    int M, int N, int K, int kcap,
    const float* __restrict__ rscaleAll)
{
    extern __shared__ float smem[];
    float* As = smem;
    float* Bs = smem + 2 * ATILE64;

    int z = blockIdx.z;
    A += (size_t)z * sA; B += (size_t)z * sB; C += (size_t)z * sC;
    const float* rscale = rscaleAll ? rscaleAll + (size_t)z * M : 0;
    int m0 = blockIdx.y * 128;
    int n0 = blockIdx.x * 128;
    int Keff = kcap ? min(K, m0 + 128) : K;

    int tid = threadIdx.x;
    int larow[4], lacol[4], abase[4];
    int lbkr[4], lbng[4], bbase[4];
#pragma unroll
    for (int i = 0; i < 4; i++) {
        int idx = tid + i * 512;
        larow[i] = idx >> 4;
        lacol[i] = (idx & 15) * 4;
        int khalfA = lacol[i] >> 5, k0A = lacol[i] & 31;
        abase[i] = khalfA * APH + a_perm_base(larow[i], k0A);
        lbkr[i] = idx >> 5;
        lbng[i] = (idx & 31) * 4;
        int khalfB = lbkr[i] >> 5, kr = lbkr[i] & 31;
        int kblk = kr >> 3, ccB = kr & 3, k4 = (kr >> 2) & 1;
        int nblk = lbng[i] >> 3, g0 = lbng[i] & 7;
        bbase[i] = khalfB * APH + (nblk * MBLK_STR + kblk * KBLK_STR + g0 * 4 + ccB) * 2 + k4;
    }

    float4 rA[4], rB[4];
#pragma unroll
    for (int i = 0; i < 4; i++) {
        rA[i] = *(const float4*)(A + (size_t)(m0 + larow[i]) * lda + lacol[i]);
        rB[i] = *(const float4*)(B + (size_t)lbkr[i] * ldb + n0 + lbng[i]);
    }
#pragma unroll
    for (int i = 0; i < 4; i++) {
        a_store4(As, abase[i], rA[i]);
        Bs[bbase[i]]      = __uint_as_float(f2tf(rB[i].x));
        Bs[bbase[i] + 8]  = __uint_as_float(f2tf(rB[i].y));
        Bs[bbase[i] + 16] = __uint_as_float(f2tf(rB[i].z));
        Bs[bbase[i] + 24] = __uint_as_float(f2tf(rB[i].w));
    }
    __syncthreads();

    int lane = tid & 31, wid = tid >> 5;
    int wmblk = (wid & 3) * 2, wnblk = (wid >> 2) * 4;
    int g = lane >> 2, cc = lane & 3;
    int fragoff = g * 4 + cc;

    float acc[2][4][4];
#pragma unroll
    for (int mi = 0; mi < 2; mi++)
#pragma unroll
        for (int ni = 0; ni < 4; ni++)
#pragma unroll
            for (int j = 0; j < 4; j++) acc[mi][ni][j] = 0.f;

    uint4 afb[2][2];
    uint2 bfb[2][4];
    int nt = Keff >> 6;
    for (int it = 0; it < nt; it++) {
        int buf = it & 1;
        const float* Ab = As + buf * ATILE64;
        const float* Bb = Bs + buf * ATILE64;
        load_frags(Ab, Bb, 0, wmblk, wnblk, fragoff, afb[0], bfb[0]);
        bool has_next = (it + 1) < nt;
        if (has_next) {
            int kt = (it + 1) << 6;
#pragma unroll
            for (int i = 0; i < 4; i++) {
                rA[i] = *(const float4*)(A + (size_t)(m0 + larow[i]) * lda + kt + lacol[i]);
                rB[i] = *(const float4*)(B + (size_t)(kt + lbkr[i]) * ldb + n0 + lbng[i]);
            }
        }
#pragma unroll
        for (int s = 0; s < 8; s++) {
            int cur = s & 1;
            if (s < 7)
                load_frags(Ab, Bb, s + 1, wmblk, wnblk, fragoff, afb[cur ^ 1], bfb[cur ^ 1]);
#pragma unroll
            for (int mi = 0; mi < 2; mi++)
#pragma unroll
                for (int ni = 0; ni < 4; ni++)
                    mma_tf32(acc[mi][ni], afb[cur][mi], bfb[cur][ni]);
        }
        if (has_next) {
            float* an = As + (buf ^ 1) * ATILE64;
            float* bn = Bs + (buf ^ 1) * ATILE64;
#pragma unroll
            for (int i = 0; i < 4; i++) {
                a_store4(an, abase[i], rA[i]);
                bn[bbase[i]]      = __uint_as_float(f2tf(rB[i].x));
                bn[bbase[i] + 8]  = __uint_as_float(f2tf(rB[i].y));
                bn[bbase[i] + 16] = __uint_as_float(f2tf(rB[i].z));
                bn[bbase[i] + 24] = __uint_as_float(f2tf(rB[i].w));
            }
            __syncthreads();
        }
    }

#pragma unroll
    for (int mi = 0; mi < 2; mi++) {
        int r = m0 + (wid & 3) * 32 + mi * 16 + g;
        float s0 = rscale ? rscale[r] : 1.f;
        float s1 = rscale ? rscale[r + 8] : 1.f;
#pragma unroll
        for (int ni = 0; ni < 4; ni++) {
            int col = n0 + (wid >> 2) * 32 + ni * 8 + cc * 2;
            *(float2*)(C + (size_t)r * ldc + col) =
                make_float2(acc[mi][ni][0] * s0, acc[mi][ni][1] * s0);
            *(float2*)(C + (size_t)(r + 8) * ldc + col) =
                make_float2(acc[mi][ni][2] * s1, acc[mi][ni][3] * s1);
        }
    }
}

// ---------------- rope table (double precision) ----------------
__global__ void rope_table(float* __restrict__ ctab, float* __restrict__ stab) {
    int t = blockIdx.x, i = threadIdx.x;
    double invf = pow(10000.0, -2.0 * (double)i / (double)HD);
    double ang = (double)t * invf;
    ctab[t * (HD / 2) + i] = (float)cos(ang);
    stab[t * (HD / 2) + i] = (float)sin(ang);
}

// ---------------- rmsnorm ----------------
__global__ void rmsnorm_kernel(const float* __restrict__ x, const float* __restrict__ w,
                               float* __restrict__ out, int ncols) {
    int row = blockIdx.x;
    const float* xr = x + (size_t)row * ncols;
    float ss = 0.f;
    for (int i = threadIdx.x; i < ncols; i += blockDim.x) {
        float v = xr[i];
        ss += v * v;
    }
    float tot = blk_sum(ss);
    float inv = rsqrtf(tot / (float)ncols + EPS);
    float* orow = out + (size_t)row * ncols;
    for (int i = threadIdx.x; i < ncols; i += blockDim.x)
        orow[i] = xr[i] * inv * w[i];
}

// ---------------- q/k rmsnorm + rope: warp-per-row, no block barriers ---------------
__global__ void __launch_bounds__(512) qk_norm_rope(
    float* __restrict__ qkv,
    const float* __restrict__ qw, const float* __restrict__ kw,
    const float* __restrict__ ctab, const float* __restrict__ stab)
{
    int t = blockIdx.x;
    int wid = threadIdx.x >> 5, lane = threadIdx.x & 31;
#pragma unroll
    for (int r = wid; r < 2 * NH; r += 16) {
        int which = r >> 4, h = r & (NH - 1);
        float* base = qkv + (size_t)t * (3 * H) + (size_t)which * H + (size_t)h * HD;
        float4 v = *(float4*)(base + lane * 4);
        float ss = v.x * v.x + v.y * v.y + v.z * v.z + v.w * v.w;
#pragma unroll
        for (int o = 16; o; o >>= 1) ss += __shfl_xor_sync(0xffffffffu, ss, o);
        float inv = rsqrtf(ss / (float)HD + EPS);
        const float* w = which ? kw : qw;
        float4 wv = *(const float4*)(w + lane * 4);
        float n0 = v.x * inv * wv.x, n1 = v.y * inv * wv.y;
        float n2 = v.z * inv * wv.z, n3 = v.w * inv * wv.w;
        int i0 = lane * 2, i1 = lane * 2 + 1;
        float c0 = ctab[t * (HD / 2) + i0], s0 = stab[t * (HD / 2) + i0];
        float c1 = ctab[t * (HD / 2) + i1], s1 = stab[t * (HD / 2) + i1];
        float4 o;
        o.x = n0 * c0 - n1 * s0;
        o.y = n0 * s0 + n1 * c0;
        o.z = n2 * c1 - n3 * s1;
        o.w = n2 * s1 + n3 * c1;
        *(float4*)(base + lane * 4) = o;
    }
}

// ---------------- causal softmax: unnormalized exp + 1/sum per row ------------------
__global__ void softmax_causal(float* __restrict__ S, float* __restrict__ rsum) {
    int t = blockIdx.x, h = blockIdx.y;
    float* row = S + ((size_t)h * T + t) * T;
    int n = t + 1;
    int fill_end = min(T, ((t >> 7) + 1) << 7);
    const float scale = 0.08838834764831845f;
    float mx = -3.4e38f;
    for (int j = threadIdx.x; j < n; j += blockDim.x)
        mx = fmaxf(mx, row[j] * scale);
    mx = blk_max(mx);
    float sum = 0.f;
    for (int j = threadIdx.x; j < n; j += blockDim.x) {
        float e = expf(row[j] * scale - mx);
        row[j] = e;
        sum += e;
    }
    sum = blk_sum(sum);
    if (threadIdx.x == 0) rsum[(size_t)h * T + t] = 1.f / sum;
    for (int j = n + (int)threadIdx.x; j < fill_end; j += blockDim.x) row[j] = 0.f;
}

// ---------------- elementwise ----------------
__global__ void silu_mul(const float* __restrict__ gu, float* __restrict__ act) {
    int idx = blockIdx.x * blockDim.x + threadIdx.x;
    if (idx >= T * II) return;
    int t = idx / II, i = idx % II;
    float g = gu[(size_t)t * I2 + i];
    float u = gu[(size_t)t * I2 + II + i];
    act[(size_t)t * II + i] = (g / (1.f + expf(-g))) * u;
}

// ---------------- routing ----------------
__global__ void gate_logits(const float* __restrict__ h2, const float* __restrict__ gw,
                            float* __restrict__ logits) {
    int t = blockIdx.x;
    __shared__ float xs[H];
    for (int i = threadIdx.x; i < H; i += blockDim.x) xs[i] = h2[(size_t)t * H + i];
    __syncthreads();
    int warp = threadIdx.x >> 5, lane = threadIdx.x & 31;
    for (int e = warp; e < NE; e += (blockDim.x >> 5)) {
        const float* w = gw + (size_t)e * H;
        float s = 0.f;
        for (int k = lane; k < H; k += 32) s += xs[k] * w[k];
#pragma unroll
        for (int o = 16; o; o >>= 1) s += __shfl_xor_sync(0xffffffffu, s, o);
        if (lane == 0) logits[(size_t)t * NE + e] = s;
    }
}

__global__ void route_topk(const float* __restrict__ logits, float* __restrict__ topw,
                           int* __restrict__ topi) {
    int t = blockIdx.x * blockDim.x + threadIdx.x;
    if (t >= T) return;
    float mx = -3.4e38f;
    int mi = 0;
#pragma unroll
    for (int e = 0; e < NE; e++) {
        float l = logits[(size_t)t * NE + e];
        if (l > mx) { mx = l; mi = e; }
    }
    float s = 0.f;
#pragma unroll
    for (int e = 0; e < NE; e++) s += expf(logits[(size_t)t * NE + e] - mx);
    topw[t] = 1.f / s;
    topi[t] = mi;
}

__global__ void zero_counts(int* c) {
    if (threadIdx.x < NE) c[threadIdx.x] = 0;
}

__global__ void build_route(const int* __restrict__ topi, int* __restrict__ counts,
                            int* __restrict__ rows) {
    int t = blockIdx.x * blockDim.x + threadIdx.x;
    if (t >= T) return;
    int e = topi[t];
    int p = atomicAdd(&counts[e], 1);
    rows[(size_t)e * T + p] = t;
}

// ---------------- host ----------------
#define SYM(p, s) do { void* _v; cudaGetSymbolAddress(&_v, s); p = (decltype(p))_v; } while (0)

extern "C" void kernel_launch(void* const* d_in, const int* in_sizes, int n_in,
                              void* d_out, int out_size) {
    const float* x      = (const float*)d_in[0];
    const float* ln1    = (const float*)d_in[1];
    const float* qkv_w  = (const float*)d_in[2];
    const float* qlnw   = (const float*)d_in[3];
    const float* klnw   = (const float*)d_in[4];
    const float* o_w    = (const float*)d_in[5];
    const float* ln2    = (const float*)d_in[6];
    const float* gate_w = (const float*)d_in[7];
    const float* egu    = (const float*)d_in[8];
    const float* edown  = (const float*)d_in[9];
    const float* sguw   = (const float*)d_in[10];
    const float* sdw    = (const float*)d_in[11];
    float* out = (float*)d_out;

    float *h, *qkv, *S, *rsum, *attn, *x2, *h2, *logits, *topw, *gu, *act, *moe, *sgu, *sact;
    float *ctab, *stab;
    int *topi, *counts, *rows;
    SYM(h, g_h); SYM(qkv, g_qkv); SYM(S, g_S); SYM(rsum, g_rsum); SYM(attn, g_attn);
    SYM(x2, g_x2); SYM(h2, g_h2); SYM(logits, g_logits); SYM(topw, g_topw);
    SYM(gu, g_gu); SYM(act, g_act); SYM(moe, g_moe); SYM(sgu, g_sgu); SYM(sact, g_sact);
    SYM(topi, g_topi); SYM(counts, g_counts); SYM(rows, g_rows);
    SYM(ctab, g_cos); SYM(stab, g_sin);

    cudaFuncSetAttribute(mma_nt, cudaFuncAttributeMaxDynamicSharedMemorySize, GSMEM);
    cudaFuncSetAttribute(mma_nn, cudaFuncAttributeMaxDynamicSharedMemorySize, GSMEM);

    rope_table<<<T, HD / 2>>>(ctab, stab);
    rmsnorm_kernel<<<T, 256>>>(x, ln1, h, H);
    // qkv = h @ qkv_w^T
    mma_nt<<<dim3(3 * H / TBN, T / TBM, 1), 512, GSMEM>>>(h, H, 0, qkv_w, H, 0, qkv, 3 * H, 0,
                                                          T, 3 * H, H, 0, 0, 0, 0, 0, 0);
    // warp-parallel q/k norm + rope
    qk_norm_rope<<<T, 512>>>(qkv, qlnw, klnw, ctab, stab);
    // S = Q K^T (causal block skip)
    mma_nt<<<dim3(T / TBN, T / TBM, NH), 512, GSMEM>>>(qkv, 3 * H, HD, qkv + H, 3 * H, HD,
                                                       S, T, (long long)T * T, T, T, HD,
                                                       0, 0, 1, 0, 0, 0);
    // softmax: unnormalized exp + row 1/sum
    softmax_causal<<<dim3(T, NH), 256>>>(S, rsum);
    // attn = (E V) * (1/sum): normalization folded into PV epilogue
    mma_nn<<<dim3(HD / 128, T / 128, NH), 512, GSMEM>>>(S, T, (long long)T * T, qkv + 2 * H, 3 * H, HD,
                                                        attn, H, HD, T, HD, T, 1, rsum);
    // x2 = x + attn @ o_w^T
    mma_nt<<<dim3(H / TBN, T / TBM, 1), 512, GSMEM>>>(attn, H, 0, o_w, H, 0, x2, H, 0,
                                                      T, H, H, 0, 0, 0, x, 0, 0);
    rmsnorm_kernel<<<T, 256>>>(x2, ln2, h2, H);
    gate_logits<<<T, 256>>>(h2, gate_w, logits);
    route_topk<<<(T + 255) / 256, 256>>>(logits, topw, topi);
    zero_counts<<<1, 32>>>(counts);
    build_route<<<(T + 255) / 256, 256>>>(topi, counts, rows);
    // MoE (top-1, gathered) — unfused silu (R8-proven)
    mma_nt<<<dim3(I2 / TBN, T / TBM, NE), 512, GSMEM>>>(h2, H, 0, egu, H, (long long)I2 * H,
                                                        gu, I2, 0, T, I2, H, rows, counts, 0, 0, 0, 0);
    silu_mul<<<(T * II + 255) / 256, 256>>>(gu, act);
    mma_nt<<<dim3(H / TBN, T / TBM, NE), 512, GSMEM>>>(act, II, 0, edown, II, (long long)H * II,
                                                       moe, H, 0, T, H, II, rows, counts, 0, 0, 0, 0);
    // shared FFN
    mma_nt<<<dim3(I2 / TBN, T / TBM, 1), 512, GSMEM>>>(h2, H, 0, sguw, H, 0, sgu, I2, 0,
                                                       T, I2, H, 0, 0, 0, 0, 0, 0);
    silu_mul<<<(T * II + 255) / 256, 256>>>(sgu, sact);
    // out = x2 + topw*moe + sact @ sdw^T
    mma_nt<<<dim3(H / TBN, T / TBM, 1), 512, GSMEM>>>(sact, II, 0, sdw, II, 0, out, H, 0,
                                                      T, H, II, 0, 0, 0, x2, moe, topw);
}

// round 12
// speedup vs baseline: 1.1937x; 1.0103x over previous
#include <cuda_runtime.h>
#include <math.h>
#include <stdint.h>

#define T  2048
#define H  2048
#define NH 16
#define HD 128
#define NE 16
#define II 2048
#define I2 4096
#define EPS 1e-6f

#define TBM 128
#define TBN 128
#define TBK 64
#define KBLK_STR 33
#define MBLK_STR 133
#define APH 4256
#define ATILE64 (2 * APH)
#define GSMEM (4 * ATILE64 * 4)  // 136192 bytes

// ---------------- scratch ----------------
__device__ float g_h[(size_t)T * H];
__device__ float g_qkv[(size_t)T * 3 * H];
__device__ float g_S[(size_t)NH * T * T];
__device__ float g_rsum[(size_t)NH * T];
__device__ float g_attn[(size_t)T * H];
__device__ float g_x2[(size_t)T * H];
__device__ float g_h2[(size_t)T * H];
__device__ float g_logits[(size_t)T * NE];
__device__ float g_topw[T];
__device__ int   g_counts[NE];
__device__ int   g_rows[(size_t)NE * T];
__device__ float g_gu[(size_t)T * I2];
__device__ float g_act[(size_t)T * II];
__device__ float g_moe[(size_t)T * H];
__device__ float g_sgu[(size_t)T * I2];
__device__ float g_sact[(size_t)T * II];
__device__ float g_cos[(size_t)T * (HD / 2)];
__device__ float g_sin[(size_t)T * (HD / 2)];

// ---------------- helpers ----------------
__device__ __forceinline__ uint32_t f2tf(float x) {
    uint32_t u;
    asm("cvt.rna.tf32.f32 %0, %1;" : "=r"(u) : "f"(x));
    return u;
}

__device__ __forceinline__ void mma_tf32(float c[4], uint4 a, uint2 b) {
    asm volatile("mma.sync.aligned.m16n8k8.row.col.f32.tf32.tf32.f32 "
                 "{%0,%1,%2,%3}, {%4,%5,%6,%7}, {%8,%9}, {%0,%1,%2,%3};"
                 : "+f"(c[0]), "+f"(c[1]), "+f"(c[2]), "+f"(c[3])
                 : "r"(a.x), "r"(a.y), "r"(a.z), "r"(a.w), "r"(b.x), "r"(b.y));
}

__device__ __forceinline__ float blk_sum(float v) {
    __shared__ float sh[33];
    __syncthreads();
    int lane = threadIdx.x & 31, w = threadIdx.x >> 5;
#pragma unroll
    for (int o = 16; o; o >>= 1) v += __shfl_xor_sync(0xffffffffu, v, o);
    if (lane == 0) sh[w] = v;
    __syncthreads();
    if (threadIdx.x < 32) {
        int nw = (blockDim.x + 31) >> 5;
        float r = (threadIdx.x < nw) ? sh[threadIdx.x] : 0.f;
#pragma unroll
        for (int o = 16; o; o >>= 1) r += __shfl_xor_sync(0xffffffffu, r, o);
        if (threadIdx.x == 0) sh[32] = r;
    }
    __syncthreads();
    return sh[32];
}

__device__ __forceinline__ float blk_max(float v) {
    __shared__ float sh[33];
    __syncthreads();
    int lane = threadIdx.x & 31, w = threadIdx.x >> 5;
#pragma unroll
    for (int o = 16; o; o >>= 1) v = fmaxf(v, __shfl_xor_sync(0xffffffffu, v, o));
    if (lane == 0) sh[w] = v;
    __syncthreads();
    if (threadIdx.x < 32) {
        int nw = (blockDim.x + 31) >> 5;
        float r = (threadIdx.x < nw) ? sh[threadIdx.x] : -3.4e38f;
#pragma unroll
        for (int o = 16; o; o >>= 1) r = fmaxf(r, __shfl_xor_sync(0xffffffffu, r, o));
        if (threadIdx.x == 0) sh[32] = r;
    }
    __syncthreads();
    return sh[32];
}

__device__ __forceinline__ int a_perm_base(int r, int k0) {
    int mblk = r >> 4, g = r & 7, half = (r >> 3) & 1;
    int kblk = k0 >> 3, k4 = (k0 >> 2) & 1;
    return (mblk * MBLK_STR + kblk * KBLK_STR + g * 4) * 4 + (half + 2 * k4);
}
__device__ __forceinline__ int b_perm_base(int r, int k0) {
    int nblk = r >> 3, g = r & 7;
    int kblk = k0 >> 3, k4 = (k0 >> 2) & 1;
    return (nblk * MBLK_STR + kblk * KBLK_STR + g * 4) * 2 + k4;
}
__device__ __forceinline__ void a_store4(float* As, int base, float4 v) {
    As[base]      = __uint_as_float(f2tf(v.x));
    As[base + 4]  = __uint_as_float(f2tf(v.y));
    As[base + 8]  = __uint_as_float(f2tf(v.z));
    As[base + 12] = __uint_as_float(f2tf(v.w));
}
__device__ __forceinline__ void b_store4(float* Bs, int base, float4 v) {
    Bs[base]     = __uint_as_float(f2tf(v.x));
    Bs[base + 2] = __uint_as_float(f2tf(v.y));
    Bs[base + 4] = __uint_as_float(f2tf(v.z));
    Bs[base + 6] = __uint_as_float(f2tf(v.w));
}

__device__ __forceinline__ void load_frags(const float* Ab, const float* Bb, int sub,
                                           int wmblk, int wnblk, int fragoff,
                                           uint4 af[2], uint2 bf[4]) {
    int khalf = sub >> 2, kblk = sub & 3;
    const float* Ah = Ab + khalf * APH;
    const float* Bh = Bb + khalf * APH;
#pragma unroll
    for (int mi = 0; mi < 2; mi++)
        af[mi] = *(const uint4*)(Ah + ((wmblk + mi) * MBLK_STR + kblk * KBLK_STR + fragoff) * 4);
#pragma unroll
    for (int ni = 0; ni < 4; ni++)
        bf[ni] = *(const uint2*)(Bh + ((wnblk + ni) * MBLK_STR + kblk * KBLK_STR + fragoff) * 2);
}

// ---------------- tf32 GEMM NT (512 thr), TBK=64, frag double-buffered (proven) ------
__global__ void __launch_bounds__(512) mma_nt(
    const float* __restrict__ A, int lda, long long sA,
    const float* __restrict__ B, int ldb, long long sB,
    float* __restrict__ C, int ldc, long long sC,
    int M, int N, int K,
    const int* __restrict__ rowsAll, const int* __restrict__ cntAll,
    int causal,
    const float* __restrict__ addA,
    const float* __restrict__ addS, const float* __restrict__ scaleVec)
{
    extern __shared__ float smem[];
    float* As = smem;
    float* Bs = smem + 2 * ATILE64;
    __shared__ int rid[TBM];

    int z = blockIdx.z;
    A += (size_t)z * sA; B += (size_t)z * sB; C += (size_t)z * sC;
    const int* rows = rowsAll ? rowsAll + (size_t)z * M : 0;
    int Mv = cntAll ? cntAll[z] : M;
    int m0 = blockIdx.y * TBM;
    if (m0 >= Mv) return;
    int n0 = blockIdx.x * TBN;
    if (causal && n0 > m0) return;

    int tid = threadIdx.x;
    if (tid < TBM) {
        int gm = m0 + tid;
        rid[tid] = rows ? (gm < Mv ? rows[gm] : -1) : gm;
    }
    __syncthreads();

    int lrow[4], lcol[4], ra[4], abase[4], bbase[4];
#pragma unroll
    for (int i = 0; i < 4; i++) {
        int idx = tid + i * 512;
        lrow[i] = idx >> 4;
        lcol[i] = (idx & 15) * 4;
        ra[i] = rid[lrow[i]];
        int khalf = lcol[i] >> 5, k0 = lcol[i] & 31;
        abase[i] = khalf * APH + a_perm_base(lrow[i], k0);
        bbase[i] = khalf * APH + b_perm_base(lrow[i], k0);
    }

    float4 rA[4], rB[4];
    const float4 z4 = make_float4(0.f, 0.f, 0.f, 0.f);
#pragma unroll
    for (int i = 0; i < 4; i++) {
        rA[i] = (ra[i] >= 0) ? *(const float4*)(A + (size_t)ra[i] * lda + lcol[i]) : z4;
        rB[i] = *(const float4*)(B + (size_t)(n0 + lrow[i]) * ldb + lcol[i]);
    }
#pragma unroll
    for (int i = 0; i < 4; i++) {
        a_store4(As, abase[i], rA[i]);
        b_store4(Bs, bbase[i], rB[i]);
    }
    __syncthreads();

    int lane = tid & 31, wid = tid >> 5;
    int wmblk = (wid & 3) * 2;
    int wnblk = (wid >> 2) * 4;
    int g = lane >> 2, cc = lane & 3;
    int fragoff = g * 4 + cc;

    float acc[2][4][4];
#pragma unroll
    for (int mi = 0; mi < 2; mi++)
#pragma unroll
        for (int ni = 0; ni < 4; ni++)
#pragma unroll
            for (int j = 0; j < 4; j++) acc[mi][ni][j] = 0.f;

    uint4 afb[2][2];
    uint2 bfb[2][4];
    int nt = K >> 6;
    for (int it = 0; it < nt; it++) {
        int buf = it & 1;
        const float* Ab = As + buf * ATILE64;
        const float* Bb = Bs + buf * ATILE64;
        load_frags(Ab, Bb, 0, wmblk, wnblk, fragoff, afb[0], bfb[0]);
        bool has_next = (it + 1) < nt;
        if (has_next) {
            int kt = (it + 1) << 6;
#pragma unroll
            for (int i = 0; i < 4; i++) {
                rA[i] = (ra[i] >= 0) ? *(const float4*)(A + (size_t)ra[i] * lda + kt + lcol[i]) : z4;
                rB[i] = *(const float4*)(B + (size_t)(n0 + lrow[i]) * ldb + kt + lcol[i]);
            }
        }
#pragma unroll
        for (int s = 0; s < 8; s++) {
            int cur = s & 1;
            if (s < 7)
                load_frags(Ab, Bb, s + 1, wmblk, wnblk, fragoff, afb[cur ^ 1], bfb[cur ^ 1]);
#pragma unroll
            for (int mi = 0; mi < 2; mi++)
#pragma unroll
                for (int ni = 0; ni < 4; ni++)
                    mma_tf32(acc[mi][ni], afb[cur][mi], bfb[cur][ni]);
        }
        if (has_next) {
            float* an = As + (buf ^ 1) * ATILE64;
            float* bn = Bs + (buf ^ 1) * ATILE64;
#pragma unroll
            for (int i = 0; i < 4; i++) {
                a_store4(an, abase[i], rA[i]);
                b_store4(bn, bbase[i], rB[i]);
            }
            __syncthreads();
        }
    }

#pragma unroll
    for (int mi = 0; mi < 2; mi++) {
        int r0 = (wid & 3) * 32 + mi * 16 + g;
        int rr[2] = { rid[r0], rid[r0 + 8] };
#pragma unroll
        for (int half = 0; half < 2; half++) {
            int r = rr[half];
            if (r < 0) continue;
#pragma unroll
            for (int ni = 0; ni < 4; ni++) {
                int col = n0 + (wid >> 2) * 32 + ni * 8 + cc * 2;
                float2 v = make_float2(acc[mi][ni][half * 2], acc[mi][ni][half * 2 + 1]);
                if (addA) {
                    float2 a = *(const float2*)(addA + (size_t)r * ldc + col);
                    v.x += a.x; v.y += a.y;
                }
                if (addS) {
                    float w = scaleVec[r];
                    float2 s = *(const float2*)(addS + (size_t)r * ldc + col);
                    v.x += s.x * w; v.y += s.y * w;
                }
                *(float2*)(C + (size_t)r * ldc + col) = v;
            }
        }
    }
}

// ---------------- tf32 GEMM NN (512 thr), TBK=64, row-scaled epilogue ----------------
__global__ void __launch_bounds__(512) mma_nn(
    const float* __restrict__ A, int lda, long long sA,
    const float* __restrict__ B, int ldb, long long sB,
    float* __restrict__ C, int ldc, long long sC,
    int M, int N, int K, int kcap,
    const float* __restrict__ rscaleAll)
{
    extern __shared__ float smem[];
    float* As = smem;
    float* Bs = smem + 2 * ATILE64;

    int z = blockIdx.z;
    A += (size_t)z * sA; B += (size_t)z * sB; C += (size_t)z * sC;
    const float* rscale = rscaleAll ? rscaleAll + (size_t)z * M : 0;
    int m0 = blockIdx.y * 128;
    int n0 = blockIdx.x * 128;
    int Keff = kcap ? min(K, m0 + 128) : K;

    int tid = threadIdx.x;
    int larow[4], lacol[4], abase[4];
    int lbkr[4], lbng[4], bbase[4];
#pragma unroll
    for (int i = 0; i < 4; i++) {
        int idx = tid + i * 512;
        larow[i] = idx >> 4;
        lacol[i] = (idx & 15) * 4;
        int khalfA = lacol[i] >> 5, k0A = lacol[i] & 31;
        abase[i] = khalfA * APH + a_perm_base(larow[i], k0A);
        lbkr[i] = idx >> 5;
        lbng[i] = (idx & 31) * 4;
        int khalfB = lbkr[i] >> 5, kr = lbkr[i] & 31;
        int kblk = kr >> 3, ccB = kr & 3, k4 = (kr >> 2) & 1;
        int nblk = lbng[i] >> 3, g0 = lbng[i] & 7;
        bbase[i] = khalfB * APH + (nblk * MBLK_STR + kblk * KBLK_STR + g0 * 4 + ccB) * 2 + k4;
    }

    float4 rA[4], rB[4];
#pragma unroll
    for (int i = 0; i < 4; i++) {
        rA[i] = *(const float4*)(A + (size_t)(m0 + larow[i]) * lda + lacol[i]);
        rB[i] = *(const float4*)(B + (size_t)lbkr[i] * ldb + n0 + lbng[i]);
    }
#pragma unroll
    for (int i = 0; i < 4; i++) {
        a_store4(As, abase[i], rA[i]);
        Bs[bbase[i]]      = __uint_as_float(f2tf(rB[i].x));
        Bs[bbase[i] + 8]  = __uint_as_float(f2tf(rB[i].y));
        Bs[bbase[i] + 16] = __uint_as_float(f2tf(rB[i].z));
        Bs[bbase[i] + 24] = __uint_as_float(f2tf(rB[i].w));
    }
    __syncthreads();

    int lane = tid & 31, wid = tid >> 5;
    int wmblk = (wid & 3) * 2, wnblk = (wid >> 2) * 4;
    int g = lane >> 2, cc = lane & 3;
    int fragoff = g * 4 + cc;

    float acc[2][4][4];
#pragma unroll
    for (int mi = 0; mi < 2; mi++)
#pragma unroll
        for (int ni = 0; ni < 4; ni++)
#pragma unroll
            for (int j = 0; j < 4; j++) acc[mi][ni][j] = 0.f;

    uint4 afb[2][2];
    uint2 bfb[2][4];
    int nt = Keff >> 6;
    for (int it = 0; it < nt; it++) {
        int buf = it & 1;
        const float* Ab = As + buf * ATILE64;
        const float* Bb = Bs + buf * ATILE64;
        load_frags(Ab, Bb, 0, wmblk, wnblk, fragoff, afb[0], bfb[0]);
        bool has_next = (it + 1) < nt;
        if (has_next) {
            int kt = (it + 1) << 6;
#pragma unroll
            for (int i = 0; i < 4; i++) {
                rA[i] = *(const float4*)(A + (size_t)(m0 + larow[i]) * lda + kt + lacol[i]);
                rB[i] = *(const float4*)(B + (size_t)(kt + lbkr[i]) * ldb + n0 + lbng[i]);
            }
        }
#pragma unroll
        for (int s = 0; s < 8; s++) {
            int cur = s & 1;
            if (s < 7)
                load_frags(Ab, Bb, s + 1, wmblk, wnblk, fragoff, afb[cur ^ 1], bfb[cur ^ 1]);
#pragma unroll
            for (int mi = 0; mi < 2; mi++)
#pragma unroll
                for (int ni = 0; ni < 4; ni++)
                    mma_tf32(acc[mi][ni], afb[cur][mi], bfb[cur][ni]);
        }
        if (has_next) {
            float* an = As + (buf ^ 1) * ATILE64;
            float* bn = Bs + (buf ^ 1) * ATILE64;
#pragma unroll
            for (int i = 0; i < 4; i++) {
                a_store4(an, abase[i], rA[i]);
                bn[bbase[i]]      = __uint_as_float(f2tf(rB[i].x));
                bn[bbase[i] + 8]  = __uint_as_float(f2tf(rB[i].y));
                bn[bbase[i] + 16] = __uint_as_float(f2tf(rB[i].z));
                bn[bbase[i] + 24] = __uint_as_float(f2tf(rB[i].w));
            }
            __syncthreads();
        }
    }

#pragma unroll
    for (int mi = 0; mi < 2; mi++) {
        int r = m0 + (wid & 3) * 32 + mi * 16 + g;
        float s0 = rscale ? rscale[r] : 1.f;
        float s1 = rscale ? rscale[r + 8] : 1.f;
#pragma unroll
        for (int ni = 0; ni < 4; ni++) {
            int col = n0 + (wid >> 2) * 32 + ni * 8 + cc * 2;
            *(float2*)(C + (size_t)r * ldc + col) =
                make_float2(acc[mi][ni][0] * s0, acc[mi][ni][1] * s0);
            *(float2*)(C + (size_t)(r + 8) * ldc + col) =
                make_float2(acc[mi][ni][2] * s1, acc[mi][ni][3] * s1);
        }
    }
}

// ---------------- rope table (double precision) ----------------
__global__ void rope_table(float* __restrict__ ctab, float* __restrict__ stab) {
    int t = blockIdx.x, i = threadIdx.x;
    double invf = pow(10000.0, -2.0 * (double)i / (double)HD);
    double ang = (double)t * invf;
    ctab[t * (HD / 2) + i] = (float)cos(ang);
    stab[t * (HD / 2) + i] = (float)sin(ang);
}

// ---------------- rmsnorm (float4) ----------------
__global__ void rmsnorm_kernel(const float* __restrict__ x, const float* __restrict__ w,
                               float* __restrict__ out, int ncols) {
    int row = blockIdx.x;
    const float4* xr = (const float4*)(x + (size_t)row * ncols);
    int n4 = ncols >> 2;
    float ss = 0.f;
    for (int i = threadIdx.x; i < n4; i += blockDim.x) {
        float4 v = xr[i];
        ss += v.x * v.x + v.y * v.y + v.z * v.z + v.w * v.w;
    }
    float tot = blk_sum(ss);
    float inv = rsqrtf(tot / (float)ncols + EPS);
    float4* orow = (float4*)(out + (size_t)row * ncols);
    const float4* w4 = (const float4*)w;
    for (int i = threadIdx.x; i < n4; i += blockDim.x) {
        float4 v = xr[i], ww = w4[i];
        orow[i] = make_float4(v.x * inv * ww.x, v.y * inv * ww.y,
                              v.z * inv * ww.z, v.w * inv * ww.w);
    }
}

// ---------------- q/k rmsnorm + rope: warp-per-row ----------------
__global__ void __launch_bounds__(512) qk_norm_rope(
    float* __restrict__ qkv,
    const float* __restrict__ qw, const float* __restrict__ kw,
    const float* __restrict__ ctab, const float* __restrict__ stab)
{
    int t = blockIdx.x;
    int wid = threadIdx.x >> 5, lane = threadIdx.x & 31;
#pragma unroll
    for (int r = wid; r < 2 * NH; r += 16) {
        int which = r >> 4, h = r & (NH - 1);
        float* base = qkv + (size_t)t * (3 * H) + (size_t)which * H + (size_t)h * HD;
        float4 v = *(float4*)(base + lane * 4);
        float ss = v.x * v.x + v.y * v.y + v.z * v.z + v.w * v.w;
#pragma unroll
        for (int o = 16; o; o >>= 1) ss += __shfl_xor_sync(0xffffffffu, ss, o);
        float inv = rsqrtf(ss / (float)HD + EPS);
        const float* w = which ? kw : qw;
        float4 wv = *(const float4*)(w + lane * 4);
        float n0 = v.x * inv * wv.x, n1 = v.y * inv * wv.y;
        float n2 = v.z * inv * wv.z, n3 = v.w * inv * wv.w;
        int i0 = lane * 2, i1 = lane * 2 + 1;
        float c0 = ctab[t * (HD / 2) + i0], s0 = stab[t * (HD / 2) + i0];
        float c1 = ctab[t * (HD / 2) + i1], s1 = stab[t * (HD / 2) + i1];
        float4 o;
        o.x = n0 * c0 - n1 * s0;
        o.y = n0 * s0 + n1 * c0;
        o.z = n2 * c1 - n3 * s1;
        o.w = n2 * s1 + n3 * c1;
        *(float4*)(base + lane * 4) = o;
    }
}

// ---------------- causal softmax: single gmem read, unnorm exp + 1/sum --------------
__global__ void softmax_causal(float* __restrict__ S, float* __restrict__ rsum) {
    extern __shared__ float rowbuf[];   // up to 2048 floats
    int t = blockIdx.x, h = blockIdx.y;
    float* row = S + ((size_t)h * T + t) * T;
    int n = t + 1;
    int fill_end = min(T, ((t >> 7) + 1) << 7);
    const float scale = 0.08838834764831845f;
    float mx = -3.4e38f;
    for (int j = threadIdx.x; j < n; j += blockDim.x) {
        float v = row[j] * scale;
        rowbuf[j] = v;
        mx = fmaxf(mx, v);
    }
    mx = blk_max(mx);
    float sum = 0.f;
    for (int j = threadIdx.x; j < n; j += blockDim.x) {
        float e = expf(rowbuf[j] - mx);
        row[j] = e;
        sum += e;
    }
    sum = blk_sum(sum);
    if (threadIdx.x == 0) rsum[(size_t)h * T + t] = 1.f / sum;
    for (int j = n + (int)threadIdx.x; j < fill_end; j += blockDim.x) row[j] = 0.f;
}

// ---------------- elementwise ----------------
__global__ void silu_mul(const float* __restrict__ gu, float* __restrict__ act) {
    int idx = blockIdx.x * blockDim.x + threadIdx.x;
    if (idx >= T * II) return;
    int t = idx / II, i = idx % II;
    float g = gu[(size_t)t * I2 + i];
    float u = gu[(size_t)t * I2 + II + i];
    act[(size_t)t * II + i] = (g / (1.f + expf(-g))) * u;
}

// ---------------- routing ----------------
#define GL_TOK 8
__global__ void __launch_bounds__(512) gate_logits(
    const float* __restrict__ h2, const float* __restrict__ gw,
    float* __restrict__ logits)
{
    extern __shared__ float xs[];   // GL_TOK * H floats = 64 KB
    int t0 = blockIdx.x * GL_TOK;
    for (int i = threadIdx.x; i < GL_TOK * H / 4; i += blockDim.x) {
        int tok = i / (H / 4), c4 = i % (H / 4);
        ((float4*)xs)[i] = *(const float4*)(h2 + (size_t)(t0 + tok) * H + c4 * 4);
    }
    __syncthreads();
    int e = threadIdx.x >> 5, lane = threadIdx.x & 31;  // 16 warps = 16 experts
    const float* w = gw + (size_t)e * H;
    float s[GL_TOK];
#pragma unroll
    for (int k = 0; k < GL_TOK; k++) s[k] = 0.f;
    for (int k4 = lane; k4 < H / 4; k4 += 32) {
        float4 wv = *(const float4*)(w + k4 * 4);
#pragma unroll
        for (int tok = 0; tok < GL_TOK; tok++) {
            const float* xrow = xs + tok * H + k4 * 4;
            s[tok] += wv.x * xrow[0] + wv.y * xrow[1] + wv.z * xrow[2] + wv.w * xrow[3];
        }
    }
#pragma unroll
    for (int tok = 0; tok < GL_TOK; tok++) {
        float v = s[tok];
#pragma unroll
        for (int o = 16; o; o >>= 1) v += __shfl_xor_sync(0xffffffffu, v, o);
        if (lane == 0) logits[(size_t)(t0 + tok) * NE + e] = v;
    }
}

__global__ void route_and_build(const float* __restrict__ logits, float* __restrict__ topw,
                                int* __restrict__ counts, int* __restrict__ rows) {
    int t = blockIdx.x * blockDim.x + threadIdx.x;
    if (t >= T) return;
    float mx = -3.4e38f;
    int mi = 0;
#pragma unroll
    for (int e = 0; e < NE; e++) {
        float l = logits[(size_t)t * NE + e];
        if (l > mx) { mx = l; mi = e; }
    }
    float s = 0.f;
#pragma unroll
    for (int e = 0; e < NE; e++) s += expf(logits[(size_t)t * NE + e] - mx);
    topw[t] = 1.f / s;
    int p = atomicAdd(&counts[mi], 1);
    rows[(size_t)mi * T + p] = t;
}

__global__ void zero_counts(int* c) {
    if (threadIdx.x < NE) c[threadIdx.x] = 0;
}

// ---------------- host ----------------
#define SYM(p, s) do { void* _v; cudaGetSymbolAddress(&_v, s); p = (decltype(p))_v; } while (0)

extern "C" void kernel_launch(void* const* d_in, const int* in_sizes, int n_in,
                              void* d_out, int out_size) {
    const float* x      = (const float*)d_in[0];
    const float* ln1    = (const float*)d_in[1];
    const float* qkv_w  = (const float*)d_in[2];
    const float* qlnw   = (const float*)d_in[3];
    const float* klnw   = (const float*)d_in[4];
    const float* o_w    = (const float*)d_in[5];
    const float* ln2    = (const float*)d_in[6];
    const float* gate_w = (const float*)d_in[7];
    const float* egu    = (const float*)d_in[8];
    const float* edown  = (const float*)d_in[9];
    const float* sguw   = (const float*)d_in[10];
    const float* sdw    = (const float*)d_in[11];
    float* out = (float*)d_out;

    float *h, *qkv, *S, *rsum, *attn, *x2, *h2, *logits, *topw, *gu, *act, *moe, *sgu, *sact;
    float *ctab, *stab;
    int *counts, *rows;
    SYM(h, g_h); SYM(qkv, g_qkv); SYM(S, g_S); SYM(rsum, g_rsum); SYM(attn, g_attn);
    SYM(x2, g_x2); SYM(h2, g_h2); SYM(logits, g_logits); SYM(topw, g_topw);
    SYM(gu, g_gu); SYM(act, g_act); SYM(moe, g_moe); SYM(sgu, g_sgu); SYM(sact, g_sact);
    SYM(counts, g_counts); SYM(rows, g_rows);
    SYM(ctab, g_cos); SYM(stab, g_sin);

    cudaFuncSetAttribute(mma_nt, cudaFuncAttributeMaxDynamicSharedMemorySize, GSMEM);
    cudaFuncSetAttribute(mma_nn, cudaFuncAttributeMaxDynamicSharedMemorySize, GSMEM);
    cudaFuncSetAttribute(gate_logits, cudaFuncAttributeMaxDynamicSharedMemorySize, GL_TOK * H * 4);
    cudaFuncSetAttribute(softmax_causal, cudaFuncAttributeMaxDynamicSharedMemorySize, T * 4);

    rope_table<<<T, HD / 2>>>(ctab, stab);
    rmsnorm_kernel<<<T, 256>>>(x, ln1, h, H);
    mma_nt<<<dim3(3 * H / TBN, T / TBM, 1), 512, GSMEM>>>(h, H, 0, qkv_w, H, 0, qkv, 3 * H, 0,
                                                          T, 3 * H, H, 0, 0, 0, 0, 0, 0);
    qk_norm_rope<<<T, 512>>>(qkv, qlnw, klnw, ctab, stab);
    mma_nt<<<dim3(T / TBN, T / TBM, NH), 512, GSMEM>>>(qkv, 3 * H, HD, qkv + H, 3 * H, HD,
                                                       S, T, (long long)T * T, T, T, HD,
                                                       0, 0, 1, 0, 0, 0);
    softmax_causal<<<dim3(T, NH), 256, T * 4>>>(S, rsum);
    mma_nn<<<dim3(HD / 128, T / 128, NH), 512, GSMEM>>>(S, T, (long long)T * T, qkv + 2 * H, 3 * H, HD,
                                                        attn, H, HD, T, HD, T, 1, rsum);
    mma_nt<<<dim3(H / TBN, T / TBM, 1), 512, GSMEM>>>(attn, H, 0, o_w, H, 0, x2, H, 0,
                                                      T, H, H, 0, 0, 0, x, 0, 0);
    rmsnorm_kernel<<<T, 256>>>(x2, ln2, h2, H);
    gate_logits<<<T / GL_TOK, 512, GL_TOK * H * 4>>>(h2, gate_w, logits);
    zero_counts<<<1, 32>>>(counts);
    route_and_build<<<(T + 255) / 256, 256>>>(logits, topw, counts, rows);
    mma_nt<<<dim3(I2 / TBN, T / TBM, NE), 512, GSMEM>>>(h2, H, 0, egu, H, (long long)I2 * H,
                                                        gu, I2, 0, T, I2, H, rows, counts, 0, 0, 0, 0);
    silu_mul<<<(T * II + 255) / 256, 256>>>(gu, act);
    mma_nt<<<dim3(H / TBN, T / TBM, NE), 512, GSMEM>>>(act, II, 0, edown, II, (long long)H * II,
                                                       moe, H, 0, T, H, II, rows, counts, 0, 0, 0, 0);
    mma_nt<<<dim3(I2 / TBN, T / TBM, 1), 512, GSMEM>>>(h2, H, 0, sguw, H, 0, sgu, I2, 0,
                                                       T, I2, H, 0, 0, 0, 0, 0, 0);
    silu_mul<<<(T * II + 255) / 256, 256>>>(sgu, sact);
    mma_nt<<<dim3(H / TBN, T / TBM, 1), 512, GSMEM>>>(sact, II, 0, sdw, II, 0, out, H, 0,
                                                      T, H, II, 0, 0, 0, x2, moe, topw);
}

// round 13
// speedup vs baseline: 1.8048x; 1.5120x over previous
#include <cuda_runtime.h>
#include <cuda_fp16.h>
#include <math.h>
#include <stdint.h>

#define T  2048
#define H  2048
#define NH 16
#define HD 128
#define NE 16
#define II 2048
#define I2 4096
#define EPS 1e-6f

#define TBM 128
#define TBN 128
#define TBK 64
// fp16 frag-permuted layout (word = 4 bytes = half2):
// A: 8 mblk x 4 kblk groups, group = 33 uint4 (skewed); strides in words
#define A_KSTR 132            // 33 uint4
#define A_MSTR 528            // 4 * 132
#define B_KSTR 66             // 33 uint2
#define B_NSTR 264            // 4 * 66
#define STG 4224              // words per matrix per stage (8*528 = 16*264)
#define GSMEM (4 * STG * 4)   // 2 stages * (A+B) = 67584 bytes

// ---------------- scratch ----------------
__device__ float g_h[(size_t)T * H];
__device__ float g_qkv[(size_t)T * 3 * H];
__device__ float g_S[(size_t)NH * T * T];
__device__ float g_rsum[(size_t)NH * T];
__device__ float g_attn[(size_t)T * H];
__device__ float g_x2[(size_t)T * H];
__device__ float g_h2[(size_t)T * H];
__device__ float g_logits[(size_t)T * NE];
__device__ float g_topw[T];
__device__ int   g_counts[NE];
__device__ int   g_rows[(size_t)NE * T];
__device__ float g_gu[(size_t)T * I2];
__device__ float g_act[(size_t)T * II];
__device__ float g_moe[(size_t)T * H];
__device__ float g_sgu[(size_t)T * I2];
__device__ float g_sact[(size_t)T * II];
__device__ float g_cos[(size_t)T * (HD / 2)];
__device__ float g_sin[(size_t)T * (HD / 2)];

// ---------------- helpers ----------------
__device__ __forceinline__ uint32_t f2h2(float x, float y) {
    __half2 h = __float22half2_rn(make_float2(x, y));
    return *(uint32_t*)&h;
}

__device__ __forceinline__ void mma_f16(float c[4], uint4 a, uint2 b) {
    asm volatile("mma.sync.aligned.m16n8k16.row.col.f32.f16.f16.f32 "
                 "{%0,%1,%2,%3}, {%4,%5,%6,%7}, {%8,%9}, {%0,%1,%2,%3};"
                 : "+f"(c[0]), "+f"(c[1]), "+f"(c[2]), "+f"(c[3])
                 : "r"(a.x), "r"(a.y), "r"(a.z), "r"(a.w), "r"(b.x), "r"(b.y));
}

__device__ __forceinline__ float blk_sum(float v) {
    __shared__ float sh[33];
    __syncthreads();
    int lane = threadIdx.x & 31, w = threadIdx.x >> 5;
#pragma unroll
    for (int o = 16; o; o >>= 1) v += __shfl_xor_sync(0xffffffffu, v, o);
    if (lane == 0) sh[w] = v;
    __syncthreads();
    if (threadIdx.x < 32) {
        int nw = (blockDim.x + 31) >> 5;
        float r = (threadIdx.x < nw) ? sh[threadIdx.x] : 0.f;
#pragma unroll
        for (int o = 16; o; o >>= 1) r += __shfl_xor_sync(0xffffffffu, r, o);
        if (threadIdx.x == 0) sh[32] = r;
    }
    __syncthreads();
    return sh[32];
}

__device__ __forceinline__ float blk_max(float v) {
    __shared__ float sh[33];
    __syncthreads();
    int lane = threadIdx.x & 31, w = threadIdx.x >> 5;
#pragma unroll
    for (int o = 16; o; o >>= 1) v = fmaxf(v, __shfl_xor_sync(0xffffffffu, v, o));
    if (lane == 0) sh[w] = v;
    __syncthreads();
    if (threadIdx.x < 32) {
        int nw = (blockDim.x + 31) >> 5;
        float r = (threadIdx.x < nw) ? sh[threadIdx.x] : -3.4e38f;
#pragma unroll
        for (int o = 16; o; o >>= 1) r = fmaxf(r, __shfl_xor_sync(0xffffffffu, r, o));
        if (threadIdx.x == 0) sh[32] = r;
    }
    __syncthreads();
    return sh[32];
}

// word offset of the half2 holding (r, k0|k0+1); the (k0+2,k0+3) pair is at +4
__device__ __forceinline__ int a_w_base(int r, int k0) {
    int mblk = r >> 4, rr = r & 15, g = rr & 7, rhalf = rr >> 3;
    int kblk = k0 >> 4, kk = k0 & 15, khigh = kk >> 3, cc = (kk & 7) >> 1;
    return mblk * A_MSTR + kblk * A_KSTR + (g * 4 + cc) * 4 + khigh * 2 + rhalf;
}
// word offset for B row n, (k0|k0+1); (k0+2,k0+3) pair at +2
__device__ __forceinline__ int b_w_base(int n, int k0) {
    int nblk = n >> 3, g = n & 7;
    int kblk = k0 >> 4, kk = k0 & 15, khigh = kk >> 3, cc = (kk & 7) >> 1;
    return nblk * B_NSTR + kblk * B_KSTR + (g * 4 + cc) * 2 + khigh;
}
__device__ __forceinline__ void a_store(uint32_t* Aw, int base, float4 v) {
    Aw[base]     = f2h2(v.x, v.y);
    Aw[base + 4] = f2h2(v.z, v.w);
}
__device__ __forceinline__ void b_store(uint32_t* Bw, int base, float4 v) {
    Bw[base]     = f2h2(v.x, v.y);
    Bw[base + 2] = f2h2(v.z, v.w);
}

__device__ __forceinline__ void load_frags(const uint32_t* Aw, const uint32_t* Bw, int kblk,
                                           int wmblk, int wnblk, int lane,
                                           uint4 af[2], uint2 bf[4]) {
#pragma unroll
    for (int mi = 0; mi < 2; mi++)
        af[mi] = *(const uint4*)(Aw + (wmblk + mi) * A_MSTR + kblk * A_KSTR + lane * 4);
#pragma unroll
    for (int ni = 0; ni < 4; ni++)
        bf[ni] = *(const uint2*)(Bw + (wnblk + ni) * B_NSTR + kblk * B_KSTR + lane * 2);
}

// ---------------- fp16 GEMM NT (512 thr), TBK=64, frag double-buffered --------------
__global__ void __launch_bounds__(512) mma_nt(
    const float* __restrict__ A, int lda, long long sA,
    const float* __restrict__ B, int ldb, long long sB,
    float* __restrict__ C, int ldc, long long sC,
    int M, int N, int K,
    const int* __restrict__ rowsAll, const int* __restrict__ cntAll,
    int causal,
    const float* __restrict__ addA,
    const float* __restrict__ addS, const float* __restrict__ scaleVec)
{
    extern __shared__ uint32_t smw[];
    uint32_t* As = smw;                 // 2 stages * STG
    uint32_t* Bs = smw + 2 * STG;
    __shared__ int rid[TBM];

    int z = blockIdx.z;
    A += (size_t)z * sA; B += (size_t)z * sB; C += (size_t)z * sC;
    const int* rows = rowsAll ? rowsAll + (size_t)z * M : 0;
    int Mv = cntAll ? cntAll[z] : M;
    int m0 = blockIdx.y * TBM;
    if (m0 >= Mv) return;
    int n0 = blockIdx.x * TBN;
    if (causal && n0 > m0) return;

    int tid = threadIdx.x;
    if (tid < TBM) {
        int gm = m0 + tid;
        rid[tid] = rows ? (gm < Mv ? rows[gm] : -1) : gm;
    }
    __syncthreads();

    int lrow[4], lcol[4], ra[4], abase[4], bbase[4];
#pragma unroll
    for (int i = 0; i < 4; i++) {
        int idx = tid + i * 512;
        lrow[i] = idx >> 4;
        lcol[i] = (idx & 15) * 4;
        ra[i] = rid[lrow[i]];
        abase[i] = a_w_base(lrow[i], lcol[i]);
        bbase[i] = b_w_base(lrow[i], lcol[i]);
    }

    float4 rA[4], rB[4];
    const float4 z4 = make_float4(0.f, 0.f, 0.f, 0.f);
#pragma unroll
    for (int i = 0; i < 4; i++) {
        rA[i] = (ra[i] >= 0) ? *(const float4*)(A + (size_t)ra[i] * lda + lcol[i]) : z4;
        rB[i] = *(const float4*)(B + (size_t)(n0 + lrow[i]) * ldb + lcol[i]);
    }
#pragma unroll
    for (int i = 0; i < 4; i++) {
        a_store(As, abase[i], rA[i]);
        b_store(Bs, bbase[i], rB[i]);
    }
    __syncthreads();

    int lane = tid & 31, wid = tid >> 5;
    int wmblk = (wid & 3) * 2;
    int wnblk = (wid >> 2) * 4;
    int g = lane >> 2, cc = lane & 3;

    float acc[2][4][4];
#pragma unroll
    for (int mi = 0; mi < 2; mi++)
#pragma unroll
        for (int ni = 0; ni < 4; ni++)
#pragma unroll
            for (int j = 0; j < 4; j++) acc[mi][ni][j] = 0.f;

    uint4 afb[2][2];
    uint2 bfb[2][4];
    int nt = K >> 6;
    for (int it = 0; it < nt; it++) {
        int buf = it & 1;
        const uint32_t* Aw = As + buf * STG;
        const uint32_t* Bw = Bs + buf * STG;
        load_frags(Aw, Bw, 0, wmblk, wnblk, lane, afb[0], bfb[0]);
        bool has_next = (it + 1) < nt;
        if (has_next) {
            int kt = (it + 1) << 6;
#pragma unroll
            for (int i = 0; i < 4; i++) {
                rA[i] = (ra[i] >= 0) ? *(const float4*)(A + (size_t)ra[i] * lda + kt + lcol[i]) : z4;
                rB[i] = *(const float4*)(B + (size_t)(n0 + lrow[i]) * ldb + kt + lcol[i]);
            }
        }
#pragma unroll
        for (int s = 0; s < 4; s++) {
            int cur = s & 1;
            if (s < 3)
                load_frags(Aw, Bw, s + 1, wmblk, wnblk, lane, afb[cur ^ 1], bfb[cur ^ 1]);
#pragma unroll
            for (int mi = 0; mi < 2; mi++)
#pragma unroll
                for (int ni = 0; ni < 4; ni++)
                    mma_f16(acc[mi][ni], afb[cur][mi], bfb[cur][ni]);
        }
        if (has_next) {
            uint32_t* an = As + (buf ^ 1) * STG;
            uint32_t* bn = Bs + (buf ^ 1) * STG;
#pragma unroll
            for (int i = 0; i < 4; i++) {
                a_store(an, abase[i], rA[i]);
                b_store(bn, bbase[i], rB[i]);
            }
            __syncthreads();
        }
    }

#pragma unroll
    for (int mi = 0; mi < 2; mi++) {
        int r0 = (wid & 3) * 32 + mi * 16 + g;
        int rr[2] = { rid[r0], rid[r0 + 8] };
#pragma unroll
        for (int half = 0; half < 2; half++) {
            int r = rr[half];
            if (r < 0) continue;
#pragma unroll
            for (int ni = 0; ni < 4; ni++) {
                int col = n0 + (wid >> 2) * 32 + ni * 8 + cc * 2;
                float2 v = make_float2(acc[mi][ni][half * 2], acc[mi][ni][half * 2 + 1]);
                if (addA) {
                    float2 a = *(const float2*)(addA + (size_t)r * ldc + col);
                    v.x += a.x; v.y += a.y;
                }
                if (addS) {
                    float w = scaleVec[r];
                    float2 s = *(const float2*)(addS + (size_t)r * ldc + col);
                    v.x += s.x * w; v.y += s.y * w;
                }
                *(float2*)(C + (size_t)r * ldc + col) = v;
            }
        }
    }
}

// ---------------- fp16 GEMM NN (512 thr), TBK=64, row-scaled epilogue ---------------
__global__ void __launch_bounds__(512) mma_nn(
    const float* __restrict__ A, int lda, long long sA,
    const float* __restrict__ B, int ldb, long long sB,
    float* __restrict__ C, int ldc, long long sC,
    int M, int N, int K, int kcap,
    const float* __restrict__ rscaleAll)
{
    extern __shared__ uint32_t smw[];
    uint32_t* As = smw;
    uint32_t* Bs = smw + 2 * STG;

    int z = blockIdx.z;
    A += (size_t)z * sA; B += (size_t)z * sB; C += (size_t)z * sC;
    const float* rscale = rscaleAll ? rscaleAll + (size_t)z * M : 0;
    int m0 = blockIdx.y * 128;
    int n0 = blockIdx.x * 128;
    int Keff = kcap ? min(K, m0 + 128) : K;

    int tid = threadIdx.x;
    int larow[4], lacol[4], abase[4];
    int lbkr[4], lbng[4];
    int bhalf[4][4];   // half-granular addresses for the 4 transposed stores
#pragma unroll
    for (int i = 0; i < 4; i++) {
        int idx = tid + i * 512;
        larow[i] = idx >> 4;
        lacol[i] = (idx & 15) * 4;
        abase[i] = a_w_base(larow[i], lacol[i]);
        lbkr[i] = idx >> 5;          // k row 0..63
        lbng[i] = (idx & 31) * 4;    // n col 0..124
        int k = lbkr[i], kk = k & 15;
        int kblk = k >> 4, khigh = kk >> 3, ccB = (kk & 7) >> 1, pos = kk & 1;
#pragma unroll
        for (int jj = 0; jj < 4; jj++) {
            int n = lbng[i] + jj;
            int nblk = n >> 3, gB = n & 7;
            int word = nblk * B_NSTR + kblk * B_KSTR + (gB * 4 + ccB) * 2 + khigh;
            bhalf[i][jj] = word * 2 + pos;
        }
    }

    float4 rA[4], rB[4];
#pragma unroll
    for (int i = 0; i < 4; i++) {
        rA[i] = *(const float4*)(A + (size_t)(m0 + larow[i]) * lda + lacol[i]);
        rB[i] = *(const float4*)(B + (size_t)lbkr[i] * ldb + n0 + lbng[i]);
    }
    {
        __half* Bh = (__half*)Bs;
#pragma unroll
        for (int i = 0; i < 4; i++) {
            a_store(As, abase[i], rA[i]);
            Bh[bhalf[i][0]] = __float2half_rn(rB[i].x);
            Bh[bhalf[i][1]] = __float2half_rn(rB[i].y);
            Bh[bhalf[i][2]] = __float2half_rn(rB[i].z);
            Bh[bhalf[i][3]] = __float2half_rn(rB[i].w);
        }
    }
    __syncthreads();

    int lane = tid & 31, wid = tid >> 5;
    int wmblk = (wid & 3) * 2, wnblk = (wid >> 2) * 4;
    int g = lane >> 2, cc = lane & 3;

    float acc[2][4][4];
#pragma unroll
    for (int mi = 0; mi < 2; mi++)
#pragma unroll
        for (int ni = 0; ni < 4; ni++)
#pragma unroll
            for (int j = 0; j < 4; j++) acc[mi][ni][j] = 0.f;

    uint4 afb[2][2];
    uint2 bfb[2][4];
    int nt = Keff >> 6;
    for (int it = 0; it < nt; it++) {
        int buf = it & 1;
        const uint32_t* Aw = As + buf * STG;
        const uint32_t* Bw = Bs + buf * STG;
        load_frags(Aw, Bw, 0, wmblk, wnblk, lane, afb[0], bfb[0]);
        bool has_next = (it + 1) < nt;
        if (has_next) {
            int kt = (it + 1) << 6;
#pragma unroll
            for (int i = 0; i < 4; i++) {
                rA[i] = *(const float4*)(A + (size_t)(m0 + larow[i]) * lda + kt + lacol[i]);
                rB[i] = *(const float4*)(B + (size_t)(kt + lbkr[i]) * ldb + n0 + lbng[i]);
            }
        }
#pragma unroll
        for (int s = 0; s < 4; s++) {
            int cur = s & 1;
            if (s < 3)
                load_frags(Aw, Bw, s + 1, wmblk, wnblk, lane, afb[cur ^ 1], bfb[cur ^ 1]);
#pragma unroll
            for (int mi = 0; mi < 2; mi++)
#pragma unroll
                for (int ni = 0; ni < 4; ni++)
                    mma_f16(acc[mi][ni], afb[cur][mi], bfb[cur][ni]);
        }
        if (has_next) {
            uint32_t* an = As + (buf ^ 1) * STG;
            __half* bn = (__half*)(Bs + (buf ^ 1) * STG);
#pragma unroll
            for (int i = 0; i < 4; i++) {
                a_store(an, abase[i], rA[i]);
                bn[bhalf[i][0]] = __float2half_rn(rB[i].x);
                bn[bhalf[i][1]] = __float2half_rn(rB[i].y);
                bn[bhalf[i][2]] = __float2half_rn(rB[i].z);
                bn[bhalf[i][3]] = __float2half_rn(rB[i].w);
            }
            __syncthreads();
        }
    }

#pragma unroll
    for (int mi = 0; mi < 2; mi++) {
        int r = m0 + (wid & 3) * 32 + mi * 16 + g;
        float s0 = rscale ? rscale[r] : 1.f;
        float s1 = rscale ? rscale[r + 8] : 1.f;
#pragma unroll
        for (int ni = 0; ni < 4; ni++) {
            int col = n0 + (wid >> 2) * 32 + ni * 8 + cc * 2;
            *(float2*)(C + (size_t)r * ldc + col) =
                make_float2(acc[mi][ni][0] * s0, acc[mi][ni][1] * s0);
            *(float2*)(C + (size_t)(r + 8) * ldc + col) =
                make_float2(acc[mi][ni][2] * s1, acc[mi][ni][3] * s1);
        }
    }
}

// ---------------- rope table (double precision) ----------------
__global__ void rope_table(float* __restrict__ ctab, float* __restrict__ stab) {
    int t = blockIdx.x, i = threadIdx.x;
    double invf = pow(10000.0, -2.0 * (double)i / (double)HD);
    double ang = (double)t * invf;
    ctab[t * (HD / 2) + i] = (float)cos(ang);
    stab[t * (HD / 2) + i] = (float)sin(ang);
}

// ---------------- rmsnorm (float4) ----------------
__global__ void rmsnorm_kernel(const float* __restrict__ x, const float* __restrict__ w,
                               float* __restrict__ out, int ncols) {
    int row = blockIdx.x;
    const float4* xr = (const float4*)(x + (size_t)row * ncols);
    int n4 = ncols >> 2;
    float ss = 0.f;
    for (int i = threadIdx.x; i < n4; i += blockDim.x) {
        float4 v = xr[i];
        ss += v.x * v.x + v.y * v.y + v.z * v.z + v.w * v.w;
    }
    float tot = blk_sum(ss);
    float inv = rsqrtf(tot / (float)ncols + EPS);
    float4* orow = (float4*)(out + (size_t)row * ncols);
    const float4* w4 = (const float4*)w;
    for (int i = threadIdx.x; i < n4; i += blockDim.x) {
        float4 v = xr[i], ww = w4[i];
        orow[i] = make_float4(v.x * inv * ww.x, v.y * inv * ww.y,
                              v.z * inv * ww.z, v.w * inv * ww.w);
    }
}

// ---------------- q/k rmsnorm + rope: warp-per-row ----------------
__global__ void __launch_bounds__(512) qk_norm_rope(
    float* __restrict__ qkv,
    const float* __restrict__ qw, const float* __restrict__ kw,
    const float* __restrict__ ctab, const float* __restrict__ stab)
{
    int t = blockIdx.x;
    int wid = threadIdx.x >> 5, lane = threadIdx.x & 31;
#pragma unroll
    for (int r = wid; r < 2 * NH; r += 16) {
        int which = r >> 4, h = r & (NH - 1);
        float* base = qkv + (size_t)t * (3 * H) + (size_t)which * H + (size_t)h * HD;
        float4 v = *(float4*)(base + lane * 4);
        float ss = v.x * v.x + v.y * v.y + v.z * v.z + v.w * v.w;
#pragma unroll
        for (int o = 16; o; o >>= 1) ss += __shfl_xor_sync(0xffffffffu, ss, o);
        float inv = rsqrtf(ss / (float)HD + EPS);
        const float* w = which ? kw : qw;
        float4 wv = *(const float4*)(w + lane * 4);
        float n0 = v.x * inv * wv.x, n1 = v.y * inv * wv.y;
        float n2 = v.z * inv * wv.z, n3 = v.w * inv * wv.w;
        int i0 = lane * 2, i1 = lane * 2 + 1;
        float c0 = ctab[t * (HD / 2) + i0], s0 = stab[t * (HD / 2) + i0];
        float c1 = ctab[t * (HD / 2) + i1], s1 = stab[t * (HD / 2) + i1];
        float4 o;
        o.x = n0 * c0 - n1 * s0;
        o.y = n0 * s0 + n1 * c0;
        o.z = n2 * c1 - n3 * s1;
        o.w = n2 * s1 + n3 * c1;
        *(float4*)(base + lane * 4) = o;
    }
}

// ---------------- causal softmax: single gmem read, unnorm exp + 1/sum --------------
__global__ void softmax_causal(float* __restrict__ S, float* __restrict__ rsum) {
    extern __shared__ float rowbuf[];
    int t = blockIdx.x, h = blockIdx.y;
    float* row = S + ((size_t)h * T + t) * T;
    int n = t + 1;
    int fill_end = min(T, ((t >> 7) + 1) << 7);
    const float scale = 0.08838834764831845f;
    float mx = -3.4e38f;
    for (int j = threadIdx.x; j < n; j += blockDim.x) {
        float v = row[j] * scale;
        rowbuf[j] = v;
        mx = fmaxf(mx, v);
    }
    mx = blk_max(mx);
    float sum = 0.f;
    for (int j = threadIdx.x; j < n; j += blockDim.x) {
        float e = expf(rowbuf[j] - mx);
        row[j] = e;
        sum += e;
    }
    sum = blk_sum(sum);
    if (threadIdx.x == 0) rsum[(size_t)h * T + t] = 1.f / sum;
    for (int j = n + (int)threadIdx.x; j < fill_end; j += blockDim.x) row[j] = 0.f;
}

// ---------------- elementwise ----------------
__global__ void silu_mul(const float* __restrict__ gu, float* __restrict__ act) {
    int idx = blockIdx.x * blockDim.x + threadIdx.x;
    if (idx >= T * II) return;
    int t = idx / II, i = idx % II;
    float g = gu[(size_t)t * I2 + i];
    float u = gu[(size_t)t * I2 + II + i];
    act[(size_t)t * II + i] = (g / (1.f + expf(-g))) * u;
}

// ---------------- routing ----------------
#define GL_TOK 8
__global__ void __launch_bounds__(512) gate_logits(
    const float* __restrict__ h2, const float* __restrict__ gw,
    float* __restrict__ logits)
{
    extern __shared__ float xs[];
    int t0 = blockIdx.x * GL_TOK;
    for (int i = threadIdx.x; i < GL_TOK * H / 4; i += blockDim.x) {
        int tok = i / (H / 4), c4 = i % (H / 4);
        ((float4*)xs)[i] = *(const float4*)(h2 + (size_t)(t0 + tok) * H + c4 * 4);
    }
    __syncthreads();
    int e = threadIdx.x >> 5, lane = threadIdx.x & 31;
    const float* w = gw + (size_t)e * H;
    float s[GL_TOK];
#pragma unroll
    for (int k = 0; k < GL_TOK; k++) s[k] = 0.f;
    for (int k4 = lane; k4 < H / 4; k4 += 32) {
        float4 wv = *(const float4*)(w + k4 * 4);
#pragma unroll
        for (int tok = 0; tok < GL_TOK; tok++) {
            const float* xrow = xs + tok * H + k4 * 4;
            s[tok] += wv.x * xrow[0] + wv.y * xrow[1] + wv.z * xrow[2] + wv.w * xrow[3];
        }
    }
#pragma unroll
    for (int tok = 0; tok < GL_TOK; tok++) {
        float v = s[tok];
#pragma unroll
        for (int o = 16; o; o >>= 1) v += __shfl_xor_sync(0xffffffffu, v, o);
        if (lane == 0) logits[(size_t)(t0 + tok) * NE + e] = v;
    }
}

__global__ void route_and_build(const float* __restrict__ logits, float* __restrict__ topw,
                                int* __restrict__ counts, int* __restrict__ rows) {
    int t = blockIdx.x * blockDim.x + threadIdx.x;
    if (t >= T) return;
    float mx = -3.4e38f;
    int mi = 0;
#pragma unroll
    for (int e = 0; e < NE; e++) {
        float l = logits[(size_t)t * NE + e];
        if (l > mx) { mx = l; mi = e; }
    }
    float s = 0.f;
#pragma unroll
    for (int e = 0; e < NE; e++) s += expf(logits[(size_t)t * NE + e] - mx);
    topw[t] = 1.f / s;
    int p = atomicAdd(&counts[mi], 1);
    rows[(size_t)mi * T + p] = t;
}

__global__ void zero_counts(int* c) {
    if (threadIdx.x < NE) c[threadIdx.x] = 0;
}

// ---------------- host ----------------
#define SYM(p, s) do { void* _v; cudaGetSymbolAddress(&_v, s); p = (decltype(p))_v; } while (0)

extern "C" void kernel_launch(void* const* d_in, const int* in_sizes, int n_in,
                              void* d_out, int out_size) {
    const float* x      = (const float*)d_in[0];
    const float* ln1    = (const float*)d_in[1];
    const float* qkv_w  = (const float*)d_in[2];
    const float* qlnw   = (const float*)d_in[3];
    const float* klnw   = (const float*)d_in[4];
    const float* o_w    = (const float*)d_in[5];
    const float* ln2    = (const float*)d_in[6];
    const float* gate_w = (const float*)d_in[7];
    const float* egu    = (const float*)d_in[8];
    const float* edown  = (const float*)d_in[9];
    const float* sguw   = (const float*)d_in[10];
    const float* sdw    = (const float*)d_in[11];
    float* out = (float*)d_out;

    float *h, *qkv, *S, *rsum, *attn, *x2, *h2, *logits, *topw, *gu, *act, *moe, *sgu, *sact;
    float *ctab, *stab;
    int *counts, *rows;
    SYM(h, g_h); SYM(qkv, g_qkv); SYM(S, g_S); SYM(rsum, g_rsum); SYM(attn, g_attn);
    SYM(x2, g_x2); SYM(h2, g_h2); SYM(logits, g_logits); SYM(topw, g_topw);
    SYM(gu, g_gu); SYM(act, g_act); SYM(moe, g_moe); SYM(sgu, g_sgu); SYM(sact, g_sact);
    SYM(counts, g_counts); SYM(rows, g_rows);
    SYM(ctab, g_cos); SYM(stab, g_sin);

    cudaFuncSetAttribute(mma_nt, cudaFuncAttributeMaxDynamicSharedMemorySize, GSMEM);
    cudaFuncSetAttribute(mma_nn, cudaFuncAttributeMaxDynamicSharedMemorySize, GSMEM);
    cudaFuncSetAttribute(gate_logits, cudaFuncAttributeMaxDynamicSharedMemorySize, GL_TOK * H * 4);
    cudaFuncSetAttribute(softmax_causal, cudaFuncAttributeMaxDynamicSharedMemorySize, T * 4);

    rope_table<<<T, HD / 2>>>(ctab, stab);
    rmsnorm_kernel<<<T, 256>>>(x, ln1, h, H);
    mma_nt<<<dim3(3 * H / TBN, T / TBM, 1), 512, GSMEM>>>(h, H, 0, qkv_w, H, 0, qkv, 3 * H, 0,
                                                          T, 3 * H, H, 0, 0, 0, 0, 0, 0);
    qk_norm_rope<<<T, 512>>>(qkv, qlnw, klnw, ctab, stab);
    mma_nt<<<dim3(T / TBN, T / TBM, NH), 512, GSMEM>>>(qkv, 3 * H, HD, qkv + H, 3 * H, HD,
                                                       S, T, (long long)T * T, T, T, HD,
                                                       0, 0, 1, 0, 0, 0);
    softmax_causal<<<dim3(T, NH), 256, T * 4>>>(S, rsum);
    mma_nn<<<dim3(HD / 128, T / 128, NH), 512, GSMEM>>>(S, T, (long long)T * T, qkv + 2 * H, 3 * H, HD,
                                                        attn, H, HD, T, HD, T, 1, rsum);
    mma_nt<<<dim3(H / TBN, T / TBM, 1), 512, GSMEM>>>(attn, H, 0, o_w, H, 0, x2, H, 0,
                                                      T, H, H, 0, 0, 0, x, 0, 0);
    rmsnorm_kernel<<<T, 256>>>(x2, ln2, h2, H);
    gate_logits<<<T / GL_TOK, 512, GL_TOK * H * 4>>>(h2, gate_w, logits);
    zero_counts<<<1, 32>>>(counts);
    route_and_build<<<(T + 255) / 256, 256>>>(logits, topw, counts, rows);
    mma_nt<<<dim3(I2 / TBN, T / TBM, NE), 512, GSMEM>>>(h2, H, 0, egu, H, (long long)I2 * H,
                                                        gu, I2, 0, T, I2, H, rows, counts, 0, 0, 0, 0);
    silu_mul<<<(T * II + 255) / 256, 256>>>(gu, act);
    mma_nt<<<dim3(H / TBN, T / TBM, NE), 512, GSMEM>>>(act, II, 0, edown, II, (long long)H * II,
                                                       moe, H, 0, T, H, II, rows, counts, 0, 0, 0, 0);
    mma_nt<<<dim3(I2 / TBN, T / TBM, 1), 512, GSMEM>>>(h2, H, 0, sguw, H, 0, sgu, I2, 0,
                                                       T, I2, H, 0, 0, 0, 0, 0, 0);
    silu_mul<<<(T * II + 255) / 256, 256>>>(sgu, sact);
    mma_nt<<<dim3(H / TBN, T / TBM, 1), 512, GSMEM>>>(sact, II, 0, sdw, II, 0, out, H, 0,
                                                      T, H, II, 0, 0, 0, x2, moe, topw);
}

// round 14
// speedup vs baseline: 1.8237x; 1.0105x over previous
#include <cuda_runtime.h>
#include <cuda_fp16.h>
#include <math.h>
#include <stdint.h>

#define T  2048
#define H  2048
#define NH 16
#define HD 128
#define NE 16
#define II 2048
#define I2 4096
#define EPS 1e-6f

#define TBM 128
#define TBN 128
#define TBK 64
#define A_KSTR 132
#define A_MSTR 528
#define B_KSTR 66
#define B_NSTR 264
#define STG 4224
#define GSMEM (4 * STG * 4)

// ---------------- scratch ----------------
__device__ float  g_h[(size_t)T * H];
__device__ float  g_qkv[(size_t)T * 3 * H];
__device__ float  g_S[(size_t)NH * T * T];
__device__ __half g_Sh[(size_t)NH * T * T];
__device__ float  g_rsum[(size_t)NH * T];
__device__ float  g_attn[(size_t)T * H];
__device__ float  g_x2[(size_t)T * H];
__device__ float  g_h2[(size_t)T * H];
__device__ float  g_logits[(size_t)T * NE];
__device__ float  g_topw[T];
__device__ int    g_counts[NE];
__device__ int    g_rows[(size_t)NE * T];
__device__ float  g_gu[(size_t)T * I2];
__device__ __half g_act[(size_t)T * II];
__device__ float  g_moe[(size_t)T * H];
__device__ float  g_sgu[(size_t)T * I2];
__device__ __half g_sact[(size_t)T * II];
__device__ float  g_cos[(size_t)T * (HD / 2)];
__device__ float  g_sin[(size_t)T * (HD / 2)];

// ---------------- helpers ----------------
__device__ __forceinline__ uint32_t f2h2(float x, float y) {
    __half2 h = __float22half2_rn(make_float2(x, y));
    return *(uint32_t*)&h;
}

__device__ __forceinline__ void mma_f16(float c[4], uint4 a, uint2 b) {
    asm volatile("mma.sync.aligned.m16n8k16.row.col.f32.f16.f16.f32 "
                 "{%0,%1,%2,%3}, {%4,%5,%6,%7}, {%8,%9}, {%0,%1,%2,%3};"
                 : "+f"(c[0]), "+f"(c[1]), "+f"(c[2]), "+f"(c[3])
                 : "r"(a.x), "r"(a.y), "r"(a.z), "r"(a.w), "r"(b.x), "r"(b.y));
}

__device__ __forceinline__ float blk_sum(float v) {
    __shared__ float sh[33];
    __syncthreads();
    int lane = threadIdx.x & 31, w = threadIdx.x >> 5;
#pragma unroll
    for (int o = 16; o; o >>= 1) v += __shfl_xor_sync(0xffffffffu, v, o);
    if (lane == 0) sh[w] = v;
    __syncthreads();
    if (threadIdx.x < 32) {
        int nw = (blockDim.x + 31) >> 5;
        float r = (threadIdx.x < nw) ? sh[threadIdx.x] : 0.f;
#pragma unroll
        for (int o = 16; o; o >>= 1) r += __shfl_xor_sync(0xffffffffu, r, o);
        if (threadIdx.x == 0) sh[32] = r;
    }
    __syncthreads();
    return sh[32];
}

__device__ __forceinline__ float blk_max(float v) {
    __shared__ float sh[33];
    __syncthreads();
    int lane = threadIdx.x & 31, w = threadIdx.x >> 5;
#pragma unroll
    for (int o = 16; o; o >>= 1) v = fmaxf(v, __shfl_xor_sync(0xffffffffu, v, o));
    if (lane == 0) sh[w] = v;
    __syncthreads();
    if (threadIdx.x < 32) {
        int nw = (blockDim.x + 31) >> 5;
        float r = (threadIdx.x < nw) ? sh[threadIdx.x] : -3.4e38f;
#pragma unroll
        for (int o = 16; o; o >>= 1) r = fmaxf(r, __shfl_xor_sync(0xffffffffu, r, o));
        if (threadIdx.x == 0) sh[32] = r;
    }
    __syncthreads();
    return sh[32];
}

__device__ __forceinline__ int a_w_base(int r, int k0) {
    int mblk = r >> 4, rr = r & 15, g = rr & 7, rhalf = rr >> 3;
    int kblk = k0 >> 4, kk = k0 & 15, khigh = kk >> 3, cc = (kk & 7) >> 1;
    return mblk * A_MSTR + kblk * A_KSTR + (g * 4 + cc) * 4 + khigh * 2 + rhalf;
}
__device__ __forceinline__ int b_w_base(int n, int k0) {
    int nblk = n >> 3, g = n & 7;
    int kblk = k0 >> 4, kk = k0 & 15, khigh = kk >> 3, cc = (kk & 7) >> 1;
    return nblk * B_NSTR + kblk * B_KSTR + (g * 4 + cc) * 2 + khigh;
}
__device__ __forceinline__ void a_store(uint32_t* Aw, int base, float4 v) {
    Aw[base]     = f2h2(v.x, v.y);
    Aw[base + 4] = f2h2(v.z, v.w);
}
__device__ __forceinline__ void a_store_h(uint32_t* Aw, int base, uint2 w) {
    Aw[base]     = w.x;
    Aw[base + 4] = w.y;
}
__device__ __forceinline__ void b_store(uint32_t* Bw, int base, float4 v) {
    Bw[base]     = f2h2(v.x, v.y);
    Bw[base + 2] = f2h2(v.z, v.w);
}

__device__ __forceinline__ void load_frags(const uint32_t* Aw, const uint32_t* Bw, int kblk,
                                           int wmblk, int wnblk, int lane,
                                           uint4 af[2], uint2 bf[4]) {
#pragma unroll
    for (int mi = 0; mi < 2; mi++)
        af[mi] = *(const uint4*)(Aw + (wmblk + mi) * A_MSTR + kblk * A_KSTR + lane * 4);
#pragma unroll
    for (int ni = 0; ni < 4; ni++)
        bf[ni] = *(const uint2*)(Bw + (wnblk + ni) * B_NSTR + kblk * B_KSTR + lane * 2);
}

// ---------------- fp16 GEMM NT (512 thr), A fp32 or fp16 (compile-time) -------------
template<int AH>
__global__ void __launch_bounds__(512) mma_nt(
    const void* __restrict__ Av, int lda, long long sA,
    const float* __restrict__ B, int ldb, long long sB,
    float* __restrict__ C, int ldc, long long sC,
    int M, int N, int K,
    const int* __restrict__ rowsAll, const int* __restrict__ cntAll,
    int causal,
    const float* __restrict__ addA,
    const float* __restrict__ addS, const float* __restrict__ scaleVec)
{
    extern __shared__ uint32_t smw[];
    uint32_t* As = smw;
    uint32_t* Bs = smw + 2 * STG;
    __shared__ int rid[TBM];

    int z = blockIdx.z;
    const float*  Af = (const float*)Av + (AH ? 0 : (size_t)z * sA);
    const __half* Ah = (const __half*)Av + (AH ? (size_t)z * sA : 0);
    B += (size_t)z * sB; C += (size_t)z * sC;
    const int* rows = rowsAll ? rowsAll + (size_t)z * M : 0;
    int Mv = cntAll ? cntAll[z] : M;
    int m0 = blockIdx.y * TBM;
    if (m0 >= Mv) return;
    int n0 = blockIdx.x * TBN;
    if (causal && n0 > m0) return;

    int tid = threadIdx.x;
    if (tid < TBM) {
        int gm = m0 + tid;
        rid[tid] = rows ? (gm < Mv ? rows[gm] : -1) : gm;
    }
    __syncthreads();

    int lrow[4], lcol[4], ra[4], abase[4], bbase[4];
#pragma unroll
    for (int i = 0; i < 4; i++) {
        int idx = tid + i * 512;
        lrow[i] = idx >> 4;
        lcol[i] = (idx & 15) * 4;
        ra[i] = rid[lrow[i]];
        abase[i] = a_w_base(lrow[i], lcol[i]);
        bbase[i] = b_w_base(lrow[i], lcol[i]);
    }

    float4 rA[4], rB[4];
    uint2 rAh[4];
    const float4 z4 = make_float4(0.f, 0.f, 0.f, 0.f);
    const uint2 z2 = make_uint2(0u, 0u);
#pragma unroll
    for (int i = 0; i < 4; i++) {
        if (AH) rAh[i] = (ra[i] >= 0) ? *(const uint2*)(Ah + (size_t)ra[i] * lda + lcol[i]) : z2;
        else    rA[i]  = (ra[i] >= 0) ? *(const float4*)(Af + (size_t)ra[i] * lda + lcol[i]) : z4;
        rB[i] = *(const float4*)(B + (size_t)(n0 + lrow[i]) * ldb + lcol[i]);
    }
#pragma unroll
    for (int i = 0; i < 4; i++) {
        if (AH) a_store_h(As, abase[i], rAh[i]);
        else    a_store(As, abase[i], rA[i]);
        b_store(Bs, bbase[i], rB[i]);
    }
    __syncthreads();

    int lane = tid & 31, wid = tid >> 5;
    int wmblk = (wid & 3) * 2;
    int wnblk = (wid >> 2) * 4;
    int g = lane >> 2, cc = lane & 3;

    float acc[2][4][4];
#pragma unroll
    for (int mi = 0; mi < 2; mi++)
#pragma unroll
        for (int ni = 0; ni < 4; ni++)
#pragma unroll
            for (int j = 0; j < 4; j++) acc[mi][ni][j] = 0.f;

    uint4 afb[2][2];
    uint2 bfb[2][4];
    int nt = K >> 6;
    for (int it = 0; it < nt; it++) {
        int buf = it & 1;
        const uint32_t* Aw = As + buf * STG;
        const uint32_t* Bw = Bs + buf * STG;
        load_frags(Aw, Bw, 0, wmblk, wnblk, lane, afb[0], bfb[0]);
        bool has_next = (it + 1) < nt;
        if (has_next) {
            int kt = (it + 1) << 6;
#pragma unroll
            for (int i = 0; i < 4; i++) {
                if (AH) rAh[i] = (ra[i] >= 0) ? *(const uint2*)(Ah + (size_t)ra[i] * lda + kt + lcol[i]) : z2;
                else    rA[i]  = (ra[i] >= 0) ? *(const float4*)(Af + (size_t)ra[i] * lda + kt + lcol[i]) : z4;
                rB[i] = *(const float4*)(B + (size_t)(n0 + lrow[i]) * ldb + kt + lcol[i]);
            }
        }
#pragma unroll
        for (int s = 0; s < 4; s++) {
            int cur = s & 1;
            if (s < 3)
                load_frags(Aw, Bw, s + 1, wmblk, wnblk, lane, afb[cur ^ 1], bfb[cur ^ 1]);
#pragma unroll
            for (int mi = 0; mi < 2; mi++)
#pragma unroll
                for (int ni = 0; ni < 4; ni++)
                    mma_f16(acc[mi][ni], afb[cur][mi], bfb[cur][ni]);
        }
        if (has_next) {
            uint32_t* an = As + (buf ^ 1) * STG;
            uint32_t* bn = Bs + (buf ^ 1) * STG;
#pragma unroll
            for (int i = 0; i < 4; i++) {
                if (AH) a_store_h(an, abase[i], rAh[i]);
                else    a_store(an, abase[i], rA[i]);
                b_store(bn, bbase[i], rB[i]);
            }
            __syncthreads();
        }
    }

#pragma unroll
    for (int mi = 0; mi < 2; mi++) {
        int r0 = (wid & 3) * 32 + mi * 16 + g;
        int rr[2] = { rid[r0], rid[r0 + 8] };
#pragma unroll
        for (int half = 0; half < 2; half++) {
            int r = rr[half];
            if (r < 0) continue;
#pragma unroll
            for (int ni = 0; ni < 4; ni++) {
                int col = n0 + (wid >> 2) * 32 + ni * 8 + cc * 2;
                float2 v = make_float2(acc[mi][ni][half * 2], acc[mi][ni][half * 2 + 1]);
                if (addA) {
                    float2 a = *(const float2*)(addA + (size_t)r * ldc + col);
                    v.x += a.x; v.y += a.y;
                }
                if (addS) {
                    float w = scaleVec[r];
                    float2 s = *(const float2*)(addS + (size_t)r * ldc + col);
                    v.x += s.x * w; v.y += s.y * w;
                }
                *(float2*)(C + (size_t)r * ldc + col) = v;
            }
        }
    }
}

// ---------------- fp16 GEMM NN (512 thr): A fp16 (Sh), row-scaled epilogue ----------
__global__ void __launch_bounds__(512) mma_nn(
    const __half* __restrict__ A, int lda, long long sA,
    const float* __restrict__ B, int ldb, long long sB,
    float* __restrict__ C, int ldc, long long sC,
    int M, int N, int K, int kcap,
    const float* __restrict__ rscaleAll)
{
    extern __shared__ uint32_t smw[];
    uint32_t* As = smw;
    uint32_t* Bs = smw + 2 * STG;

    int z = blockIdx.z;
    A += (size_t)z * sA; B += (size_t)z * sB; C += (size_t)z * sC;
    const float* rscale = rscaleAll ? rscaleAll + (size_t)z * M : 0;
    int m0 = blockIdx.y * 128;
    int n0 = blockIdx.x * 128;
    int Keff = kcap ? min(K, m0 + 128) : K;

    int tid = threadIdx.x;
    int larow[4], lacol[4], abase[4];
    int lbkr[4], lbng[4];
    int bhalf[4][4];
#pragma unroll
    for (int i = 0; i < 4; i++) {
        int idx = tid + i * 512;
        larow[i] = idx >> 4;
        lacol[i] = (idx & 15) * 4;
        abase[i] = a_w_base(larow[i], lacol[i]);
        lbkr[i] = idx >> 5;
        lbng[i] = (idx & 31) * 4;
        int k = lbkr[i], kk = k & 15;
        int kblk = k >> 4, khigh = kk >> 3, ccB = (kk & 7) >> 1, pos = kk & 1;
#pragma unroll
        for (int jj = 0; jj < 4; jj++) {
            int n = lbng[i] + jj;
            int nblk = n >> 3, gB = n & 7;
            int word = nblk * B_NSTR + kblk * B_KSTR + (gB * 4 + ccB) * 2 + khigh;
            bhalf[i][jj] = word * 2 + pos;
        }
    }

    uint2 rAh[4];
    float4 rB[4];
#pragma unroll
    for (int i = 0; i < 4; i++) {
        rAh[i] = *(const uint2*)(A + (size_t)(m0 + larow[i]) * lda + lacol[i]);
        rB[i] = *(const float4*)(B + (size_t)lbkr[i] * ldb + n0 + lbng[i]);
    }
    {
        __half* Bh = (__half*)Bs;
#pragma unroll
        for (int i = 0; i < 4; i++) {
            a_store_h(As, abase[i], rAh[i]);
            Bh[bhalf[i][0]] = __float2half_rn(rB[i].x);
            Bh[bhalf[i][1]] = __float2half_rn(rB[i].y);
            Bh[bhalf[i][2]] = __float2half_rn(rB[i].z);
            Bh[bhalf[i][3]] = __float2half_rn(rB[i].w);
        }
    }
    __syncthreads();

    int lane = tid & 31, wid = tid >> 5;
    int wmblk = (wid & 3) * 2, wnblk = (wid >> 2) * 4;
    int g = lane >> 2, cc = lane & 3;

    float acc[2][4][4];
#pragma unroll
    for (int mi = 0; mi < 2; mi++)
#pragma unroll
        for (int ni = 0; ni < 4; ni++)
#pragma unroll
            for (int j = 0; j < 4; j++) acc[mi][ni][j] = 0.f;

    uint4 afb[2][2];
    uint2 bfb[2][4];
    int nt = Keff >> 6;
    for (int it = 0; it < nt; it++) {
        int buf = it & 1;
        const uint32_t* Aw = As + buf * STG;
        const uint32_t* Bw = Bs + buf * STG;
        load_frags(Aw, Bw, 0, wmblk, wnblk, lane, afb[0], bfb[0]);
        bool has_next = (it + 1) < nt;
        if (has_next) {
            int kt = (it + 1) << 6;
#pragma unroll
            for (int i = 0; i < 4; i++) {
                rAh[i] = *(const uint2*)(A + (size_t)(m0 + larow[i]) * lda + kt + lacol[i]);
                rB[i] = *(const float4*)(B + (size_t)(kt + lbkr[i]) * ldb + n0 + lbng[i]);
            }
        }
#pragma unroll
        for (int s = 0; s < 4; s++) {
            int cur = s & 1;
            if (s < 3)
                load_frags(Aw, Bw, s + 1, wmblk, wnblk, lane, afb[cur ^ 1], bfb[cur ^ 1]);
#pragma unroll
            for (int mi = 0; mi < 2; mi++)
#pragma unroll
                for (int ni = 0; ni < 4; ni++)
                    mma_f16(acc[mi][ni], afb[cur][mi], bfb[cur][ni]);
        }
        if (has_next) {
            uint32_t* an = As + (buf ^ 1) * STG;
            __half* bn = (__half*)(Bs + (buf ^ 1) * STG);
#pragma unroll
            for (int i = 0; i < 4; i++) {
                a_store_h(an, abase[i], rAh[i]);
                bn[bhalf[i][0]] = __float2half_rn(rB[i].x);
                bn[bhalf[i][1]] = __float2half_rn(rB[i].y);
                bn[bhalf[i][2]] = __float2half_rn(rB[i].z);
                bn[bhalf[i][3]] = __float2half_rn(rB[i].w);
            }
            __syncthreads();
        }
    }

#pragma unroll
    for (int mi = 0; mi < 2; mi++) {
        int r = m0 + (wid & 3) * 32 + mi * 16 + g;
        float s0 = rscale ? rscale[r] : 1.f;
        float s1 = rscale ? rscale[r + 8] : 1.f;
#pragma unroll
        for (int ni = 0; ni < 4; ni++) {
            int col = n0 + (wid >> 2) * 32 + ni * 8 + cc * 2;
            *(float2*)(C + (size_t)r * ldc + col) =
                make_float2(acc[mi][ni][0] * s0, acc[mi][ni][1] * s0);
            *(float2*)(C + (size_t)(r + 8) * ldc + col) =
                make_float2(acc[mi][ni][2] * s1, acc[mi][ni][3] * s1);
        }
    }
}

// ---------------- rope table ----------------
__global__ void rope_table(float* __restrict__ ctab, float* __restrict__ stab) {
    int t = blockIdx.x, i = threadIdx.x;
    double invf = pow(10000.0, -2.0 * (double)i / (double)HD);
    double ang = (double)t * invf;
    ctab[t * (HD / 2) + i] = (float)cos(ang);
    stab[t * (HD / 2) + i] = (float)sin(ang);
}

// ---------------- rmsnorm (float4) ----------------
__global__ void rmsnorm_kernel(const float* __restrict__ x, const float* __restrict__ w,
                               float* __restrict__ out, int ncols) {
    int row = blockIdx.x;
    const float4* xr = (const float4*)(x + (size_t)row * ncols);
    int n4 = ncols >> 2;
    float ss = 0.f;
    for (int i = threadIdx.x; i < n4; i += blockDim.x) {
        float4 v = xr[i];
        ss += v.x * v.x + v.y * v.y + v.z * v.z + v.w * v.w;
    }
    float tot = blk_sum(ss);
    float inv = rsqrtf(tot / (float)ncols + EPS);
    float4* orow = (float4*)(out + (size_t)row * ncols);
    const float4* w4 = (const float4*)w;
    for (int i = threadIdx.x; i < n4; i += blockDim.x) {
        float4 v = xr[i], ww = w4[i];
        orow[i] = make_float4(v.x * inv * ww.x, v.y * inv * ww.y,
                              v.z * inv * ww.z, v.w * inv * ww.w);
    }
}

// ---------------- q/k rmsnorm + rope ----------------
__global__ void __launch_bounds__(512) qk_norm_rope(
    float* __restrict__ qkv,
    const float* __restrict__ qw, const float* __restrict__ kw,
    const float* __restrict__ ctab, const float* __restrict__ stab)
{
    int t = blockIdx.x;
    int wid = threadIdx.x >> 5, lane = threadIdx.x & 31;
#pragma unroll
    for (int r = wid; r < 2 * NH; r += 16) {
        int which = r >> 4, h = r & (NH - 1);
        float* base = qkv + (size_t)t * (3 * H) + (size_t)which * H + (size_t)h * HD;
        float4 v = *(float4*)(base + lane * 4);
        float ss = v.x * v.x + v.y * v.y + v.z * v.z + v.w * v.w;
#pragma unroll
        for (int o = 16; o; o >>= 1) ss += __shfl_xor_sync(0xffffffffu, ss, o);
        float inv = rsqrtf(ss / (float)HD + EPS);
        const float* w = which ? kw : qw;
        float4 wv = *(const float4*)(w + lane * 4);
        float n0 = v.x * inv * wv.x, n1 = v.y * inv * wv.y;
        float n2 = v.z * inv * wv.z, n3 = v.w * inv * wv.w;
        int i0 = lane * 2, i1 = lane * 2 + 1;
        float c0 = ctab[t * (HD / 2) + i0], s0 = stab[t * (HD / 2) + i0];
        float c1 = ctab[t * (HD / 2) + i1], s1 = stab[t * (HD / 2) + i1];
        float4 o;
        o.x = n0 * c0 - n1 * s0;
        o.y = n0 * s0 + n1 * c0;
        o.z = n2 * c1 - n3 * s1;
        o.w = n2 * s1 + n3 * c1;
        *(float4*)(base + lane * 4) = o;
    }
}

// ---------------- causal softmax: reads fp32 scores, writes half exp + 1/sum --------
__global__ void softmax_causal(const float* __restrict__ S, __half* __restrict__ Sh,
                               float* __restrict__ rsum) {
    extern __shared__ float rowbuf[];
    int t = blockIdx.x, h = blockIdx.y;
    const float* row = S + ((size_t)h * T + t) * T;
    __half* hrow = Sh + ((size_t)h * T + t) * T;
    int n = t + 1;
    int fill_end = min(T, ((t >> 7) + 1) << 7);
    const float scale = 0.08838834764831845f;
    float mx = -3.4e38f;
    for (int j = threadIdx.x; j < n; j += blockDim.x) {
        float v = row[j] * scale;
        rowbuf[j] = v;
        mx = fmaxf(mx, v);
    }
    mx = blk_max(mx);
    float sum = 0.f;
    for (int j = threadIdx.x; j < n; j += blockDim.x) {
        float e = expf(rowbuf[j] - mx);
        hrow[j] = __float2half_rn(e);
        sum += e;
    }
    sum = blk_sum(sum);
    if (threadIdx.x == 0) rsum[(size_t)h * T + t] = 1.f / sum;
    const __half hz = __float2half_rn(0.f);
    for (int j = n + (int)threadIdx.x; j < fill_end; j += blockDim.x) hrow[j] = hz;
}

// ---------------- silu_mul: writes half ----------------
__global__ void silu_mul(const float* __restrict__ gu, __half* __restrict__ act) {
    int idx = blockIdx.x * blockDim.x + threadIdx.x;
    if (idx >= T * II) return;
    int t = idx / II, i = idx % II;
    float g = gu[(size_t)t * I2 + i];
    float u = gu[(size_t)t * I2 + II + i];
    act[(size_t)t * II + i] = __float2half_rn((g / (1.f + expf(-g))) * u);
}

// ---------------- routing ----------------
#define GL_TOK 8
__global__ void __launch_bounds__(512) gate_logits(
    const float* __restrict__ h2, const float* __restrict__ gw,
    float* __restrict__ logits)
{
    extern __shared__ float xs[];
    int t0 = blockIdx.x * GL_TOK;
    for (int i = threadIdx.x; i < GL_TOK * H / 4; i += blockDim.x) {
        int tok = i / (H / 4), c4 = i % (H / 4);
        ((float4*)xs)[i] = *(const float4*)(h2 + (size_t)(t0 + tok) * H + c4 * 4);
    }
    __syncthreads();
    int e = threadIdx.x >> 5, lane = threadIdx.x & 31;
    const float* w = gw + (size_t)e * H;
    float s[GL_TOK];
#pragma unroll
    for (int k = 0; k < GL_TOK; k++) s[k] = 0.f;
    for (int k4 = lane; k4 < H / 4; k4 += 32) {
        float4 wv = *(const float4*)(w + k4 * 4);
#pragma unroll
        for (int tok = 0; tok < GL_TOK; tok++) {
            const float* xrow = xs + tok * H + k4 * 4;
            s[tok] += wv.x * xrow[0] + wv.y * xrow[1] + wv.z * xrow[2] + wv.w * xrow[3];
        }
    }
#pragma unroll
    for (int tok = 0; tok < GL_TOK; tok++) {
        float v = s[tok];
#pragma unroll
        for (int o = 16; o; o >>= 1) v += __shfl_xor_sync(0xffffffffu, v, o);
        if (lane == 0) logits[(size_t)(t0 + tok) * NE + e] = v;
    }
}

__global__ void route_and_build(const float* __restrict__ logits, float* __restrict__ topw,
                                int* __restrict__ counts, int* __restrict__ rows) {
    int t = blockIdx.x * blockDim.x + threadIdx.x;
    if (t >= T) return;
    float mx = -3.4e38f;
    int mi = 0;
#pragma unroll
    for (int e = 0; e < NE; e++) {
        float l = logits[(size_t)t * NE + e];
        if (l > mx) { mx = l; mi = e; }
    }
    float s = 0.f;
#pragma unroll
    for (int e = 0; e < NE; e++) s += expf(logits[(size_t)t * NE + e] - mx);
    topw[t] = 1.f / s;
    int p = atomicAdd(&counts[mi], 1);
    rows[(size_t)mi * T + p] = t;
}

__global__ void zero_counts(int* c) {
    if (threadIdx.x < NE) c[threadIdx.x] = 0;
}

// ---------------- host ----------------
#define SYM(p, s) do { void* _v; cudaGetSymbolAddress(&_v, s); p = (decltype(p))_v; } while (0)

extern "C" void kernel_launch(void* const* d_in, const int* in_sizes, int n_in,
                              void* d_out, int out_size) {
    const float* x      = (const float*)d_in[0];
    const float* ln1    = (const float*)d_in[1];
    const float* qkv_w  = (const float*)d_in[2];
    const float* qlnw   = (const float*)d_in[3];
    const float* klnw   = (const float*)d_in[4];
    const float* o_w    = (const float*)d_in[5];
    const float* ln2    = (const float*)d_in[6];
    const float* gate_w = (const float*)d_in[7];
    const float* egu    = (const float*)d_in[8];
    const float* edown  = (const float*)d_in[9];
    const float* sguw   = (const float*)d_in[10];
    const float* sdw    = (const float*)d_in[11];
    float* out = (float*)d_out;

    float *h, *qkv, *S, *rsum, *attn, *x2, *h2, *logits, *topw, *gu, *moe, *sgu;
    __half *Sh, *act, *sact;
    float *ctab, *stab;
    int *counts, *rows;
    SYM(h, g_h); SYM(qkv, g_qkv); SYM(S, g_S); SYM(Sh, g_Sh); SYM(rsum, g_rsum);
    SYM(attn, g_attn); SYM(x2, g_x2); SYM(h2, g_h2); SYM(logits, g_logits);
    SYM(topw, g_topw); SYM(gu, g_gu); SYM(act, g_act); SYM(moe, g_moe);
    SYM(sgu, g_sgu); SYM(sact, g_sact);
    SYM(counts, g_counts); SYM(rows, g_rows);
    SYM(ctab, g_cos); SYM(stab, g_sin);

    cudaFuncSetAttribute(mma_nt<0>, cudaFuncAttributeMaxDynamicSharedMemorySize, GSMEM);
    cudaFuncSetAttribute(mma_nt<1>, cudaFuncAttributeMaxDynamicSharedMemorySize, GSMEM);
    cudaFuncSetAttribute(mma_nn, cudaFuncAttributeMaxDynamicSharedMemorySize, GSMEM);
    cudaFuncSetAttribute(gate_logits, cudaFuncAttributeMaxDynamicSharedMemorySize, GL_TOK * H * 4);
    cudaFuncSetAttribute(softmax_causal, cudaFuncAttributeMaxDynamicSharedMemorySize, T * 4);

    rope_table<<<T, HD / 2>>>(ctab, stab);
    rmsnorm_kernel<<<T, 256>>>(x, ln1, h, H);
    mma_nt<0><<<dim3(3 * H / TBN, T / TBM, 1), 512, GSMEM>>>(h, H, 0, qkv_w, H, 0, qkv, 3 * H, 0,
                                                             T, 3 * H, H, 0, 0, 0, 0, 0, 0);
    qk_norm_rope<<<T, 512>>>(qkv, qlnw, klnw, ctab, stab);
    mma_nt<0><<<dim3(T / TBN, T / TBM, NH), 512, GSMEM>>>(qkv, 3 * H, HD, qkv + H, 3 * H, HD,
                                                          S, T, (long long)T * T, T, T, HD,
                                                          0, 0, 1, 0, 0, 0);
    softmax_causal<<<dim3(T, NH), 256, T * 4>>>(S, Sh, rsum);
    mma_nn<<<dim3(HD / 128, T / 128, NH), 512, GSMEM>>>(Sh, T, (long long)T * T, qkv + 2 * H, 3 * H, HD,
                                                        attn, H, HD, T, HD, T, 1, rsum);
    mma_nt<0><<<dim3(H / TBN, T / TBM, 1), 512, GSMEM>>>(attn, H, 0, o_w, H, 0, x2, H, 0,
                                                         T, H, H, 0, 0, 0, x, 0, 0);
    rmsnorm_kernel<<<T, 256>>>(x2, ln2, h2, H);
    gate_logits<<<T / GL_TOK, 512, GL_TOK * H * 4>>>(h2, gate_w, logits);
    zero_counts<<<1, 32>>>(counts);
    route_and_build<<<(T + 255) / 256, 256>>>(logits, topw, counts, rows);
    mma_nt<0><<<dim3(I2 / TBN, T / TBM, NE), 512, GSMEM>>>(h2, H, 0, egu, H, (long long)I2 * H,
                                                           gu, I2, 0, T, I2, H, rows, counts, 0, 0, 0, 0);
    silu_mul<<<(T * II + 255) / 256, 256>>>(gu, act);
    mma_nt<1><<<dim3(H / TBN, T / TBM, NE), 512, GSMEM>>>(act, II, 0, edown, II, (long long)H * II,
                                                          moe, H, 0, T, H, II, rows, counts, 0, 0, 0, 0);
    mma_nt<0><<<dim3(I2 / TBN, T / TBM, 1), 512, GSMEM>>>(h2, H, 0, sguw, H, 0, sgu, I2, 0,
                                                          T, I2, H, 0, 0, 0, 0, 0, 0);
    silu_mul<<<(T * II + 255) / 256, 256>>>(sgu, sact);
    mma_nt<1><<<dim3(H / TBN, T / TBM, 1), 512, GSMEM>>>(sact, II, 0, sdw, II, 0, out, H, 0,
                                                         T, H, II, 0, 0, 0, x2, moe, topw);
}

// round 16
// speedup vs baseline: 1.8796x; 1.0307x over previous
#include <cuda_runtime.h>
#include <cuda_fp16.h>
#include <math.h>
#include <stdint.h>

#define T  2048
#define H  2048
#define NH 16
#define HD 128
#define NE 16
#define II 2048
#define I2 4096
#define EPS 1e-6f

#define TBM 128
#define TBN 128
#define TBK 64
#define A_KSTR 132
#define A_MSTR 528
#define B_KSTR 66
#define B_NSTR 264
#define STG 4224
#define GSMEM (4 * STG * 4)

// ---------------- scratch ----------------
__device__ __half g_hh[(size_t)T * H];
__device__ float  g_qkv[(size_t)T * 3 * H];
__device__ float  g_S[(size_t)NH * T * T];
__device__ __half g_Sh[(size_t)NH * T * T];
__device__ float  g_rsum[(size_t)NH * T];
__device__ __half g_attnh[(size_t)T * H];
__device__ float  g_x2[(size_t)T * H];
__device__ float  g_h2[(size_t)T * H];
__device__ float  g_logits[(size_t)T * NE];
__device__ float  g_topw[T];
__device__ int    g_counts[NE];
__device__ int    g_rows[(size_t)NE * T];
__device__ float  g_gu[(size_t)T * I2];
__device__ __half g_act[(size_t)T * II];
__device__ float  g_sgu[(size_t)T * I2];
__device__ __half g_sact[(size_t)T * II];
__device__ float  g_moe[(size_t)T * H];
__device__ float  g_cos[(size_t)T * (HD / 2)];
__device__ float  g_sin[(size_t)T * (HD / 2)];

// ---------------- helpers ----------------
__device__ __forceinline__ uint32_t f2h2(float x, float y) {
    __half2 h = __float22half2_rn(make_float2(x, y));
    return *(uint32_t*)&h;
}

__device__ __forceinline__ void mma_f16(float c[4], uint4 a, uint2 b) {
    asm volatile("mma.sync.aligned.m16n8k16.row.col.f32.f16.f16.f32 "
                 "{%0,%1,%2,%3}, {%4,%5,%6,%7}, {%8,%9}, {%0,%1,%2,%3};"
                 : "+f"(c[0]), "+f"(c[1]), "+f"(c[2]), "+f"(c[3])
                 : "r"(a.x), "r"(a.y), "r"(a.z), "r"(a.w), "r"(b.x), "r"(b.y));
}

__device__ __forceinline__ float blk_sum(float v) {
    __shared__ float sh[33];
    __syncthreads();
    int lane = threadIdx.x & 31, w = threadIdx.x >> 5;
#pragma unroll
    for (int o = 16; o; o >>= 1) v += __shfl_xor_sync(0xffffffffu, v, o);
    if (lane == 0) sh[w] = v;
    __syncthreads();
    if (threadIdx.x < 32) {
        int nw = (blockDim.x + 31) >> 5;
        float r = (threadIdx.x < nw) ? sh[threadIdx.x] : 0.f;
#pragma unroll
        for (int o = 16; o; o >>= 1) r += __shfl_xor_sync(0xffffffffu, r, o);
        if (threadIdx.x == 0) sh[32] = r;
    }
    __syncthreads();
    return sh[32];
}

__device__ __forceinline__ float blk_max(float v) {
    __shared__ float sh[33];
    __syncthreads();
    int lane = threadIdx.x & 31, w = threadIdx.x >> 5;
#pragma unroll
    for (int o = 16; o; o >>= 1) v = fmaxf(v, __shfl_xor_sync(0xffffffffu, v, o));
    if (lane == 0) sh[w] = v;
    __syncthreads();
    if (threadIdx.x < 32) {
        int nw = (blockDim.x + 31) >> 5;
        float r = (threadIdx.x < nw) ? sh[threadIdx.x] : -3.4e38f;
#pragma unroll
        for (int o = 16; o; o >>= 1) r = fmaxf(r, __shfl_xor_sync(0xffffffffu, r, o));
        if (threadIdx.x == 0) sh[32] = r;
    }
    __syncthreads();
    return sh[32];
}

__device__ __forceinline__ int a_w_base(int r, int k0) {
    int mblk = r >> 4, rr = r & 15, g = rr & 7, rhalf = rr >> 3;
    int kblk = k0 >> 4, kk = k0 & 15, khigh = kk >> 3, cc = (kk & 7) >> 1;
    return mblk * A_MSTR + kblk * A_KSTR + (g * 4 + cc) * 4 + khigh * 2 + rhalf;
}
__device__ __forceinline__ int b_w_base(int n, int k0) {
    int nblk = n >> 3, g = n & 7;
    int kblk = k0 >> 4, kk = k0 & 15, khigh = kk >> 3, cc = (kk & 7) >> 1;
    return nblk * B_NSTR + kblk * B_KSTR + (g * 4 + cc) * 2 + khigh;
}
__device__ __forceinline__ void a_store(uint32_t* Aw, int base, float4 v) {
    Aw[base]     = f2h2(v.x, v.y);
    Aw[base + 4] = f2h2(v.z, v.w);
}
__device__ __forceinline__ void a_store_h(uint32_t* Aw, int base, uint2 w) {
    Aw[base]     = w.x;
    Aw[base + 4] = w.y;
}
__device__ __forceinline__ void b_store(uint32_t* Bw, int base, float4 v) {
    Bw[base]     = f2h2(v.x, v.y);
    Bw[base + 2] = f2h2(v.z, v.w);
}

__device__ __forceinline__ void load_frags(const uint32_t* Aw, const uint32_t* Bw, int kblk,
                                           int wmblk, int wnblk, int lane,
                                           uint4 af[2], uint2 bf[4]) {
#pragma unroll
    for (int mi = 0; mi < 2; mi++)
        af[mi] = *(const uint4*)(Aw + (wmblk + mi) * A_MSTR + kblk * A_KSTR + lane * 4);
#pragma unroll
    for (int ni = 0; ni < 4; ni++)
        bf[ni] = *(const uint2*)(Bw + (wnblk + ni) * B_NSTR + kblk * B_KSTR + lane * 2);
}

// ---------------- fp16 GEMM NT: A fp32(0)/half(1), B fp32, C fp32; M-major grid -----
template<int AH>
__global__ void __launch_bounds__(512) mma_nt(
    const void* __restrict__ Av, int lda, long long sA,
    const float* __restrict__ B, int ldb, long long sB,
    float* __restrict__ C, int ldc, long long sC,
    int M, int N, int K,
    const int* __restrict__ rowsAll, const int* __restrict__ cntAll,
    int causal,
    const float* __restrict__ addA,
    const float* __restrict__ addS, const float* __restrict__ scaleVec)
{
    extern __shared__ uint32_t smw[];
    uint32_t* As = smw;
    uint32_t* Bs = smw + 2 * STG;
    __shared__ int rid[TBM];

    int z = blockIdx.z;
    const float*  Af = (const float*)Av + (AH ? 0 : (size_t)z * sA);
    const __half* Ah = (const __half*)Av + (AH ? (size_t)z * sA : 0);
    B += (size_t)z * sB; C += (size_t)z * sC;
    const int* rows = rowsAll ? rowsAll + (size_t)z * M : 0;
    int Mv = cntAll ? cntAll[z] : M;
    int m0 = blockIdx.x * TBM;
    if (m0 >= Mv) return;
    int n0 = blockIdx.y * TBN;
    if (causal && n0 > m0) return;

    int tid = threadIdx.x;
    if (tid < TBM) {
        int gm = m0 + tid;
        rid[tid] = rows ? (gm < Mv ? rows[gm] : -1) : gm;
    }
    __syncthreads();

    int lrow[4], lcol[4], ra[4], abase[4], bbase[4];
#pragma unroll
    for (int i = 0; i < 4; i++) {
        int idx = tid + i * 512;
        lrow[i] = idx >> 4;
        lcol[i] = (idx & 15) * 4;
        ra[i] = rid[lrow[i]];
        abase[i] = a_w_base(lrow[i], lcol[i]);
        bbase[i] = b_w_base(lrow[i], lcol[i]);
    }

    float4 rA[4], rB[4];
    uint2 rAh[4];
    const float4 z4 = make_float4(0.f, 0.f, 0.f, 0.f);
    const uint2 z2 = make_uint2(0u, 0u);
#pragma unroll
    for (int i = 0; i < 4; i++) {
        if (AH) rAh[i] = (ra[i] >= 0) ? *(const uint2*)(Ah + (size_t)ra[i] * lda + lcol[i]) : z2;
        else    rA[i]  = (ra[i] >= 0) ? *(const float4*)(Af + (size_t)ra[i] * lda + lcol[i]) : z4;
        rB[i] = *(const float4*)(B + (size_t)(n0 + lrow[i]) * ldb + lcol[i]);
    }
#pragma unroll
    for (int i = 0; i < 4; i++) {
        if (AH) a_store_h(As, abase[i], rAh[i]);
        else    a_store(As, abase[i], rA[i]);
        b_store(Bs, bbase[i], rB[i]);
    }
    __syncthreads();

    int lane = tid & 31, wid = tid >> 5;
    int wmblk = (wid & 3) * 2;
    int wnblk = (wid >> 2) * 4;
    int g = lane >> 2, cc = lane & 3;

    float acc[2][4][4];
#pragma unroll
    for (int mi = 0; mi < 2; mi++)
#pragma unroll
        for (int ni = 0; ni < 4; ni++)
#pragma unroll
            for (int j = 0; j < 4; j++) acc[mi][ni][j] = 0.f;

    uint4 afb[2][2];
    uint2 bfb[2][4];
    int nt = K >> 6;
    for (int it = 0; it < nt; it++) {
        int buf = it & 1;
        const uint32_t* Aw = As + buf * STG;
        const uint32_t* Bw = Bs + buf * STG;
        load_frags(Aw, Bw, 0, wmblk, wnblk, lane, afb[0], bfb[0]);
        bool has_next = (it + 1) < nt;
        if (has_next) {
            int kt = (it + 1) << 6;
#pragma unroll
            for (int i = 0; i < 4; i++) {
                if (AH) rAh[i] = (ra[i] >= 0) ? *(const uint2*)(Ah + (size_t)ra[i] * lda + kt + lcol[i]) : z2;
                else    rA[i]  = (ra[i] >= 0) ? *(const float4*)(Af + (size_t)ra[i] * lda + kt + lcol[i]) : z4;
                rB[i] = *(const float4*)(B + (size_t)(n0 + lrow[i]) * ldb + kt + lcol[i]);
            }
        }
#pragma unroll
        for (int s = 0; s < 4; s++) {
            int cur = s & 1;
            if (s < 3)
                load_frags(Aw, Bw, s + 1, wmblk, wnblk, lane, afb[cur ^ 1], bfb[cur ^ 1]);
#pragma unroll
            for (int mi = 0; mi < 2; mi++)
#pragma unroll
                for (int ni = 0; ni < 4; ni++)
                    mma_f16(acc[mi][ni], afb[cur][mi], bfb[cur][ni]);
        }
        if (has_next) {
            uint32_t* an = As + (buf ^ 1) * STG;
            uint32_t* bn = Bs + (buf ^ 1) * STG;
#pragma unroll
            for (int i = 0; i < 4; i++) {
                if (AH) a_store_h(an, abase[i], rAh[i]);
                else    a_store(an, abase[i], rA[i]);
                b_store(bn, bbase[i], rB[i]);
            }
            __syncthreads();
        }
    }

#pragma unroll
    for (int mi = 0; mi < 2; mi++) {
        int r0 = (wid & 3) * 32 + mi * 16 + g;
        int rr[2] = { rid[r0], rid[r0 + 8] };
#pragma unroll
        for (int half = 0; half < 2; half++) {
            int r = rr[half];
            if (r < 0) continue;
#pragma unroll
            for (int ni = 0; ni < 4; ni++) {
                int col = n0 + (wid >> 2) * 32 + ni * 8 + cc * 2;
                float2 v = make_float2(acc[mi][ni][half * 2], acc[mi][ni][half * 2 + 1]);
                if (addA) {
                    float2 a = *(const float2*)(addA + (size_t)r * ldc + col);
                    v.x += a.x; v.y += a.y;
                }
                if (addS) {
                    float w = scaleVec[r];
                    float2 s = *(const float2*)(addS + (size_t)r * ldc + col);
                    v.x += s.x * w; v.y += s.y * w;
                }
                *(float2*)(C + (size_t)r * ldc + col) = v;
            }
        }
    }
}

// ---------------- fp16 GEMM NN: A half (Sh), B fp32 (V), C half, row-scaled ---------
__global__ void __launch_bounds__(512) mma_nn(
    const __half* __restrict__ A, int lda, long long sA,
    const float* __restrict__ B, int ldb, long long sB,
    __half* __restrict__ C, int ldc, long long sC,
    int M, int N, int K, int kcap,
    const float* __restrict__ rscaleAll)
{
    extern __shared__ uint32_t smw[];
    uint32_t* As = smw;
    uint32_t* Bs = smw + 2 * STG;

    int z = blockIdx.z;
    A += (size_t)z * sA; B += (size_t)z * sB; C += (size_t)z * sC;
    const float* rscale = rscaleAll ? rscaleAll + (size_t)z * M : 0;
    int m0 = blockIdx.y * 128;
    int n0 = blockIdx.x * 128;
    int Keff = kcap ? min(K, m0 + 128) : K;

    int tid = threadIdx.x;
    int larow[4], lacol[4], abase[4];
    int lbkr[4], lbng[4];
    int bhalf[4][4];
#pragma unroll
    for (int i = 0; i < 4; i++) {
        int idx = tid + i * 512;
        larow[i] = idx >> 4;
        lacol[i] = (idx & 15) * 4;
        abase[i] = a_w_base(larow[i], lacol[i]);
        lbkr[i] = idx >> 5;
        lbng[i] = (idx & 31) * 4;
        int k = lbkr[i], kk = k & 15;
        int kblk = k >> 4, khigh = kk >> 3, ccB = (kk & 7) >> 1, pos = kk & 1;
#pragma unroll
        for (int jj = 0; jj < 4; jj++) {
            int n = lbng[i] + jj;
            int nblk = n >> 3, gB = n & 7;
            int word = nblk * B_NSTR + kblk * B_KSTR + (gB * 4 + ccB) * 2 + khigh;
            bhalf[i][jj] = word * 2 + pos;
        }
    }

    uint2 rAh[4];
    float4 rB[4];
#pragma unroll
    for (int i = 0; i < 4; i++) {
        rAh[i] = *(const uint2*)(A + (size_t)(m0 + larow[i]) * lda + lacol[i]);
        rB[i] = *(const float4*)(B + (size_t)lbkr[i] * ldb + n0 + lbng[i]);
    }
    {
        __half* Bh = (__half*)Bs;
#pragma unroll
        for (int i = 0; i < 4; i++) {
            a_store_h(As, abase[i], rAh[i]);
            Bh[bhalf[i][0]] = __float2half_rn(rB[i].x);
            Bh[bhalf[i][1]] = __float2half_rn(rB[i].y);
            Bh[bhalf[i][2]] = __float2half_rn(rB[i].z);
            Bh[bhalf[i][3]] = __float2half_rn(rB[i].w);
        }
    }
    __syncthreads();

    int lane = tid & 31, wid = tid >> 5;
    int wmblk = (wid & 3) * 2, wnblk = (wid >> 2) * 4;
    int g = lane >> 2, cc = lane & 3;

    float acc[2][4][4];
#pragma unroll
    for (int mi = 0; mi < 2; mi++)
#pragma unroll
        for (int ni = 0; ni < 4; ni++)
#pragma unroll
            for (int j = 0; j < 4; j++) acc[mi][ni][j] = 0.f;

    uint4 afb[2][2];
    uint2 bfb[2][4];
    int nt = Keff >> 6;
    for (int it = 0; it < nt; it++) {
        int buf = it & 1;
        const uint32_t* Aw = As + buf * STG;
        const uint32_t* Bw = Bs + buf * STG;
        load_frags(Aw, Bw, 0, wmblk, wnblk, lane, afb[0], bfb[0]);
        bool has_next = (it + 1) < nt;
        if (has_next) {
            int kt = (it + 1) << 6;
#pragma unroll
            for (int i = 0; i < 4; i++) {
                rAh[i] = *(const uint2*)(A + (size_t)(m0 + larow[i]) * lda + kt + lacol[i]);
                rB[i] = *(const float4*)(B + (size_t)(kt + lbkr[i]) * ldb + n0 + lbng[i]);
            }
        }
#pragma unroll
        for (int s = 0; s < 4; s++) {
            int cur = s & 1;
            if (s < 3)
                load_frags(Aw, Bw, s + 1, wmblk, wnblk, lane, afb[cur ^ 1], bfb[cur ^ 1]);
#pragma unroll
            for (int mi = 0; mi < 2; mi++)
#pragma unroll
                for (int ni = 0; ni < 4; ni++)
                    mma_f16(acc[mi][ni], afb[cur][mi], bfb[cur][ni]);
        }
        if (has_next) {
            uint32_t* an = As + (buf ^ 1) * STG;
            __half* bn = (__half*)(Bs + (buf ^ 1) * STG);
#pragma unroll
            for (int i = 0; i < 4; i++) {
                a_store_h(an, abase[i], rAh[i]);
                bn[bhalf[i][0]] = __float2half_rn(rB[i].x);
                bn[bhalf[i][1]] = __float2half_rn(rB[i].y);
                bn[bhalf[i][2]] = __float2half_rn(rB[i].z);
                bn[bhalf[i][3]] = __float2half_rn(rB[i].w);
            }
            __syncthreads();
        }
    }

#pragma unroll
    for (int mi = 0; mi < 2; mi++) {
        int r = m0 + (wid & 3) * 32 + mi * 16 + g;
        float s0 = rscale ? rscale[r] : 1.f;
        float s1 = rscale ? rscale[r + 8] : 1.f;
#pragma unroll
        for (int ni = 0; ni < 4; ni++) {
            int col = n0 + (wid >> 2) * 32 + ni * 8 + cc * 2;
            *(uint32_t*)(C + (size_t)r * ldc + col) =
                f2h2(acc[mi][ni][0] * s0, acc[mi][ni][1] * s0);
            *(uint32_t*)(C + (size_t)(r + 8) * ldc + col) =
                f2h2(acc[mi][ni][2] * s1, acc[mi][ni][3] * s1);
        }
    }
}

// ---------------- rope table ----------------
__global__ void rope_table(float* __restrict__ ctab, float* __restrict__ stab) {
    int t = blockIdx.x, i = threadIdx.x;
    double invf = pow(10000.0, -2.0 * (double)i / (double)HD);
    double ang = (double)t * invf;
    ctab[t * (HD / 2) + i] = (float)cos(ang);
    stab[t * (HD / 2) + i] = (float)sin(ang);
}

// ---------------- rmsnorm: fp32 in, fp32 (OH=0) or half (OH=1) out ------------------
template<int OH>
__global__ void rmsnorm_kernel(const float* __restrict__ x, const float* __restrict__ w,
                               void* __restrict__ outv, int ncols) {
    int row = blockIdx.x;
    const float4* xr = (const float4*)(x + (size_t)row * ncols);
    int n4 = ncols >> 2;
    float ss = 0.f;
    for (int i = threadIdx.x; i < n4; i += blockDim.x) {
        float4 v = xr[i];
        ss += v.x * v.x + v.y * v.y + v.z * v.z + v.w * v.w;
    }
    float tot = blk_sum(ss);
    float inv = rsqrtf(tot / (float)ncols + EPS);
    const float4* w4 = (const float4*)w;
    if (OH) {
        uint2* orow = (uint2*)((__half*)outv + (size_t)row * ncols);
        for (int i = threadIdx.x; i < n4; i += blockDim.x) {
            float4 v = xr[i], ww = w4[i];
            uint2 o;
            o.x = f2h2(v.x * inv * ww.x, v.y * inv * ww.y);
            o.y = f2h2(v.z * inv * ww.z, v.w * inv * ww.w);
            orow[i] = o;
        }
    } else {
        float4* orow = (float4*)((float*)outv + (size_t)row * ncols);
        for (int i = threadIdx.x; i < n4; i += blockDim.x) {
            float4 v = xr[i], ww = w4[i];
            orow[i] = make_float4(v.x * inv * ww.x, v.y * inv * ww.y,
                                  v.z * inv * ww.z, v.w * inv * ww.w);
        }
    }
}

// ---------------- q/k rmsnorm + rope (fp32 qkv) ----------------
__global__ void __launch_bounds__(512) qk_norm_rope(
    float* __restrict__ qkv,
    const float* __restrict__ qw, const float* __restrict__ kw,
    const float* __restrict__ ctab, const float* __restrict__ stab)
{
    int t = blockIdx.x;
    int wid = threadIdx.x >> 5, lane = threadIdx.x & 31;
#pragma unroll
    for (int r = wid; r < 2 * NH; r += 16) {
        int which = r >> 4, h = r & (NH - 1);
        float* base = qkv + (size_t)t * (3 * H) + (size_t)which * H + (size_t)h * HD;
        float4 v = *(float4*)(base + lane * 4);
        float ss = v.x * v.x + v.y * v.y + v.z * v.z + v.w * v.w;
#pragma unroll
        for (int o = 16; o; o >>= 1) ss += __shfl_xor_sync(0xffffffffu, ss, o);
        float inv = rsqrtf(ss / (float)HD + EPS);
        const float* w = which ? kw : qw;
        float4 wv = *(const float4*)(w + lane * 4);
        float n0 = v.x * inv * wv.x, n1 = v.y * inv * wv.y;
        float n2 = v.z * inv * wv.z, n3 = v.w * inv * wv.w;
        int i0 = lane * 2, i1 = lane * 2 + 1;
        float c0 = ctab[t * (HD / 2) + i0], s0 = stab[t * (HD / 2) + i0];
        float c1 = ctab[t * (HD / 2) + i1], s1 = stab[t * (HD / 2) + i1];
        float4 o;
        o.x = n0 * c0 - n1 * s0;
        o.y = n0 * s0 + n1 * c0;
        o.z = n2 * c1 - n3 * s1;
        o.w = n2 * s1 + n3 * c1;
        *(float4*)(base + lane * 4) = o;
    }
}

// ---------------- causal softmax: fp32 scores -> half exp + 1/sum -------------------
__global__ void softmax_causal(const float* __restrict__ S, __half* __restrict__ Sh,
                               float* __restrict__ rsum) {
    extern __shared__ float rowbuf[];
    int t = blockIdx.x, h = blockIdx.y;
    const float* row = S + ((size_t)h * T + t) * T;
    __half* hrow = Sh + ((size_t)h * T + t) * T;
    int n = t + 1;
    int fill_end = min(T, ((t >> 7) + 1) << 7);
    const float scale = 0.08838834764831845f;
    float mx = -3.4e38f;
    for (int j = threadIdx.x; j < n; j += blockDim.x) {
        float v = row[j] * scale;
        rowbuf[j] = v;
        mx = fmaxf(mx, v);
    }
    mx = blk_max(mx);
    float sum = 0.f;
    for (int j = threadIdx.x; j < n; j += blockDim.x) {
        float e = expf(rowbuf[j] - mx);
        hrow[j] = __float2half_rn(e);
        sum += e;
    }
    sum = blk_sum(sum);
    if (threadIdx.x == 0) rsum[(size_t)h * T + t] = 1.f / sum;
    const __half hz = __float2half_rn(0.f);
    for (int j = n + (int)threadIdx.x; j < fill_end; j += blockDim.x) hrow[j] = hz;
}

// ---------------- silu_mul: fp32 gu -> half act ----------------
__global__ void silu_mul(const float* __restrict__ gu, __half* __restrict__ act) {
    int idx = blockIdx.x * blockDim.x + threadIdx.x;
    if (idx >= T * II) return;
    int t = idx / II, i = idx % II;
    float g = gu[(size_t)t * I2 + i];
    float u = gu[(size_t)t * I2 + II + i];
    act[(size_t)t * II + i] = __float2half_rn((g / (1.f + expf(-g))) * u);
}

// ---------------- routing (fp32 h2) ----------------
#define GL_TOK 8
__global__ void __launch_bounds__(512) gate_logits(
    const float* __restrict__ h2, const float* __restrict__ gw,
    float* __restrict__ logits)
{
    extern __shared__ float xs[];
    int t0 = blockIdx.x * GL_TOK;
    for (int i = threadIdx.x; i < GL_TOK * H / 4; i += blockDim.x) {
        int tok = i / (H / 4), c4 = i % (H / 4);
        ((float4*)xs)[i] = *(const float4*)(h2 + (size_t)(t0 + tok) * H + c4 * 4);
    }
    __syncthreads();
    int e = threadIdx.x >> 5, lane = threadIdx.x & 31;
    const float* w = gw + (size_t)e * H;
    float s[GL_TOK];
#pragma unroll
    for (int k = 0; k < GL_TOK; k++) s[k] = 0.f;
    for (int k4 = lane; k4 < H / 4; k4 += 32) {
        float4 wv = *(const float4*)(w + k4 * 4);
#pragma unroll
        for (int tok = 0; tok < GL_TOK; tok++) {
            const float* xrow = xs + tok * H + k4 * 4;
            s[tok] += wv.x * xrow[0] + wv.y * xrow[1] + wv.z * xrow[2] + wv.w * xrow[3];
        }
    }
#pragma unroll
    for (int tok = 0; tok < GL_TOK; tok++) {
        float v = s[tok];
#pragma unroll
        for (int o = 16; o; o >>= 1) v += __shfl_xor_sync(0xffffffffu, v, o);
        if (lane == 0) logits[(size_t)(t0 + tok) * NE + e] = v;
    }
}

__global__ void route_and_build(const float* __restrict__ logits, float* __restrict__ topw,
                                int* __restrict__ counts, int* __restrict__ rows) {
    int t = blockIdx.x * blockDim.x + threadIdx.x;
    if (t >= T) return;
    float mx = -3.4e38f;
    int mi = 0;
#pragma unroll
    for (int e = 0; e < NE; e++) {
        float l = logits[(size_t)t * NE + e];
        if (l > mx) { mx = l; mi = e; }
    }
    float s = 0.f;
#pragma unroll
    for (int e = 0; e < NE; e++) s += expf(logits[(size_t)t * NE + e] - mx);
    topw[t] = 1.f / s;
    int p = atomicAdd(&counts[mi], 1);
    rows[(size_t)mi * T + p] = t;
}

__global__ void zero_counts(int* c) {
    if (threadIdx.x < NE) c[threadIdx.x] = 0;
}

// ---------------- host ----------------
#define SYM(p, s) do { void* _v; cudaGetSymbolAddress(&_v, s); p = (decltype(p))_v; } while (0)

extern "C" void kernel_launch(void* const* d_in, const int* in_sizes, int n_in,
                              void* d_out, int out_size) {
    const float* x      = (const float*)d_in[0];
    const float* ln1    = (const float*)d_in[1];
    const float* qkv_w  = (const float*)d_in[2];
    const float* qlnw   = (const float*)d_in[3];
    const float* klnw   = (const float*)d_in[4];
    const float* o_w    = (const float*)d_in[5];
    const float* ln2    = (const float*)d_in[6];
    const float* gate_w = (const float*)d_in[7];
    const float* egu    = (const float*)d_in[8];
    const float* edown  = (const float*)d_in[9];
    const float* sguw   = (const float*)d_in[10];
    const float* sdw    = (const float*)d_in[11];
    float* out = (float*)d_out;

    __half *hh, *Sh, *attnh, *act, *sact;
    float *qkv, *S, *rsum, *x2, *h2, *logits, *topw, *gu, *sgu, *moe, *ctab, *stab;
    int *counts, *rows;
    SYM(hh, g_hh); SYM(qkv, g_qkv); SYM(S, g_S); SYM(Sh, g_Sh); SYM(rsum, g_rsum);
    SYM(attnh, g_attnh); SYM(x2, g_x2); SYM(h2, g_h2); SYM(logits, g_logits);
    SYM(topw, g_topw); SYM(gu, g_gu); SYM(act, g_act); SYM(moe, g_moe);
    SYM(sgu, g_sgu); SYM(sact, g_sact);
    SYM(counts, g_counts); SYM(rows, g_rows);
    SYM(ctab, g_cos); SYM(stab, g_sin);

    cudaFuncSetAttribute(mma_nt<0>, cudaFuncAttributeMaxDynamicSharedMemorySize, GSMEM);
    cudaFuncSetAttribute(mma_nt<1>, cudaFuncAttributeMaxDynamicSharedMemorySize, GSMEM);
    cudaFuncSetAttribute(mma_nn, cudaFuncAttributeMaxDynamicSharedMemorySize, GSMEM);
    cudaFuncSetAttribute(gate_logits, cudaFuncAttributeMaxDynamicSharedMemorySize, GL_TOK * H * 4);
    cudaFuncSetAttribute(softmax_causal, cudaFuncAttributeMaxDynamicSharedMemorySize, T * 4);

    rope_table<<<T, HD / 2>>>(ctab, stab);
    // h (half) = rmsnorm(x, ln1)
    rmsnorm_kernel<1><<<T, 256>>>(x, ln1, hh, H);
    // qkv (fp32) = h @ qkv_w^T  (A half; M-major grid)
    mma_nt<1><<<dim3(T / TBM, 3 * H / TBN, 1), 512, GSMEM>>>(
        hh, H, 0, qkv_w, H, 0, qkv, 3 * H, 0, T, 3 * H, H, 0, 0, 0, 0, 0, 0);
    qk_norm_rope<<<T, 512>>>(qkv, qlnw, klnw, ctab, stab);
    // S (fp32) = Q K^T (causal skip)
    mma_nt<0><<<dim3(T / TBM, T / TBN, NH), 512, GSMEM>>>(
        qkv, 3 * H, HD, qkv + H, 3 * H, HD, S, T, (long long)T * T,
        T, T, HD, 0, 0, 1, 0, 0, 0);
    softmax_causal<<<dim3(T, NH), 256, T * 4>>>(S, Sh, rsum);
    // attn (half) = (E V) * 1/sum
    mma_nn<<<dim3(HD / 128, T / 128, NH), 512, GSMEM>>>(
        Sh, T, (long long)T * T, qkv + 2 * H, 3 * H, HD,
        attnh, H, HD, T, HD, T, 1, rsum);
    // x2 (fp32) = x + attn @ o_w^T
    mma_nt<1><<<dim3(T / TBM, H / TBN, 1), 512, GSMEM>>>(
        attnh, H, 0, o_w, H, 0, x2, H, 0, T, H, H, 0, 0, 0, x, 0, 0);
    // h2 (fp32) = rmsnorm(x2, ln2) — fp32 for routing
    rmsnorm_kernel<0><<<T, 256>>>(x2, ln2, h2, H);
    gate_logits<<<T / GL_TOK, 512, GL_TOK * H * 4>>>(h2, gate_w, logits);
    zero_counts<<<1, 32>>>(counts);
    route_and_build<<<(T + 255) / 256, 256>>>(logits, topw, counts, rows);
    // MoE gate-up (gathered, A fp32 h2)
    mma_nt<0><<<dim3(T / TBM, I2 / TBN, NE), 512, GSMEM>>>(
        h2, H, 0, egu, H, (long long)I2 * H, gu, I2, 0,
        T, I2, H, rows, counts, 0, 0, 0, 0);
    silu_mul<<<(T * II + 255) / 256, 256>>>(gu, act);
    // MoE down (gathered, A half act)
    mma_nt<1><<<dim3(T / TBM, H / TBN, NE), 512, GSMEM>>>(
        act, II, 0, edown, II, (long long)H * II, moe, H, 0,
        T, H, II, rows, counts, 0, 0, 0, 0);
    // shared gate-up (A fp32 h2)
    mma_nt<0><<<dim3(T / TBM, I2 / TBN, 1), 512, GSMEM>>>(
        h2, H, 0, sguw, H, 0, sgu, I2, 0, T, I2, H, 0, 0, 0, 0, 0, 0);
    silu_mul<<<(T * II + 255) / 256, 256>>>(sgu, sact);
    // out = x2 + topw*moe + sact @ sdw^T (A half sact)
    mma_nt<1><<<dim3(T / TBM, H / TBN, 1), 512, GSMEM>>>(
        sact, II, 0, sdw, II, 0, out, H, 0, T, H, II, 0, 0, 0, x2, moe, topw);
}

// round 17
// speedup vs baseline: 2.0059x; 1.0672x over previous
#include <cuda_runtime.h>
#include <cuda_fp16.h>
#include <math.h>
#include <stdint.h>

#define T  2048
#define H  2048
#define NH 16
#define HD 128
#define NE 16
#define II 2048
#define I2 4096
#define EPS 1e-6f

#define TBM 128
#define TBN 128
#define TBK 64
#define A_KSTR 132
#define A_MSTR 528
#define B_KSTR 66
#define B_NSTR 264
#define STG 4224
#define GSMEM (4 * STG * 4)

// flash smem layout (words)
#define SMW_Q 0
#define SMW_K (2 * STG)
#define SMW_V (4 * STG)
#define SMW_P (6 * STG)
#define SMW_RED (8 * STG)
#define FL_SMEM ((8 * STG + 896) * 4)   // 138752 B

// ---------------- scratch ----------------
__device__ __half g_hh[(size_t)T * H];
__device__ float  g_qkv[(size_t)T * 3 * H];
__device__ __half g_attnh[(size_t)T * H];
__device__ float  g_x2[(size_t)T * H];
__device__ float  g_h2[(size_t)T * H];
__device__ float  g_logits[(size_t)T * NE];
__device__ float  g_topw[T];
__device__ int    g_counts[NE];
__device__ int    g_rows[(size_t)NE * T];
__device__ float  g_gu[(size_t)T * I2];
__device__ __half g_act[(size_t)T * II];
__device__ float  g_sgu[(size_t)T * I2];
__device__ __half g_sact[(size_t)T * II];
__device__ float  g_moe[(size_t)T * H];
__device__ float  g_cos[(size_t)T * (HD / 2)];
__device__ float  g_sin[(size_t)T * (HD / 2)];

// ---------------- helpers ----------------
__device__ __forceinline__ uint32_t f2h2(float x, float y) {
    __half2 h = __float22half2_rn(make_float2(x, y));
    return *(uint32_t*)&h;
}

__device__ __forceinline__ void mma_f16(float c[4], uint4 a, uint2 b) {
    asm volatile("mma.sync.aligned.m16n8k16.row.col.f32.f16.f16.f32 "
                 "{%0,%1,%2,%3}, {%4,%5,%6,%7}, {%8,%9}, {%0,%1,%2,%3};"
                 : "+f"(c[0]), "+f"(c[1]), "+f"(c[2]), "+f"(c[3])
                 : "r"(a.x), "r"(a.y), "r"(a.z), "r"(a.w), "r"(b.x), "r"(b.y));
}

__device__ __forceinline__ float blk_sum(float v) {
    __shared__ float sh[33];
    __syncthreads();
    int lane = threadIdx.x & 31, w = threadIdx.x >> 5;
#pragma unroll
    for (int o = 16; o; o >>= 1) v += __shfl_xor_sync(0xffffffffu, v, o);
    if (lane == 0) sh[w] = v;
    __syncthreads();
    if (threadIdx.x < 32) {
        int nw = (blockDim.x + 31) >> 5;
        float r = (threadIdx.x < nw) ? sh[threadIdx.x] : 0.f;
#pragma unroll
        for (int o = 16; o; o >>= 1) r += __shfl_xor_sync(0xffffffffu, r, o);
        if (threadIdx.x == 0) sh[32] = r;
    }
    __syncthreads();
    return sh[32];
}

__device__ __forceinline__ int a_w_base(int r, int k0) {
    int mblk = r >> 4, rr = r & 15, g = rr & 7, rhalf = rr >> 3;
    int kblk = k0 >> 4, kk = k0 & 15, khigh = kk >> 3, cc = (kk & 7) >> 1;
    return mblk * A_MSTR + kblk * A_KSTR + (g * 4 + cc) * 4 + khigh * 2 + rhalf;
}
__device__ __forceinline__ int b_w_base(int n, int k0) {
    int nblk = n >> 3, g = n & 7;
    int kblk = k0 >> 4, kk = k0 & 15, khigh = kk >> 3, cc = (kk & 7) >> 1;
    return nblk * B_NSTR + kblk * B_KSTR + (g * 4 + cc) * 2 + khigh;
}
__device__ __forceinline__ void a_store(uint32_t* Aw, int base, float4 v) {
    Aw[base]     = f2h2(v.x, v.y);
    Aw[base + 4] = f2h2(v.z, v.w);
}
__device__ __forceinline__ void a_store_h(uint32_t* Aw, int base, uint2 w) {
    Aw[base]     = w.x;
    Aw[base + 4] = w.y;
}
__device__ __forceinline__ void b_store(uint32_t* Bw, int base, float4 v) {
    Bw[base]     = f2h2(v.x, v.y);
    Bw[base + 2] = f2h2(v.z, v.w);
}

__device__ __forceinline__ void load_frags(const uint32_t* Aw, const uint32_t* Bw, int kblk,
                                           int wmblk, int wnblk, int lane,
                                           uint4 af[2], uint2 bf[4]) {
#pragma unroll
    for (int mi = 0; mi < 2; mi++)
        af[mi] = *(const uint4*)(Aw + (wmblk + mi) * A_MSTR + kblk * A_KSTR + lane * 4);
#pragma unroll
    for (int ni = 0; ni < 4; ni++)
        bf[ni] = *(const uint2*)(Bw + (wnblk + ni) * B_NSTR + kblk * B_KSTR + lane * 2);
}

// ---------------- fp16 GEMM NT: A fp32(0)/half(1), B fp32, C fp32; M-major grid -----
template<int AH>
__global__ void __launch_bounds__(512) mma_nt(
    const void* __restrict__ Av, int lda, long long sA,
    const float* __restrict__ B, int ldb, long long sB,
    float* __restrict__ C, int ldc, long long sC,
    int M, int N, int K,
    const int* __restrict__ rowsAll, const int* __restrict__ cntAll,
    const float* __restrict__ addA,
    const float* __restrict__ addS, const float* __restrict__ scaleVec)
{
    extern __shared__ uint32_t smw[];
    uint32_t* As = smw;
    uint32_t* Bs = smw + 2 * STG;
    __shared__ int rid[TBM];

    int z = blockIdx.z;
    const float*  Af = (const float*)Av + (AH ? 0 : (size_t)z * sA);
    const __half* Ah = (const __half*)Av + (AH ? (size_t)z * sA : 0);
    B += (size_t)z * sB; C += (size_t)z * sC;
    const int* rows = rowsAll ? rowsAll + (size_t)z * M : 0;
    int Mv = cntAll ? cntAll[z] : M;
    int m0 = blockIdx.x * TBM;
    if (m0 >= Mv) return;
    int n0 = blockIdx.y * TBN;

    int tid = threadIdx.x;
    if (tid < TBM) {
        int gm = m0 + tid;
        rid[tid] = rows ? (gm < Mv ? rows[gm] : -1) : gm;
    }
    __syncthreads();

    int lrow[4], lcol[4], ra[4], abase[4], bbase[4];
#pragma unroll
    for (int i = 0; i < 4; i++) {
        int idx = tid + i * 512;
        lrow[i] = idx >> 4;
        lcol[i] = (idx & 15) * 4;
        ra[i] = rid[lrow[i]];
        abase[i] = a_w_base(lrow[i], lcol[i]);
        bbase[i] = b_w_base(lrow[i], lcol[i]);
    }

    float4 rA[4], rB[4];
    uint2 rAh[4];
    const float4 z4 = make_float4(0.f, 0.f, 0.f, 0.f);
    const uint2 z2 = make_uint2(0u, 0u);
#pragma unroll
    for (int i = 0; i < 4; i++) {
        if (AH) rAh[i] = (ra[i] >= 0) ? *(const uint2*)(Ah + (size_t)ra[i] * lda + lcol[i]) : z2;
        else    rA[i]  = (ra[i] >= 0) ? *(const float4*)(Af + (size_t)ra[i] * lda + lcol[i]) : z4;
        rB[i] = *(const float4*)(B + (size_t)(n0 + lrow[i]) * ldb + lcol[i]);
    }
#pragma unroll
    for (int i = 0; i < 4; i++) {
        if (AH) a_store_h(As, abase[i], rAh[i]);
        else    a_store(As, abase[i], rA[i]);
        b_store(Bs, bbase[i], rB[i]);
    }
    __syncthreads();

    int lane = tid & 31, wid = tid >> 5;
    int wmblk = (wid & 3) * 2;
    int wnblk = (wid >> 2) * 4;
    int g = lane >> 2, cc = lane & 3;

    float acc[2][4][4];
#pragma unroll
    for (int mi = 0; mi < 2; mi++)
#pragma unroll
        for (int ni = 0; ni < 4; ni++)
#pragma unroll
            for (int j = 0; j < 4; j++) acc[mi][ni][j] = 0.f;

    uint4 afb[2][2];
    uint2 bfb[2][4];
    int nt = K >> 6;
    for (int it = 0; it < nt; it++) {
        int buf = it & 1;
        const uint32_t* Aw = As + buf * STG;
        const uint32_t* Bw = Bs + buf * STG;
        load_frags(Aw, Bw, 0, wmblk, wnblk, lane, afb[0], bfb[0]);
        bool has_next = (it + 1) < nt;
        if (has_next) {
            int kt = (it + 1) << 6;
#pragma unroll
            for (int i = 0; i < 4; i++) {
                if (AH) rAh[i] = (ra[i] >= 0) ? *(const uint2*)(Ah + (size_t)ra[i] * lda + kt + lcol[i]) : z2;
                else    rA[i]  = (ra[i] >= 0) ? *(const float4*)(Af + (size_t)ra[i] * lda + kt + lcol[i]) : z4;
                rB[i] = *(const float4*)(B + (size_t)(n0 + lrow[i]) * ldb + kt + lcol[i]);
            }
        }
#pragma unroll
        for (int s = 0; s < 4; s++) {
            int cur = s & 1;
            if (s < 3)
                load_frags(Aw, Bw, s + 1, wmblk, wnblk, lane, afb[cur ^ 1], bfb[cur ^ 1]);
#pragma unroll
            for (int mi = 0; mi < 2; mi++)
#pragma unroll
                for (int ni = 0; ni < 4; ni++)
                    mma_f16(acc[mi][ni], afb[cur][mi], bfb[cur][ni]);
        }
        if (has_next) {
            uint32_t* an = As + (buf ^ 1) * STG;
            uint32_t* bn = Bs + (buf ^ 1) * STG;
#pragma unroll
            for (int i = 0; i < 4; i++) {
                if (AH) a_store_h(an, abase[i], rAh[i]);
                else    a_store(an, abase[i], rA[i]);
                b_store(bn, bbase[i], rB[i]);
            }
            __syncthreads();
        }
    }

#pragma unroll
    for (int mi = 0; mi < 2; mi++) {
        int r0 = (wid & 3) * 32 + mi * 16 + g;
        int rr[2] = { rid[r0], rid[r0 + 8] };
#pragma unroll
        for (int half = 0; half < 2; half++) {
            int r = rr[half];
            if (r < 0) continue;
#pragma unroll
            for (int ni = 0; ni < 4; ni++) {
                int col = n0 + (wid >> 2) * 32 + ni * 8 + cc * 2;
                float2 v = make_float2(acc[mi][ni][half * 2], acc[mi][ni][half * 2 + 1]);
                if (addA) {
                    float2 a = *(const float2*)(addA + (size_t)r * ldc + col);
                    v.x += a.x; v.y += a.y;
                }
                if (addS) {
                    float w = scaleVec[r];
                    float2 s = *(const float2*)(addS + (size_t)r * ldc + col);
                    v.x += s.x * w; v.y += s.y * w;
                }
                *(float2*)(C + (size_t)r * ldc + col) = v;
            }
        }
    }
}

// ---------------- fused flash attention ----------------
// grid: (T/128, NH); 512 threads. Q,K,V from fp32 qkv; writes half attn.
__global__ void __launch_bounds__(512) flash_attn(
    const float* __restrict__ qkv, __half* __restrict__ attn)
{
    extern __shared__ uint32_t smw[];
    uint32_t* qs = smw + SMW_Q;
    uint32_t* ks = smw + SMW_K;
    uint32_t* vs = smw + SMW_V;
    uint32_t* ps = smw + SMW_P;
    float* m_i = (float*)(smw + SMW_RED);
    float* l_i = m_i + 128;
    float* f_i = m_i + 256;
    float* red = m_i + 384;   // [4][128]

    int m0 = blockIdx.x * 128;
    int head = blockIdx.y;
    int tid = threadIdx.x, lane = tid & 31, wid = tid >> 5;
    int wmblk = (wid & 3) * 2, wnblk = (wid >> 2) * 4;
    int g = lane >> 2, cc = lane & 3;
    const float scale = 0.08838834764831845f;

    // load Q tile (2 k-stages)
#pragma unroll
    for (int s = 0; s < 2; s++)
#pragma unroll
        for (int i = 0; i < 4; i++) {
            int idx = tid + i * 512;
            int r = idx >> 4, c = (idx & 15) * 4;
            float4 v = *(const float4*)(qkv + (size_t)(m0 + r) * (3 * H) + head * HD + s * 64 + c);
            a_store(qs + s * STG, a_w_base(r, c), v);
        }
    if (tid < 128) { m_i[tid] = -3.0e38f; l_i[tid] = 0.f; }

    float oacc[2][4][4];
#pragma unroll
    for (int mi = 0; mi < 2; mi++)
#pragma unroll
        for (int ni = 0; ni < 4; ni++)
#pragma unroll
            for (int j = 0; j < 4; j++) oacc[mi][ni][j] = 0.f;

    for (int n0 = 0; n0 <= m0; n0 += 128) {
        __syncthreads();   // protect ks/vs/ps/red from prev iter readers
        // load K tile (B-NT layout) and V tile (B-NN layout)
#pragma unroll
        for (int s = 0; s < 2; s++)
#pragma unroll
            for (int i = 0; i < 4; i++) {
                int idx = tid + i * 512;
                int r = idx >> 4, c = (idx & 15) * 4;
                float4 kv = *(const float4*)(qkv + (size_t)(n0 + r) * (3 * H) + H + head * HD + s * 64 + c);
                b_store(ks + s * STG, b_w_base(r, c), kv);
                int kr = idx >> 5, nc = (idx & 31) * 4;
                float4 vv = *(const float4*)(qkv + (size_t)(n0 + s * 64 + kr) * (3 * H) + 2 * H + head * HD + nc);
                __half* vh = (__half*)(vs + s * STG);
                int kk = kr & 15;
                int kblk = kr >> 4, khigh = kk >> 3, ccB = (kk & 7) >> 1, pos = kr & 1;
                const float* vf = (const float*)&vv;
#pragma unroll
                for (int jj = 0; jj < 4; jj++) {
                    int n = nc + jj;
                    int word = (n >> 3) * B_NSTR + kblk * B_KSTR + ((n & 7) * 4 + ccB) * 2 + khigh;
                    vh[word * 2 + pos] = __float2half_rn(vf[jj]);
                }
            }
        __syncthreads();   // B1: tiles ready

        // S = Q K^T
        float sacc[2][4][4];
#pragma unroll
        for (int mi = 0; mi < 2; mi++)
#pragma unroll
            for (int ni = 0; ni < 4; ni++)
#pragma unroll
                for (int j = 0; j < 4; j++) sacc[mi][ni][j] = 0.f;
#pragma unroll
        for (int s = 0; s < 2; s++)
#pragma unroll
            for (int sub = 0; sub < 4; sub++) {
                uint4 af[2]; uint2 bf[4];
                load_frags(qs + s * STG, ks + s * STG, sub, wmblk, wnblk, lane, af, bf);
#pragma unroll
                for (int mi = 0; mi < 2; mi++)
#pragma unroll
                    for (int ni = 0; ni < 4; ni++)
                        mma_f16(sacc[mi][ni], af[mi], bf[ni]);
            }

        // scale + causal mask (diag tile)
        bool diag = (n0 == m0);
#pragma unroll
        for (int mi = 0; mi < 2; mi++) {
            int r0 = wmblk * 16 + mi * 16 + g;
#pragma unroll
            for (int ni = 0; ni < 4; ni++) {
                int col = wnblk * 8 + ni * 8 + cc * 2;
#pragma unroll
                for (int j = 0; j < 4; j++) {
                    int r = r0 + (j >> 1) * 8;
                    int c = col + (j & 1);
                    float v = sacc[mi][ni][j] * scale;
                    if (diag && c > r) v = -1.0e30f;
                    sacc[mi][ni][j] = v;
                }
            }
        }

        // row max within warp slice -> red[group][row]
#pragma unroll
        for (int mi = 0; mi < 2; mi++) {
            float mx0 = -3.0e38f, mx1 = -3.0e38f;
#pragma unroll
            for (int ni = 0; ni < 4; ni++) {
                mx0 = fmaxf(mx0, fmaxf(sacc[mi][ni][0], sacc[mi][ni][1]));
                mx1 = fmaxf(mx1, fmaxf(sacc[mi][ni][2], sacc[mi][ni][3]));
            }
#pragma unroll
            for (int o = 1; o <= 2; o <<= 1) {
                mx0 = fmaxf(mx0, __shfl_xor_sync(0xffffffffu, mx0, o));
                mx1 = fmaxf(mx1, __shfl_xor_sync(0xffffffffu, mx1, o));
            }
            if (cc == 0) {
                int r0 = (wid & 3) * 32 + mi * 16 + g;
                red[(wid >> 2) * 128 + r0] = mx0;
                red[(wid >> 2) * 128 + r0 + 8] = mx1;
            }
        }
        __syncthreads();   // B2

        // update m, f
        if (tid < 128) {
            float mnew = fmaxf(fmaxf(red[tid], red[128 + tid]),
                               fmaxf(red[256 + tid], red[384 + tid]));
            mnew = fmaxf(mnew, m_i[tid]);
            f_i[tid] = expf(m_i[tid] - mnew);
            m_i[tid] = mnew;
        }
        __syncthreads();   // B3

        // P = exp(s - m); store to ps (A layout); partial row sums -> red
#pragma unroll
        for (int mi = 0; mi < 2; mi++) {
            int r0 = (wid & 3) * 32 + mi * 16 + g;
            float mn0 = m_i[r0], mn1 = m_i[r0 + 8];
            float sum0 = 0.f, sum1 = 0.f;
#pragma unroll
            for (int ni = 0; ni < 4; ni++) {
                float p0 = expf(sacc[mi][ni][0] - mn0);
                float p1 = expf(sacc[mi][ni][1] - mn0);
                float p2 = expf(sacc[mi][ni][2] - mn1);
                float p3 = expf(sacc[mi][ni][3] - mn1);
                sum0 += p0 + p1;
                sum1 += p2 + p3;
                int kabs = (wid >> 2) * 32 + ni * 8 + cc * 2;
                int stg = kabs >> 6, kl = kabs & 63;
                ps[stg * STG + a_w_base(r0, kl)] = f2h2(p0, p1);
                ps[stg * STG + a_w_base(r0 + 8, kl)] = f2h2(p2, p3);
            }
#pragma unroll
            for (int o = 1; o <= 2; o <<= 1) {
                sum0 += __shfl_xor_sync(0xffffffffu, sum0, o);
                sum1 += __shfl_xor_sync(0xffffffffu, sum1, o);
            }
            if (cc == 0) {
                red[(wid >> 2) * 128 + r0] = sum0;
                red[(wid >> 2) * 128 + r0 + 8] = sum1;
            }
        }
        __syncthreads();   // B4

        // l update
        if (tid < 128)
            l_i[tid] = l_i[tid] * f_i[tid] +
                       red[tid] + red[128 + tid] + red[256 + tid] + red[384 + tid];

        // rescale O by f for my rows
#pragma unroll
        for (int mi = 0; mi < 2; mi++) {
            int r0 = (wid & 3) * 32 + mi * 16 + g;
            float f0 = f_i[r0], f1 = f_i[r0 + 8];
#pragma unroll
            for (int ni = 0; ni < 4; ni++) {
                oacc[mi][ni][0] *= f0; oacc[mi][ni][1] *= f0;
                oacc[mi][ni][2] *= f1; oacc[mi][ni][3] *= f1;
            }
        }

        // O += P @ V
#pragma unroll
        for (int s = 0; s < 2; s++)
#pragma unroll
            for (int sub = 0; sub < 4; sub++) {
                uint4 af[2]; uint2 bf[4];
                load_frags(ps + s * STG, vs + s * STG, sub, wmblk, wnblk, lane, af, bf);
#pragma unroll
                for (int mi = 0; mi < 2; mi++)
#pragma unroll
                    for (int ni = 0; ni < 4; ni++)
                        mma_f16(oacc[mi][ni], af[mi], bf[ni]);
            }
    }
    __syncthreads();

    // write attn = O / l (half)
#pragma unroll
    for (int mi = 0; mi < 2; mi++) {
        int r0 = (wid & 3) * 32 + mi * 16 + g;
        float i0 = 1.f / l_i[r0], i1 = 1.f / l_i[r0 + 8];
#pragma unroll
        for (int ni = 0; ni < 4; ni++) {
            int col = (wid >> 2) * 32 + ni * 8 + cc * 2;
            *(uint32_t*)(attn + (size_t)(m0 + r0) * H + head * HD + col) =
                f2h2(oacc[mi][ni][0] * i0, oacc[mi][ni][1] * i0);
            *(uint32_t*)(attn + (size_t)(m0 + r0 + 8) * H + head * HD + col) =
                f2h2(oacc[mi][ni][2] * i1, oacc[mi][ni][3] * i1);
        }
    }
}

// ---------------- rope table ----------------
__global__ void rope_table(float* __restrict__ ctab, float* __restrict__ stab) {
    int t = blockIdx.x, i = threadIdx.x;
    double invf = pow(10000.0, -2.0 * (double)i / (double)HD);
    double ang = (double)t * invf;
    ctab[t * (HD / 2) + i] = (float)cos(ang);
    stab[t * (HD / 2) + i] = (float)sin(ang);
}

// ---------------- rmsnorm: fp32 in, fp32 (OH=0) or half (OH=1) out ------------------
template<int OH>
__global__ void rmsnorm_kernel(const float* __restrict__ x, const float* __restrict__ w,
                               void* __restrict__ outv, int ncols) {
    int row = blockIdx.x;
    const float4* xr = (const float4*)(x + (size_t)row * ncols);
    int n4 = ncols >> 2;
    float ss = 0.f;
    for (int i = threadIdx.x; i < n4; i += blockDim.x) {
        float4 v = xr[i];
        ss += v.x * v.x + v.y * v.y + v.z * v.z + v.w * v.w;
    }
    float tot = blk_sum(ss);
    float inv = rsqrtf(tot / (float)ncols + EPS);
    const float4* w4 = (const float4*)w;
    if (OH) {
        uint2* orow = (uint2*)((__half*)outv + (size_t)row * ncols);
        for (int i = threadIdx.x; i < n4; i += blockDim.x) {
            float4 v = xr[i], ww = w4[i];
            uint2 o;
            o.x = f2h2(v.x * inv * ww.x, v.y * inv * ww.y);
            o.y = f2h2(v.z * inv * ww.z, v.w * inv * ww.w);
            orow[i] = o;
        }
    } else {
        float4* orow = (float4*)((float*)outv + (size_t)row * ncols);
        for (int i = threadIdx.x; i < n4; i += blockDim.x) {
            float4 v = xr[i], ww = w4[i];
            orow[i] = make_float4(v.x * inv * ww.x, v.y * inv * ww.y,
                                  v.z * inv * ww.z, v.w * inv * ww.w);
        }
    }
}

// ---------------- q/k rmsnorm + rope (fp32 qkv) ----------------
__global__ void __launch_bounds__(512) qk_norm_rope(
    float* __restrict__ qkv,
    const float* __restrict__ qw, const float* __restrict__ kw,
    const float* __restrict__ ctab, const float* __restrict__ stab)
{
    int t = blockIdx.x;
    int wid = threadIdx.x >> 5, lane = threadIdx.x & 31;
#pragma unroll
    for (int r = wid; r < 2 * NH; r += 16) {
        int which = r >> 4, h = r & (NH - 1);
        float* base = qkv + (size_t)t * (3 * H) + (size_t)which * H + (size_t)h * HD;
        float4 v = *(float4*)(base + lane * 4);
        float ss = v.x * v.x + v.y * v.y + v.z * v.z + v.w * v.w;
#pragma unroll
        for (int o = 16; o; o >>= 1) ss += __shfl_xor_sync(0xffffffffu, ss, o);
        float inv = rsqrtf(ss / (float)HD + EPS);
        const float* w = which ? kw : qw;
        float4 wv = *(const float4*)(w + lane * 4);
        float n0 = v.x * inv * wv.x, n1 = v.y * inv * wv.y;
        float n2 = v.z * inv * wv.z, n3 = v.w * inv * wv.w;
        int i0 = lane * 2, i1 = lane * 2 + 1;
        float c0 = ctab[t * (HD / 2) + i0], s0 = stab[t * (HD / 2) + i0];
        float c1 = ctab[t * (HD / 2) + i1], s1 = stab[t * (HD / 2) + i1];
        float4 o;
        o.x = n0 * c0 - n1 * s0;
        o.y = n0 * s0 + n1 * c0;
        o.z = n2 * c1 - n3 * s1;
        o.w = n2 * s1 + n3 * c1;
        *(float4*)(base + lane * 4) = o;
    }
}

// ---------------- silu_mul: fp32 gu -> half act ----------------
__global__ void silu_mul(const float* __restrict__ gu, __half* __restrict__ act) {
    int idx = blockIdx.x * blockDim.x + threadIdx.x;
    if (idx >= T * II) return;
    int t = idx / II, i = idx % II;
    float g = gu[(size_t)t * I2 + i];
    float u = gu[(size_t)t * I2 + II + i];
    act[(size_t)t * II + i] = __float2half_rn((g / (1.f + expf(-g))) * u);
}

// ---------------- routing (fp32 h2) ----------------
#define GL_TOK 8
__global__ void __launch_bounds__(512) gate_logits(
    const float* __restrict__ h2, const float* __restrict__ gw,
    float* __restrict__ logits)
{
    extern __shared__ float xs[];
    int t0 = blockIdx.x * GL_TOK;
    for (int i = threadIdx.x; i < GL_TOK * H / 4; i += blockDim.x) {
        int tok = i / (H / 4), c4 = i % (H / 4);
        ((float4*)xs)[i] = *(const float4*)(h2 + (size_t)(t0 + tok) * H + c4 * 4);
    }
    __syncthreads();
    int e = threadIdx.x >> 5, lane = threadIdx.x & 31;
    const float* w = gw + (size_t)e * H;
    float s[GL_TOK];
#pragma unroll
    for (int k = 0; k < GL_TOK; k++) s[k] = 0.f;
    for (int k4 = lane; k4 < H / 4; k4 += 32) {
        float4 wv = *(const float4*)(w + k4 * 4);
#pragma unroll
        for (int tok = 0; tok < GL_TOK; tok++) {
            const float* xrow = xs + tok * H + k4 * 4;
            s[tok] += wv.x * xrow[0] + wv.y * xrow[1] + wv.z * xrow[2] + wv.w * xrow[3];
        }
    }
#pragma unroll
    for (int tok = 0; tok < GL_TOK; tok++) {
        float v = s[tok];
#pragma unroll
        for (int o = 16; o; o >>= 1) v += __shfl_xor_sync(0xffffffffu, v, o);
        if (lane == 0) logits[(size_t)(t0 + tok) * NE + e] = v;
    }
}

__global__ void route_and_build(const float* __restrict__ logits, float* __restrict__ topw,
                                int* __restrict__ counts, int* __restrict__ rows) {
    int t = blockIdx.x * blockDim.x + threadIdx.x;
    if (t >= T) return;
    float mx = -3.4e38f;
    int mi = 0;
#pragma unroll
    for (int e = 0; e < NE; e++) {
        float l = logits[(size_t)t * NE + e];
        if (l > mx) { mx = l; mi = e; }
    }
    float s = 0.f;
#pragma unroll
    for (int e = 0; e < NE; e++) s += expf(logits[(size_t)t * NE + e] - mx);
    topw[t] = 1.f / s;
    int p = atomicAdd(&counts[mi], 1);
    rows[(size_t)mi * T + p] = t;
}

__global__ void zero_counts(int* c) {
    if (threadIdx.x < NE) c[threadIdx.x] = 0;
}

// ---------------- host ----------------
#define SYM(p, s) do { void* _v; cudaGetSymbolAddress(&_v, s); p = (decltype(p))_v; } while (0)

extern "C" void kernel_launch(void* const* d_in, const int* in_sizes, int n_in,
                              void* d_out, int out_size) {
    const float* x      = (const float*)d_in[0];
    const float* ln1    = (const float*)d_in[1];
    const float* qkv_w  = (const float*)d_in[2];
    const float* qlnw   = (const float*)d_in[3];
    const float* klnw   = (const float*)d_in[4];
    const float* o_w    = (const float*)d_in[5];
    const float* ln2    = (const float*)d_in[6];
    const float* gate_w = (const float*)d_in[7];
    const float* egu    = (const float*)d_in[8];
    const float* edown  = (const float*)d_in[9];
    const float* sguw   = (const float*)d_in[10];
    const float* sdw    = (const float*)d_in[11];
    float* out = (float*)d_out;

    __half *hh, *attnh, *act, *sact;
    float *qkv, *x2, *h2, *logits, *topw, *gu, *sgu, *moe, *ctab, *stab;
    int *counts, *rows;
    SYM(hh, g_hh); SYM(qkv, g_qkv); SYM(attnh, g_attnh);
    SYM(x2, g_x2); SYM(h2, g_h2); SYM(logits, g_logits);
    SYM(topw, g_topw); SYM(gu, g_gu); SYM(act, g_act); SYM(moe, g_moe);
    SYM(sgu, g_sgu); SYM(sact, g_sact);
    SYM(counts, g_counts); SYM(rows, g_rows);
    SYM(ctab, g_cos); SYM(stab, g_sin);

    cudaFuncSetAttribute(mma_nt<0>, cudaFuncAttributeMaxDynamicSharedMemorySize, GSMEM);
    cudaFuncSetAttribute(mma_nt<1>, cudaFuncAttributeMaxDynamicSharedMemorySize, GSMEM);
    cudaFuncSetAttribute(flash_attn, cudaFuncAttributeMaxDynamicSharedMemorySize, FL_SMEM);
    cudaFuncSetAttribute(gate_logits, cudaFuncAttributeMaxDynamicSharedMemorySize, GL_TOK * H * 4);

    rope_table<<<T, HD / 2>>>(ctab, stab);
    rmsnorm_kernel<1><<<T, 256>>>(x, ln1, hh, H);
    // qkv (fp32) = h @ qkv_w^T
    mma_nt<1><<<dim3(T / TBM, 3 * H / TBN, 1), 512, GSMEM>>>(
        hh, H, 0, qkv_w, H, 0, qkv, 3 * H, 0, T, 3 * H, H, 0, 0, 0, 0, 0);
    qk_norm_rope<<<T, 512>>>(qkv, qlnw, klnw, ctab, stab);
    // fused attention -> half attn
    flash_attn<<<dim3(T / 128, NH), 512, FL_SMEM>>>(qkv, attnh);
    // x2 = x + attn @ o_w^T
    mma_nt<1><<<dim3(T / TBM, H / TBN, 1), 512, GSMEM>>>(
        attnh, H, 0, o_w, H, 0, x2, H, 0, T, H, H, 0, 0, x, 0, 0);
    rmsnorm_kernel<0><<<T, 256>>>(x2, ln2, h2, H);
    gate_logits<<<T / GL_TOK, 512, GL_TOK * H * 4>>>(h2, gate_w, logits);
    zero_counts<<<1, 32>>>(counts);
    route_and_build<<<(T + 255) / 256, 256>>>(logits, topw, counts, rows);
    mma_nt<0><<<dim3(T / TBM, I2 / TBN, NE), 512, GSMEM>>>(
        h2, H, 0, egu, H, (long long)I2 * H, gu, I2, 0,
        T, I2, H, rows, counts, 0, 0, 0);
    silu_mul<<<(T * II + 255) / 256, 256>>>(gu, act);
    mma_nt<1><<<dim3(T / TBM, H / TBN, NE), 512, GSMEM>>>(
        act, II, 0, edown, II, (long long)H * II, moe, H, 0,
        T, H, II, rows, counts, 0, 0, 0);
    mma_nt<0><<<dim3(T / TBM, I2 / TBN, 1), 512, GSMEM>>>(
        h2, H, 0, sguw, H, 0, sgu, I2, 0, T, I2, H, 0, 0, 0, 0, 0);
    silu_mul<<<(T * II + 255) / 256, 256>>>(sgu, sact);
    mma_nt<1><<<dim3(T / TBM, H / TBN, 1), 512, GSMEM>>>(
        sact, II, 0, sdw, II, 0, out, H, 0, T, H, II, 0, 0, x2, moe, topw);
}